// round 1
// baseline (speedup 1.0000x reference)
#include <cuda_runtime.h>
#include <math.h>

#define NN 50000
#define EE 800000
#define DD 256
#define HH 256
#define LL 40

// ---------------- scratch (device globals; no allocation allowed) ----------------
__device__ float g_bufA[(size_t)NN * HH];   // 51.2 MB
__device__ float g_bufB[(size_t)NN * HH];   // 51.2 MB
__device__ float g_h2[(size_t)NN * LL];     // 8 MB
__device__ int   g_src[EE];
__device__ int   g_dst[EE];
__device__ int   g_col[EE];
__device__ int   g_counts[NN];
__device__ int   g_rowptr[NN + 1];
__device__ int   g_cursor[NN];
__device__ float g_dinv[NN];
__device__ float g_als[NN];
__device__ float g_ald[NN];
__device__ float g_colsum[DD];
__device__ float g_colsumsq[DD];
__device__ float g_mean[DD];
__device__ float g_istd[DD];
__device__ int   g_flag;  // 1 = edge_index is int64, 0 = int32

__device__ __forceinline__ float lrelu(float v) { return v > 0.f ? v : 0.2f * v; }

// ---------------- setup kernels ----------------
__global__ void zero_kernel() {
    int i = blockIdx.x * blockDim.x + threadIdx.x;
    if (i < NN) g_counts[i] = 0;
    if (i < DD) { g_colsum[i] = 0.f; g_colsumsq[i] = 0.f; }
}

// int64 little-endian => high 32-bit words are zero (values < 2^31).
__global__ void detect_kernel(const unsigned int* __restrict__ p) {
    if (blockIdx.x == 0 && threadIdx.x == 0) {
        int is64 = 1;
        for (int i = 0; i < 64; i++)
            if (p[2 * i + 1] != 0u) { is64 = 0; break; }
        g_flag = is64;
    }
}

__global__ void convert_kernel(const void* __restrict__ ei) {
    int e = blockIdx.x * blockDim.x + threadIdx.x;
    if (e >= EE) return;
    int s, d;
    if (g_flag) {
        const long long* p = (const long long*)ei;
        s = (int)p[e]; d = (int)p[EE + e];
    } else {
        const int* p = (const int*)ei;
        s = p[e]; d = p[EE + e];
    }
    g_src[e] = s;
    g_dst[e] = d;
    atomicAdd(&g_counts[d], 1);
}

__global__ void stats_kernel(const float* __restrict__ x) {
    int c = threadIdx.x;                       // 256 threads -> one column each
    int rpb = (NN + gridDim.x - 1) / gridDim.x;
    int r0 = blockIdx.x * rpb;
    int r1 = min(r0 + rpb, NN);
    float s = 0.f, s2 = 0.f;
    for (int r = r0; r < r1; r++) {
        float v = x[(size_t)r * DD + c];
        s += v; s2 += v * v;
    }
    atomicAdd(&g_colsum[c], s);
    atomicAdd(&g_colsumsq[c], s2);
}

__global__ void finalize_kernel() {
    int c = threadIdx.x;
    float mean = g_colsum[c] / (float)NN;
    float var = (g_colsumsq[c] - (float)NN * mean * mean) / (float)(NN - 1);
    g_mean[c] = mean;
    g_istd[c] = rsqrtf(var);
}

__global__ void standardize_kernel(const float* __restrict__ x) {
    int idx = blockIdx.x * blockDim.x + threadIdx.x;  // over NN*64 float4
    if (idx >= NN * 64) return;
    int c4 = (idx & 63) * 4;
    float4 v = ((const float4*)x)[idx];
    v.x = (v.x - g_mean[c4 + 0]) * g_istd[c4 + 0];
    v.y = (v.y - g_mean[c4 + 1]) * g_istd[c4 + 1];
    v.z = (v.z - g_mean[c4 + 2]) * g_istd[c4 + 2];
    v.w = (v.w - g_mean[c4 + 3]) * g_istd[c4 + 3];
    ((float4*)g_bufA)[idx] = v;
}

__global__ void dinv_kernel() {
    int i = blockIdx.x * blockDim.x + threadIdx.x;
    if (i < NN) g_dinv[i] = rsqrtf((float)(g_counts[i] + 1));  // +1 self loop
}

// single-block scan over counts -> rowptr / cursor
__global__ void scan_kernel() {
    __shared__ int sdata[1024];
    __shared__ int s_off;
    int tid = threadIdx.x;
    if (tid == 0) s_off = 0;
    __syncthreads();
    for (int base = 0; base < NN; base += 1024) {
        int i = base + tid;
        int v = (i < NN) ? g_counts[i] : 0;
        sdata[tid] = v;
        __syncthreads();
        for (int d = 1; d < 1024; d <<= 1) {
            int t = (tid >= d) ? sdata[tid - d] : 0;
            __syncthreads();
            sdata[tid] += t;
            __syncthreads();
        }
        int excl = sdata[tid] - v;
        int off = s_off;
        if (i < NN) { g_rowptr[i] = off + excl; g_cursor[i] = off + excl; }
        __syncthreads();
        if (tid == 1023) s_off = off + sdata[1023];
        __syncthreads();
    }
    if (tid == 0) g_rowptr[NN] = s_off;
}

__global__ void fill_kernel() {
    int e = blockIdx.x * blockDim.x + threadIdx.x;
    if (e >= EE) return;
    int d = g_dst[e];
    int p = atomicAdd(&g_cursor[d], 1);
    g_col[p] = g_src[e];
}

// ---------------- GEMM: C[M,Nn] = A[M,256] @ B[256,Nn] (fp32 SIMT) ----------------
__global__ void gemm_kernel(const float* __restrict__ A, const float* __restrict__ B,
                            float* __restrict__ C, int M, int Nn) {
    const int K = 256;
    __shared__ float As[16][128];
    __shared__ float Bs[16][64];
    int tid = threadIdx.x;
    int bm = blockIdx.y * 128;
    int bn = blockIdx.x * 64;
    int tx = tid & 15;   // N dir, 16 * 4 = 64
    int ty = tid >> 4;   // M dir, 16 * 8 = 128
    float acc[8][4];
#pragma unroll
    for (int i = 0; i < 8; i++)
#pragma unroll
        for (int j = 0; j < 4; j++) acc[i][j] = 0.f;

    for (int k0 = 0; k0 < K; k0 += 16) {
        // A tile: 128x16, 2 float4 per thread, store transposed
#pragma unroll
        for (int l = 0; l < 2; l++) {
            int lin = tid + l * 256;
            int row = lin >> 2;
            int c4 = (lin & 3) * 4;
            float4 v = make_float4(0.f, 0.f, 0.f, 0.f);
            if (bm + row < M)
                v = *(const float4*)(A + (size_t)(bm + row) * K + k0 + c4);
            As[c4 + 0][row] = v.x;
            As[c4 + 1][row] = v.y;
            As[c4 + 2][row] = v.z;
            As[c4 + 3][row] = v.w;
        }
        // B tile: 16x64, 4 guarded scalars per thread
        {
            int row = tid >> 4;
            int c4 = (tid & 15) * 4;
#pragma unroll
            for (int j = 0; j < 4; j++) {
                int cc = bn + c4 + j;
                Bs[row][c4 + j] = (cc < Nn) ? B[(size_t)(k0 + row) * Nn + cc] : 0.f;
            }
        }
        __syncthreads();
#pragma unroll
        for (int k = 0; k < 16; k++) {
            float4 a0 = *(const float4*)&As[k][ty * 8];
            float4 a1 = *(const float4*)&As[k][ty * 8 + 4];
            float4 b0 = *(const float4*)&Bs[k][tx * 4];
            float a[8] = {a0.x, a0.y, a0.z, a0.w, a1.x, a1.y, a1.z, a1.w};
            float b[4] = {b0.x, b0.y, b0.z, b0.w};
#pragma unroll
            for (int i = 0; i < 8; i++)
#pragma unroll
                for (int j = 0; j < 4; j++) acc[i][j] += a[i] * b[j];
        }
        __syncthreads();
    }
#pragma unroll
    for (int i = 0; i < 8; i++) {
        int row = bm + ty * 8 + i;
        if (row >= M) continue;
#pragma unroll
        for (int j = 0; j < 4; j++) {
            int col = bn + tx * 4 + j;
            if (col < Nn) C[(size_t)row * Nn + col] = acc[i][j];
        }
    }
}

// ---------------- GCN aggregate (warp per dst node, 256 features) ----------------
__global__ void gcn_agg_kernel(const float* __restrict__ h, const float* __restrict__ bias,
                               float* __restrict__ out, int do_relu) {
    int t = blockIdx.x * blockDim.x + threadIdx.x;
    int node = t >> 5;
    int lane = t & 31;
    if (node >= NN) return;
    int beg = g_rowptr[node], end = g_rowptr[node + 1];
    float di = g_dinv[node];
    const float4* h4 = (const float4*)h;
    float w = di * di;  // self loop
    float4 v0 = h4[node * 64 + lane];
    float4 v1 = h4[node * 64 + lane + 32];
    float4 a0 = make_float4(w * v0.x, w * v0.y, w * v0.z, w * v0.w);
    float4 a1 = make_float4(w * v1.x, w * v1.y, w * v1.z, w * v1.w);
    for (int e = beg; e < end; e++) {
        int s = g_col[e];
        float we = g_dinv[s] * di;
        v0 = h4[s * 64 + lane];
        v1 = h4[s * 64 + lane + 32];
        a0.x += we * v0.x; a0.y += we * v0.y; a0.z += we * v0.z; a0.w += we * v0.w;
        a1.x += we * v1.x; a1.y += we * v1.y; a1.z += we * v1.z; a1.w += we * v1.w;
    }
    float4 b0 = ((const float4*)bias)[lane];
    float4 b1 = ((const float4*)bias)[lane + 32];
    a0.x += b0.x; a0.y += b0.y; a0.z += b0.z; a0.w += b0.w;
    a1.x += b1.x; a1.y += b1.y; a1.z += b1.z; a1.w += b1.w;
    if (do_relu) {
        a0.x = fmaxf(a0.x, 0.f); a0.y = fmaxf(a0.y, 0.f);
        a0.z = fmaxf(a0.z, 0.f); a0.w = fmaxf(a0.w, 0.f);
        a1.x = fmaxf(a1.x, 0.f); a1.y = fmaxf(a1.y, 0.f);
        a1.z = fmaxf(a1.z, 0.f); a1.w = fmaxf(a1.w, 0.f);
    }
    ((float4*)out)[node * 64 + lane] = a0;
    ((float4*)out)[node * 64 + lane + 32] = a1;
}

// ---------------- GAT attention logits: al = h @ a  (warp per node) ----------------
__global__ void al_kernel(const float* __restrict__ h, const float* __restrict__ asrc,
                          const float* __restrict__ adst) {
    int t = blockIdx.x * blockDim.x + threadIdx.x;
    int node = t >> 5;
    int lane = t & 31;
    if (node >= NN) return;
    const float4* h4 = (const float4*)h + node * 64;
    float4 v0 = h4[lane], v1 = h4[lane + 32];
    float4 s0 = ((const float4*)asrc)[lane], s1 = ((const float4*)asrc)[lane + 32];
    float4 d0 = ((const float4*)adst)[lane], d1 = ((const float4*)adst)[lane + 32];
    float ds = v0.x * s0.x + v0.y * s0.y + v0.z * s0.z + v0.w * s0.w +
               v1.x * s1.x + v1.y * s1.y + v1.z * s1.z + v1.w * s1.w;
    float dd = v0.x * d0.x + v0.y * d0.y + v0.z * d0.z + v0.w * d0.w +
               v1.x * d1.x + v1.y * d1.y + v1.z * d1.z + v1.w * d1.w;
    for (int o = 16; o; o >>= 1) {
        ds += __shfl_xor_sync(0xffffffffu, ds, o);
        dd += __shfl_xor_sync(0xffffffffu, dd, o);
    }
    if (lane == 0) { g_als[node] = ds; g_ald[node] = dd; }
}

// ---------------- GAT aggregate with segment softmax (warp per dst) ----------------
__global__ void gat_agg_kernel(const float* __restrict__ h, const float* __restrict__ bias,
                               float* __restrict__ out) {
    int t = blockIdx.x * blockDim.x + threadIdx.x;
    int node = t >> 5;
    int lane = t & 31;
    if (node >= NN) return;
    int beg = g_rowptr[node], end = g_rowptr[node + 1];
    float aldi = g_ald[node];
    float e_self = lrelu(g_als[node] + aldi);
    // pass 1: segment max
    float m = e_self;
    for (int e = beg + lane; e < end; e += 32)
        m = fmaxf(m, lrelu(g_als[g_col[e]] + aldi));
    for (int o = 16; o; o >>= 1) m = fmaxf(m, __shfl_xor_sync(0xffffffffu, m, o));
    // pass 2: fused exp-sum + weighted accumulate
    const float4* h4 = (const float4*)h;
    float z = __expf(e_self - m);
    float4 v0 = h4[node * 64 + lane];
    float4 v1 = h4[node * 64 + lane + 32];
    float4 a0 = make_float4(z * v0.x, z * v0.y, z * v0.z, z * v0.w);
    float4 a1 = make_float4(z * v1.x, z * v1.y, z * v1.z, z * v1.w);
    for (int e = beg; e < end; e++) {
        int s = g_col[e];
        float w = __expf(lrelu(g_als[s] + aldi) - m);
        z += w;
        v0 = h4[s * 64 + lane];
        v1 = h4[s * 64 + lane + 32];
        a0.x += w * v0.x; a0.y += w * v0.y; a0.z += w * v0.z; a0.w += w * v0.w;
        a1.x += w * v1.x; a1.y += w * v1.y; a1.z += w * v1.z; a1.w += w * v1.w;
    }
    float inv = 1.0f / z;
    float4 b0 = ((const float4*)bias)[lane];
    float4 b1 = ((const float4*)bias)[lane + 32];
    a0.x = fmaxf(a0.x * inv + b0.x, 0.f); a0.y = fmaxf(a0.y * inv + b0.y, 0.f);
    a0.z = fmaxf(a0.z * inv + b0.z, 0.f); a0.w = fmaxf(a0.w * inv + b0.w, 0.f);
    a1.x = fmaxf(a1.x * inv + b1.x, 0.f); a1.y = fmaxf(a1.y * inv + b1.y, 0.f);
    a1.z = fmaxf(a1.z * inv + b1.z, 0.f); a1.w = fmaxf(a1.w * inv + b1.w, 0.f);
    ((float4*)out)[node * 64 + lane] = a0;
    ((float4*)out)[node * 64 + lane + 32] = a1;
}

// ---------------- final GCN (L=40) + log_softmax (warp per dst node) ----------------
__global__ void gcn2_kernel(const float* __restrict__ h2, const float* __restrict__ b2,
                            float* __restrict__ out) {
    int t = blockIdx.x * blockDim.x + threadIdx.x;
    int node = t >> 5;
    int lane = t & 31;
    if (node >= NN) return;
    int beg = g_rowptr[node], end = g_rowptr[node + 1];
    float di = g_dinv[node];
    float w = di * di;
    float a0 = w * h2[(size_t)node * LL + lane];
    float a1 = (lane < 8) ? w * h2[(size_t)node * LL + lane + 32] : 0.f;
    for (int e = beg; e < end; e++) {
        int s = g_col[e];
        float we = g_dinv[s] * di;
        a0 += we * h2[(size_t)s * LL + lane];
        if (lane < 8) a1 += we * h2[(size_t)s * LL + lane + 32];
    }
    float v0 = a0 + b2[lane];
    float v1 = (lane < 8) ? a1 + b2[lane + 32] : -INFINITY;
    float m = fmaxf(v0, v1);
    for (int o = 16; o; o >>= 1) m = fmaxf(m, __shfl_xor_sync(0xffffffffu, m, o));
    float z = expf(v0 - m) + ((lane < 8) ? expf(v1 - m) : 0.f);
    for (int o = 16; o; o >>= 1) z += __shfl_xor_sync(0xffffffffu, z, o);
    float ls = logf(z);
    out[(size_t)node * LL + lane] = v0 - m - ls;
    if (lane < 8) out[(size_t)node * LL + lane + 32] = v1 - m - ls;
}

// ---------------- launch ----------------
extern "C" void kernel_launch(void* const* d_in, const int* in_sizes, int n_in,
                              void* d_out, int out_size) {
    const float* x   = (const float*)d_in[0];
    const void*  ei  = d_in[1];
    const float* W1  = (const float*)d_in[2];
    const float* b1  = (const float*)d_in[3];
    const float* Wg  = (const float*)d_in[4];
    const float* a_s = (const float*)d_in[5];
    const float* a_d = (const float*)d_in[6];
    const float* bg  = (const float*)d_in[7];
    const float* W2  = (const float*)d_in[8];
    const float* b2  = (const float*)d_in[9];
    float* out = (float*)d_out;

    float *pA, *pB, *pH2;
    cudaGetSymbolAddress((void**)&pA, g_bufA);
    cudaGetSymbolAddress((void**)&pB, g_bufB);
    cudaGetSymbolAddress((void**)&pH2, g_h2);

    const int tpb = 256;
    zero_kernel<<<(NN + tpb - 1) / tpb, tpb>>>();
    detect_kernel<<<1, 32>>>((const unsigned int*)ei);
    convert_kernel<<<(EE + tpb - 1) / tpb, tpb>>>(ei);
    stats_kernel<<<128, 256>>>(x);
    finalize_kernel<<<1, 256>>>();
    standardize_kernel<<<(NN * 64 + tpb - 1) / tpb, tpb>>>(x);
    dinv_kernel<<<(NN + tpb - 1) / tpb, tpb>>>();
    scan_kernel<<<1, 1024>>>();
    fill_kernel<<<(EE + tpb - 1) / tpb, tpb>>>();

    dim3 g256((256 + 63) / 64, (NN + 127) / 128);
    dim3 g40((40 + 63) / 64, (NN + 127) / 128);
    int warpGrid = (NN * 32 + tpb - 1) / tpb;

    // GCN layer 1 (+ReLU)
    gemm_kernel<<<g256, 256>>>(pA, W1, pB, NN, 256);
    gcn_agg_kernel<<<warpGrid, tpb>>>(pB, b1, pA, 1);

    // GAT layer 1 (+ReLU)
    gemm_kernel<<<g256, 256>>>(pA, Wg, pB, NN, 256);
    al_kernel<<<warpGrid, tpb>>>(pB, a_s, a_d);
    gat_agg_kernel<<<warpGrid, tpb>>>(pB, bg, pA);

    // GAT layer 2 (+ReLU)
    gemm_kernel<<<g256, 256>>>(pA, Wg, pB, NN, 256);
    al_kernel<<<warpGrid, tpb>>>(pB, a_s, a_d);
    gat_agg_kernel<<<warpGrid, tpb>>>(pB, bg, pA);

    // GCN layer 2 + log_softmax
    gemm_kernel<<<g40, 256>>>(pA, W2, pH2, NN, 40);
    gcn2_kernel<<<warpGrid, tpb>>>(pH2, b2, out);
}

// round 3
// speedup vs baseline: 1.2883x; 1.2883x over previous
#include <cuda_runtime.h>
#include <cuda_bf16.h>
#include <math.h>
#include <stdint.h>

#define NN 50000
#define EE 800000
#define DD 256
#define HH 256
#define LL 40

// ---------------- scratch (device globals; no allocation allowed) ----------------
__device__ float g_bufA[(size_t)NN * HH];   // 51.2 MB
__device__ float g_bufB[(size_t)NN * HH];   // 51.2 MB
__device__ float g_h2[(size_t)NN * LL];     // 8 MB
__device__ int   g_src[EE];
__device__ int   g_dst[EE];
__device__ int   g_col[EE];
__device__ int   g_counts[NN];
__device__ int   g_rowptr[NN + 1];
__device__ int   g_cursor[NN];
__device__ float g_dinv[NN];
__device__ float g_als[NN];
__device__ float g_ald[NN];
__device__ float g_colsum[DD];
__device__ float g_colsumsq[DD];
__device__ float g_mean[DD];
__device__ float g_istd[DD];
__device__ int   g_flag;  // 1 = edge_index is int64, 0 = int32
// transposed + split weight planes: [n][k] bf16, 16B-aligned via uint4 backing
__device__ uint4 g_Whi4[(256 * 256) / 8];
__device__ uint4 g_Wlo4[(256 * 256) / 8];

__device__ __forceinline__ float lrelu(float v) { return v > 0.f ? v : 0.2f * v; }
__device__ __forceinline__ uint32_t swz128(uint32_t o) { return o ^ ((o >> 3) & 0x70); }

__device__ __forceinline__ uint32_t smem_u32(const void* p) {
    uint32_t a;
    asm("{ .reg .u64 t; cvta.to.shared.u64 t, %1; cvt.u32.u64 %0, t; }" : "=r"(a) : "l"(p));
    return a;
}

#define LDSM_X4(r0, r1, r2, r3, addr)                                               \
    asm volatile("ldmatrix.sync.aligned.m8n8.x4.shared.b16 {%0,%1,%2,%3}, [%4];"    \
                 : "=r"(r0), "=r"(r1), "=r"(r2), "=r"(r3) : "r"(addr))

#define MMA16816(d, a, b)                                                           \
    asm volatile("mma.sync.aligned.m16n8k16.row.col.f32.bf16.bf16.f32 "             \
                 "{%0,%1,%2,%3}, {%4,%5,%6,%7}, {%8,%9}, {%0,%1,%2,%3};"            \
                 : "+f"((d)[0]), "+f"((d)[1]), "+f"((d)[2]), "+f"((d)[3])           \
                 : "r"((a)[0]), "r"((a)[1]), "r"((a)[2]), "r"((a)[3]),              \
                   "r"((b)[0]), "r"((b)[1]))

// ---------------- setup kernels ----------------
__global__ void zero_kernel() {
    int i = blockIdx.x * blockDim.x + threadIdx.x;
    if (i < NN) g_counts[i] = 0;
    if (i < DD) { g_colsum[i] = 0.f; g_colsumsq[i] = 0.f; }
}

__global__ void detect_kernel(const unsigned int* __restrict__ p) {
    if (blockIdx.x == 0 && threadIdx.x == 0) {
        int is64 = 1;
        for (int i = 0; i < 64; i++)
            if (p[2 * i + 1] != 0u) { is64 = 0; break; }
        g_flag = is64;
    }
}

__global__ void convert_kernel(const void* __restrict__ ei) {
    int e = blockIdx.x * blockDim.x + threadIdx.x;
    if (e >= EE) return;
    int s, d;
    if (g_flag) {
        const long long* p = (const long long*)ei;
        s = (int)p[e]; d = (int)p[EE + e];
    } else {
        const int* p = (const int*)ei;
        s = p[e]; d = p[EE + e];
    }
    g_src[e] = s;
    g_dst[e] = d;
    atomicAdd(&g_counts[d], 1);
}

__global__ void stats_kernel(const float* __restrict__ x) {
    int cg = threadIdx.x & 63;
    int rlane = threadIdx.x >> 6;
    float4 s = make_float4(0.f, 0.f, 0.f, 0.f);
    float4 s2 = make_float4(0.f, 0.f, 0.f, 0.f);
    for (int r = blockIdx.x * 4 + rlane; r < NN; r += gridDim.x * 4) {
        float4 v = ((const float4*)x)[(size_t)r * 64 + cg];
        s.x += v.x; s.y += v.y; s.z += v.z; s.w += v.w;
        s2.x += v.x * v.x; s2.y += v.y * v.y; s2.z += v.z * v.z; s2.w += v.w * v.w;
    }
    int c = cg * 4;
    atomicAdd(&g_colsum[c + 0], s.x); atomicAdd(&g_colsum[c + 1], s.y);
    atomicAdd(&g_colsum[c + 2], s.z); atomicAdd(&g_colsum[c + 3], s.w);
    atomicAdd(&g_colsumsq[c + 0], s2.x); atomicAdd(&g_colsumsq[c + 1], s2.y);
    atomicAdd(&g_colsumsq[c + 2], s2.z); atomicAdd(&g_colsumsq[c + 3], s2.w);
}

__global__ void finalize_kernel() {
    int c = threadIdx.x;
    float mean = g_colsum[c] / (float)NN;
    float var = (g_colsumsq[c] - (float)NN * mean * mean) / (float)(NN - 1);
    g_mean[c] = mean;
    g_istd[c] = rsqrtf(var);
}

__global__ void standardize_kernel(const float* __restrict__ x) {
    int idx = blockIdx.x * blockDim.x + threadIdx.x;
    if (idx >= NN * 64) return;
    int c4 = (idx & 63) * 4;
    float4 v = ((const float4*)x)[idx];
    v.x = (v.x - g_mean[c4 + 0]) * g_istd[c4 + 0];
    v.y = (v.y - g_mean[c4 + 1]) * g_istd[c4 + 1];
    v.z = (v.z - g_mean[c4 + 2]) * g_istd[c4 + 2];
    v.w = (v.w - g_mean[c4 + 3]) * g_istd[c4 + 3];
    ((float4*)g_bufA)[idx] = v;
}

__global__ void dinv_kernel() {
    int i = blockIdx.x * blockDim.x + threadIdx.x;
    if (i < NN) g_dinv[i] = rsqrtf((float)(g_counts[i] + 1));
}

__global__ void scan_kernel() {
    __shared__ int sdata[1024];
    __shared__ int s_off;
    int tid = threadIdx.x;
    if (tid == 0) s_off = 0;
    __syncthreads();
    for (int base = 0; base < NN; base += 1024) {
        int i = base + tid;
        int v = (i < NN) ? g_counts[i] : 0;
        sdata[tid] = v;
        __syncthreads();
        for (int d = 1; d < 1024; d <<= 1) {
            int t = (tid >= d) ? sdata[tid - d] : 0;
            __syncthreads();
            sdata[tid] += t;
            __syncthreads();
        }
        int excl = sdata[tid] - v;
        int off = s_off;
        if (i < NN) { g_rowptr[i] = off + excl; g_cursor[i] = off + excl; }
        __syncthreads();
        if (tid == 1023) s_off = off + sdata[1023];
        __syncthreads();
    }
    if (tid == 0) g_rowptr[NN] = s_off;
}

__global__ void fill_kernel() {
    int e = blockIdx.x * blockDim.x + threadIdx.x;
    if (e >= EE) return;
    int d = g_dst[e];
    int p = atomicAdd(&g_cursor[d], 1);
    g_col[p] = g_src[e];
}

// ---------------- weight transpose + hi/lo split: out[n][k] = split(W[k][n]) ---------------
__global__ void splitW_kernel(const float* __restrict__ W) {
    int idx = blockIdx.x * blockDim.x + threadIdx.x;
    if (idx >= 256 * 256) return;
    int k = idx >> 8;
    int n = idx & 255;
    float v = W[idx];
    __nv_bfloat16 h = __float2bfloat16(v);
    float r = v - __bfloat162float(h);
    __nv_bfloat16* whi = (__nv_bfloat16*)g_Whi4;
    __nv_bfloat16* wlo = (__nv_bfloat16*)g_Wlo4;
    whi[n * 256 + k] = h;
    wlo[n * 256 + k] = __float2bfloat16(r);
}

// ---------------- mma.sync GEMM: C[M,256] = A[M,256] @ Wsplit^T (bf16 hi/lo 3-term) --------
// Tile 128x128, 256 threads (8 warps, 4Mx2N), warp tile 32x64, K-chunks of 64.
// SMEM planes (16KB each): Ahi, Alo, Bhi, Blo. Rows of 64 bf16 = 128B, SW128 swizzled.
#define SO_AHI 0
#define SO_ALO 16384
#define SO_BHI 32768
#define SO_BLO 49152
#define MMA_SMEM 65536

__global__ void __launch_bounds__(256) mma_gemm_kernel(
    const float* __restrict__ A, const __nv_bfloat16* __restrict__ Bhi_g,
    const __nv_bfloat16* __restrict__ Blo_g, float* __restrict__ C, int M) {
    extern __shared__ char smem[];
    uint32_t sb = smem_u32(smem);
    int tid = threadIdx.x;
    int wid = tid >> 5, lane = tid & 31;
    int bm = blockIdx.y * 128;
    int bn = blockIdx.x * 128;
    int wm = (wid >> 1) * 32;     // warp M offset within tile
    int wn = (wid & 1) * 64;      // warp N offset within tile

    float acc[2][8][4];
#pragma unroll
    for (int mt = 0; mt < 2; mt++)
#pragma unroll
        for (int nt = 0; nt < 8; nt++)
#pragma unroll
            for (int r = 0; r < 4; r++) acc[mt][nt][r] = 0.f;

    // precomputed ldmatrix addresses (within-chunk ks offsets added in loop)
    // A: row = wm + mt*16 + lane%16 ; colbyte = (lane/16)*16
    uint32_t a_addr[2];
#pragma unroll
    for (int mt = 0; mt < 2; mt++) {
        uint32_t row = (uint32_t)(wm + mt * 16 + (lane & 15));
        uint32_t cb = (uint32_t)((lane >> 4) * 16);
        a_addr[mt] = sb + swz128(row * 128 + cb);  // +ks*32 applied via swz-safe add? no: recompute
    }
    // B: row = wn + ntp*16 + lane%8 + (lane>=16)*8 ; colbyte = ((lane>>3)&1)*16
    uint32_t b_row[4], b_cb;
#pragma unroll
    for (int ntp = 0; ntp < 4; ntp++)
        b_row[ntp] = (uint32_t)(wn + ntp * 16 + (lane & 7) + ((lane >> 4) << 3));
    b_cb = (uint32_t)(((lane >> 3) & 1) * 16);

    for (int ch = 0; ch < 4; ch++) {
        int k0 = ch * 64;
        __syncthreads();
        // ---- stage A chunk [128 x 64] fp32 -> bf16 hi/lo planes (SW128) ----
#pragma unroll
        for (int i = 0; i < 8; i++) {
            int lin = tid + i * 256;
            int row = lin >> 4;
            int c4 = (lin & 15) * 4;
            float4 v = make_float4(0.f, 0.f, 0.f, 0.f);
            int gr = bm + row;
            if (gr < M) v = *(const float4*)(A + (size_t)gr * 256 + k0 + c4);
            __nv_bfloat16 hx = __float2bfloat16(v.x), hy = __float2bfloat16(v.y);
            __nv_bfloat16 hz = __float2bfloat16(v.z), hw = __float2bfloat16(v.w);
            __nv_bfloat16 lx = __float2bfloat16(v.x - __bfloat162float(hx));
            __nv_bfloat16 ly = __float2bfloat16(v.y - __bfloat162float(hy));
            __nv_bfloat16 lz = __float2bfloat16(v.z - __bfloat162float(hz));
            __nv_bfloat16 lw = __float2bfloat16(v.w - __bfloat162float(hw));
            uint32_t so = swz128((uint32_t)(row * 128 + c4 * 2));
            __nv_bfloat162 p0, p1;
            p0.x = hx; p0.y = hy; p1.x = hz; p1.y = hw;
            uint2 uh = make_uint2(*(unsigned*)&p0, *(unsigned*)&p1);
            p0.x = lx; p0.y = ly; p1.x = lz; p1.y = lw;
            uint2 ul = make_uint2(*(unsigned*)&p0, *(unsigned*)&p1);
            *(uint2*)(smem + SO_AHI + so) = uh;
            *(uint2*)(smem + SO_ALO + so) = ul;
        }
        // ---- stage B chunk [128 x 64] bf16 planes (already split+transposed) ----
#pragma unroll
        for (int i = 0; i < 4; i++) {
            int lin = tid + i * 256;
            int row = lin >> 3;
            int u8 = lin & 7;
            uint32_t so = swz128((uint32_t)(row * 128 + u8 * 16));
            const uint4* sh = (const uint4*)(Bhi_g + (size_t)(bn + row) * 256 + k0);
            const uint4* sl = (const uint4*)(Blo_g + (size_t)(bn + row) * 256 + k0);
            *(uint4*)(smem + SO_BHI + so) = sh[u8];
            *(uint4*)(smem + SO_BLO + so) = sl[u8];
        }
        __syncthreads();

        // ---- compute 4 k16-steps ----
#pragma unroll
        for (int ks = 0; ks < 4; ks++) {
            uint32_t kb = (uint32_t)(ks * 32);
            uint32_t ah[2][4], al[2][4];
#pragma unroll
            for (int mt = 0; mt < 2; mt++) {
                uint32_t row = (uint32_t)(wm + mt * 16 + (lane & 15));
                uint32_t cb = (uint32_t)((lane >> 4) * 16) + kb;
                uint32_t ad = sb + swz128(row * 128 + cb);
                LDSM_X4(ah[mt][0], ah[mt][1], ah[mt][2], ah[mt][3], ad + SO_AHI);
                LDSM_X4(al[mt][0], al[mt][1], al[mt][2], al[mt][3], ad + SO_ALO);
            }
            uint32_t bh[8][2], bl[8][2];
#pragma unroll
            for (int ntp = 0; ntp < 4; ntp++) {
                uint32_t bd = sb + swz128(b_row[ntp] * 128 + b_cb + kb);
                LDSM_X4(bh[2 * ntp][0], bh[2 * ntp][1], bh[2 * ntp + 1][0],
                        bh[2 * ntp + 1][1], bd + SO_BHI);
                LDSM_X4(bl[2 * ntp][0], bl[2 * ntp][1], bl[2 * ntp + 1][0],
                        bl[2 * ntp + 1][1], bd + SO_BLO);
            }
#pragma unroll
            for (int mt = 0; mt < 2; mt++)
#pragma unroll
                for (int nt = 0; nt < 8; nt++) {
                    MMA16816(acc[mt][nt], ah[mt], bh[nt]);
                    MMA16816(acc[mt][nt], ah[mt], bl[nt]);
                    MMA16816(acc[mt][nt], al[mt], bh[nt]);
                }
        }
    }

    // ---- epilogue: write accumulators ----
#pragma unroll
    for (int mt = 0; mt < 2; mt++) {
        int r0 = bm + wm + mt * 16 + (lane >> 2);
        int r1 = r0 + 8;
#pragma unroll
        for (int nt = 0; nt < 8; nt++) {
            int col = bn + wn + nt * 8 + (lane & 3) * 2;
            if (r0 < M) *(float2*)(C + (size_t)r0 * 256 + col) =
                make_float2(acc[mt][nt][0], acc[mt][nt][1]);
            if (r1 < M) *(float2*)(C + (size_t)r1 * 256 + col) =
                make_float2(acc[mt][nt][2], acc[mt][nt][3]);
        }
    }
}

// ---------------- SIMT GEMM (final 256x40 layer) ----------------
__global__ void gemm_kernel(const float* __restrict__ A, const float* __restrict__ B,
                            float* __restrict__ C, int M, int Nn) {
    const int K = 256;
    __shared__ float As[16][128];
    __shared__ float Bs[16][64];
    int tid = threadIdx.x;
    int bm = blockIdx.y * 128;
    int bn = blockIdx.x * 64;
    int tx = tid & 15;
    int ty = tid >> 4;
    float acc[8][4];
#pragma unroll
    for (int i = 0; i < 8; i++)
#pragma unroll
        for (int j = 0; j < 4; j++) acc[i][j] = 0.f;

    for (int k0 = 0; k0 < K; k0 += 16) {
#pragma unroll
        for (int l = 0; l < 2; l++) {
            int lin = tid + l * 256;
            int row = lin >> 2;
            int c4 = (lin & 3) * 4;
            float4 v = make_float4(0.f, 0.f, 0.f, 0.f);
            if (bm + row < M)
                v = *(const float4*)(A + (size_t)(bm + row) * K + k0 + c4);
            As[c4 + 0][row] = v.x;
            As[c4 + 1][row] = v.y;
            As[c4 + 2][row] = v.z;
            As[c4 + 3][row] = v.w;
        }
        {
            int row = tid >> 4;
            int c4 = (tid & 15) * 4;
#pragma unroll
            for (int j = 0; j < 4; j++) {
                int cc = bn + c4 + j;
                Bs[row][c4 + j] = (cc < Nn) ? B[(size_t)(k0 + row) * Nn + cc] : 0.f;
            }
        }
        __syncthreads();
#pragma unroll
        for (int k = 0; k < 16; k++) {
            float4 a0 = *(const float4*)&As[k][ty * 8];
            float4 a1 = *(const float4*)&As[k][ty * 8 + 4];
            float4 b0 = *(const float4*)&Bs[k][tx * 4];
            float a[8] = {a0.x, a0.y, a0.z, a0.w, a1.x, a1.y, a1.z, a1.w};
            float b[4] = {b0.x, b0.y, b0.z, b0.w};
#pragma unroll
            for (int i = 0; i < 8; i++)
#pragma unroll
                for (int j = 0; j < 4; j++) acc[i][j] += a[i] * b[j];
        }
        __syncthreads();
    }
#pragma unroll
    for (int i = 0; i < 8; i++) {
        int row = bm + ty * 8 + i;
        if (row >= M) continue;
#pragma unroll
        for (int j = 0; j < 4; j++) {
            int col = bn + tx * 4 + j;
            if (col < Nn) C[(size_t)row * Nn + col] = acc[i][j];
        }
    }
}

// ---------------- GCN aggregate (warp per dst node, 256 features) ----------------
__global__ void gcn_agg_kernel(const float* __restrict__ h, const float* __restrict__ bias,
                               float* __restrict__ out, int do_relu) {
    int t = blockIdx.x * blockDim.x + threadIdx.x;
    int node = t >> 5;
    int lane = t & 31;
    if (node >= NN) return;
    int beg = g_rowptr[node], end = g_rowptr[node + 1];
    float di = g_dinv[node];
    const float4* h4 = (const float4*)h;
    float w = di * di;
    float4 v0 = h4[node * 64 + lane];
    float4 v1 = h4[node * 64 + lane + 32];
    float4 a0 = make_float4(w * v0.x, w * v0.y, w * v0.z, w * v0.w);
    float4 a1 = make_float4(w * v1.x, w * v1.y, w * v1.z, w * v1.w);
    for (int e = beg; e < end; e++) {
        int s = g_col[e];
        float we = g_dinv[s] * di;
        v0 = h4[s * 64 + lane];
        v1 = h4[s * 64 + lane + 32];
        a0.x += we * v0.x; a0.y += we * v0.y; a0.z += we * v0.z; a0.w += we * v0.w;
        a1.x += we * v1.x; a1.y += we * v1.y; a1.z += we * v1.z; a1.w += we * v1.w;
    }
    float4 b0 = ((const float4*)bias)[lane];
    float4 b1 = ((const float4*)bias)[lane + 32];
    a0.x += b0.x; a0.y += b0.y; a0.z += b0.z; a0.w += b0.w;
    a1.x += b1.x; a1.y += b1.y; a1.z += b1.z; a1.w += b1.w;
    if (do_relu) {
        a0.x = fmaxf(a0.x, 0.f); a0.y = fmaxf(a0.y, 0.f);
        a0.z = fmaxf(a0.z, 0.f); a0.w = fmaxf(a0.w, 0.f);
        a1.x = fmaxf(a1.x, 0.f); a1.y = fmaxf(a1.y, 0.f);
        a1.z = fmaxf(a1.z, 0.f); a1.w = fmaxf(a1.w, 0.f);
    }
    ((float4*)out)[node * 64 + lane] = a0;
    ((float4*)out)[node * 64 + lane + 32] = a1;
}

// ---------------- GAT attention logits ----------------
__global__ void al_kernel(const float* __restrict__ h, const float* __restrict__ asrc,
                          const float* __restrict__ adst) {
    int t = blockIdx.x * blockDim.x + threadIdx.x;
    int node = t >> 5;
    int lane = t & 31;
    if (node >= NN) return;
    const float4* h4 = (const float4*)h + node * 64;
    float4 v0 = h4[lane], v1 = h4[lane + 32];
    float4 s0 = ((const float4*)asrc)[lane], s1 = ((const float4*)asrc)[lane + 32];
    float4 d0 = ((const float4*)adst)[lane], d1 = ((const float4*)adst)[lane + 32];
    float ds = v0.x * s0.x + v0.y * s0.y + v0.z * s0.z + v0.w * s0.w +
               v1.x * s1.x + v1.y * s1.y + v1.z * s1.z + v1.w * s1.w;
    float dd = v0.x * d0.x + v0.y * d0.y + v0.z * d0.z + v0.w * d0.w +
               v1.x * d1.x + v1.y * d1.y + v1.z * d1.z + v1.w * d1.w;
    for (int o = 16; o; o >>= 1) {
        ds += __shfl_xor_sync(0xffffffffu, ds, o);
        dd += __shfl_xor_sync(0xffffffffu, dd, o);
    }
    if (lane == 0) { g_als[node] = ds; g_ald[node] = dd; }
}

// ---------------- GAT aggregate with segment softmax ----------------
__global__ void gat_agg_kernel(const float* __restrict__ h, const float* __restrict__ bias,
                               float* __restrict__ out) {
    int t = blockIdx.x * blockDim.x + threadIdx.x;
    int node = t >> 5;
    int lane = t & 31;
    if (node >= NN) return;
    int beg = g_rowptr[node], end = g_rowptr[node + 1];
    float aldi = g_ald[node];
    float e_self = lrelu(g_als[node] + aldi);
    float m = e_self;
    for (int e = beg + lane; e < end; e += 32)
        m = fmaxf(m, lrelu(g_als[g_col[e]] + aldi));
    for (int o = 16; o; o >>= 1) m = fmaxf(m, __shfl_xor_sync(0xffffffffu, m, o));
    const float4* h4 = (const float4*)h;
    float z = __expf(e_self - m);
    float4 v0 = h4[node * 64 + lane];
    float4 v1 = h4[node * 64 + lane + 32];
    float4 a0 = make_float4(z * v0.x, z * v0.y, z * v0.z, z * v0.w);
    float4 a1 = make_float4(z * v1.x, z * v1.y, z * v1.z, z * v1.w);
    for (int e = beg; e < end; e++) {
        int s = g_col[e];
        float w = __expf(lrelu(g_als[s] + aldi) - m);
        z += w;
        v0 = h4[s * 64 + lane];
        v1 = h4[s * 64 + lane + 32];
        a0.x += w * v0.x; a0.y += w * v0.y; a0.z += w * v0.z; a0.w += w * v0.w;
        a1.x += w * v1.x; a1.y += w * v1.y; a1.z += w * v1.z; a1.w += w * v1.w;
    }
    float inv = 1.0f / z;
    float4 b0 = ((const float4*)bias)[lane];
    float4 b1 = ((const float4*)bias)[lane + 32];
    a0.x = fmaxf(a0.x * inv + b0.x, 0.f); a0.y = fmaxf(a0.y * inv + b0.y, 0.f);
    a0.z = fmaxf(a0.z * inv + b0.z, 0.f); a0.w = fmaxf(a0.w * inv + b0.w, 0.f);
    a1.x = fmaxf(a1.x * inv + b1.x, 0.f); a1.y = fmaxf(a1.y * inv + b1.y, 0.f);
    a1.z = fmaxf(a1.z * inv + b1.z, 0.f); a1.w = fmaxf(a1.w * inv + b1.w, 0.f);
    ((float4*)out)[node * 64 + lane] = a0;
    ((float4*)out)[node * 64 + lane + 32] = a1;
}

// ---------------- final GCN (L=40) + log_softmax ----------------
__global__ void gcn2_kernel(const float* __restrict__ h2, const float* __restrict__ b2,
                            float* __restrict__ out) {
    int t = blockIdx.x * blockDim.x + threadIdx.x;
    int node = t >> 5;
    int lane = t & 31;
    if (node >= NN) return;
    int beg = g_rowptr[node], end = g_rowptr[node + 1];
    float di = g_dinv[node];
    float w = di * di;
    float a0 = w * h2[(size_t)node * LL + lane];
    float a1 = (lane < 8) ? w * h2[(size_t)node * LL + lane + 32] : 0.f;
    for (int e = beg; e < end; e++) {
        int s = g_col[e];
        float we = g_dinv[s] * di;
        a0 += we * h2[(size_t)s * LL + lane];
        if (lane < 8) a1 += we * h2[(size_t)s * LL + lane + 32];
    }
    float v0 = a0 + b2[lane];
    float v1 = (lane < 8) ? a1 + b2[lane + 32] : -INFINITY;
    float m = fmaxf(v0, v1);
    for (int o = 16; o; o >>= 1) m = fmaxf(m, __shfl_xor_sync(0xffffffffu, m, o));
    float z = expf(v0 - m) + ((lane < 8) ? expf(v1 - m) : 0.f);
    for (int o = 16; o; o >>= 1) z += __shfl_xor_sync(0xffffffffu, z, o);
    float ls = logf(z);
    out[(size_t)node * LL + lane] = v0 - m - ls;
    if (lane < 8) out[(size_t)node * LL + lane + 32] = v1 - m - ls;
}

// ---------------- launch ----------------
extern "C" void kernel_launch(void* const* d_in, const int* in_sizes, int n_in,
                              void* d_out, int out_size) {
    const float* x   = (const float*)d_in[0];
    const void*  ei  = d_in[1];
    const float* W1  = (const float*)d_in[2];
    const float* b1  = (const float*)d_in[3];
    const float* Wg  = (const float*)d_in[4];
    const float* a_s = (const float*)d_in[5];
    const float* a_d = (const float*)d_in[6];
    const float* bg  = (const float*)d_in[7];
    const float* W2  = (const float*)d_in[8];
    const float* b2  = (const float*)d_in[9];
    float* out = (float*)d_out;

    float *pA, *pB, *pH2;
    __nv_bfloat16 *pWhi, *pWlo;
    cudaGetSymbolAddress((void**)&pA, g_bufA);
    cudaGetSymbolAddress((void**)&pB, g_bufB);
    cudaGetSymbolAddress((void**)&pH2, g_h2);
    cudaGetSymbolAddress((void**)&pWhi, g_Whi4);
    cudaGetSymbolAddress((void**)&pWlo, g_Wlo4);

    cudaFuncSetAttribute(mma_gemm_kernel, cudaFuncAttributeMaxDynamicSharedMemorySize, MMA_SMEM);

    const int tpb = 256;
    zero_kernel<<<(NN + tpb - 1) / tpb, tpb>>>();
    detect_kernel<<<1, 32>>>((const unsigned int*)ei);
    convert_kernel<<<(EE + tpb - 1) / tpb, tpb>>>(ei);
    stats_kernel<<<256, 256>>>(x);
    finalize_kernel<<<1, 256>>>();
    standardize_kernel<<<(NN * 64 + tpb - 1) / tpb, tpb>>>(x);
    dinv_kernel<<<(NN + tpb - 1) / tpb, tpb>>>();
    scan_kernel<<<1, 1024>>>();
    fill_kernel<<<(EE + tpb - 1) / tpb, tpb>>>();

    dim3 gMMA(2, (NN + 127) / 128);
    dim3 g40((40 + 63) / 64, (NN + 127) / 128);
    int warpGrid = (NN * 32 + tpb - 1) / tpb;

    // GCN layer 1 (+ReLU)
    splitW_kernel<<<(256 * 256) / tpb, tpb>>>(W1);
    mma_gemm_kernel<<<gMMA, 256, MMA_SMEM>>>(pA, pWhi, pWlo, pB, NN);
    gcn_agg_kernel<<<warpGrid, tpb>>>(pB, b1, pA, 1);

    // GAT layer 1 (+ReLU)
    splitW_kernel<<<(256 * 256) / tpb, tpb>>>(Wg);
    mma_gemm_kernel<<<gMMA, 256, MMA_SMEM>>>(pA, pWhi, pWlo, pB, NN);
    al_kernel<<<warpGrid, tpb>>>(pB, a_s, a_d);
    gat_agg_kernel<<<warpGrid, tpb>>>(pB, bg, pA);

    // GAT layer 2 (+ReLU) — Wg planes already split
    mma_gemm_kernel<<<gMMA, 256, MMA_SMEM>>>(pA, pWhi, pWlo, pB, NN);
    al_kernel<<<warpGrid, tpb>>>(pB, a_s, a_d);
    gat_agg_kernel<<<warpGrid, tpb>>>(pB, bg, pA);

    // GCN layer 2 + log_softmax
    gemm_kernel<<<g40, 256>>>(pA, W2, pH2, NN, 40);
    gcn2_kernel<<<warpGrid, tpb>>>(pH2, b2, out);
}

// round 4
// speedup vs baseline: 1.5123x; 1.1739x over previous
#include <cuda_runtime.h>
#include <cuda_bf16.h>
#include <math.h>
#include <stdint.h>

#define NN 50000
#define EE 800000
#define DD 256
#define HH 256
#define LL 40

// ---------------- scratch (device globals; no allocation allowed) ----------------
__device__ float g_bufA[(size_t)NN * HH];   // 51.2 MB
__device__ float g_bufB[(size_t)NN * HH];   // 51.2 MB
__device__ float g_h2[(size_t)NN * LL];     // 8 MB
__device__ int   g_src[EE];
__device__ int   g_dst[EE];
__device__ int   g_col[EE];
__device__ int   g_counts[NN];
__device__ int   g_rowptr[NN + 1];
__device__ int   g_cursor[NN];
__device__ float g_dinv[NN];
__device__ float g_als[NN];
__device__ float g_ald[NN];
__device__ float g_colsum[DD];
__device__ float g_colsumsq[DD];
__device__ float g_mean[DD];
__device__ float g_istd[DD];
__device__ int   g_flag;  // 1 = edge_index is int64, 0 = int32
// transposed + split weight planes: [n][k] bf16, 16B-aligned via uint4 backing
__device__ uint4 g_Whi4[(256 * 256) / 8];
__device__ uint4 g_Wlo4[(256 * 256) / 8];

__device__ __forceinline__ float lrelu(float v) { return v > 0.f ? v : 0.2f * v; }
__device__ __forceinline__ uint32_t swz128(uint32_t o) { return o ^ ((o >> 3) & 0x70); }

__device__ __forceinline__ uint32_t smem_u32(const void* p) {
    uint32_t a;
    asm("{ .reg .u64 t; cvta.to.shared.u64 t, %1; cvt.u32.u64 %0, t; }" : "=r"(a) : "l"(p));
    return a;
}

#define LDSM_X4(r0, r1, r2, r3, addr)                                               \
    asm volatile("ldmatrix.sync.aligned.m8n8.x4.shared.b16 {%0,%1,%2,%3}, [%4];"    \
                 : "=r"(r0), "=r"(r1), "=r"(r2), "=r"(r3) : "r"(addr))

#define MMA16816(d, a, b)                                                           \
    asm volatile("mma.sync.aligned.m16n8k16.row.col.f32.bf16.bf16.f32 "             \
                 "{%0,%1,%2,%3}, {%4,%5,%6,%7}, {%8,%9}, {%0,%1,%2,%3};"            \
                 : "+f"((d)[0]), "+f"((d)[1]), "+f"((d)[2]), "+f"((d)[3])           \
                 : "r"((a)[0]), "r"((a)[1]), "r"((a)[2]), "r"((a)[3]),              \
                   "r"((b)[0]), "r"((b)[1]))

// ---------------- setup kernels ----------------
__global__ void zero_kernel() {
    int i = blockIdx.x * blockDim.x + threadIdx.x;
    if (i < NN) g_counts[i] = 0;
    if (i < DD) { g_colsum[i] = 0.f; g_colsumsq[i] = 0.f; }
}

__global__ void detect_kernel(const unsigned int* __restrict__ p) {
    if (blockIdx.x == 0 && threadIdx.x == 0) {
        int is64 = 1;
        for (int i = 0; i < 64; i++)
            if (p[2 * i + 1] != 0u) { is64 = 0; break; }
        g_flag = is64;
    }
}

__global__ void convert_kernel(const void* __restrict__ ei) {
    int e = blockIdx.x * blockDim.x + threadIdx.x;
    if (e >= EE) return;
    int s, d;
    if (g_flag) {
        const long long* p = (const long long*)ei;
        s = (int)p[e]; d = (int)p[EE + e];
    } else {
        const int* p = (const int*)ei;
        s = p[e]; d = p[EE + e];
    }
    g_src[e] = s;
    g_dst[e] = d;
    atomicAdd(&g_counts[d], 1);
}

// block covers 256 contiguous rows; thread does 64 rows in 16 iters of 4 (MLP=4)
__global__ void stats_kernel(const float* __restrict__ x) {
    int cg = threadIdx.x & 63;
    int rl = threadIdx.x >> 6;   // 0..3
    int base = blockIdx.x * 256 + rl * 64;
    float4 s = make_float4(0.f, 0.f, 0.f, 0.f);
    float4 s2 = make_float4(0.f, 0.f, 0.f, 0.f);
#pragma unroll 1
    for (int i = 0; i < 64; i += 4) {
        float4 v[4];
#pragma unroll
        for (int j = 0; j < 4; j++) {
            int r = base + i + j;
            v[j] = (r < NN) ? ((const float4*)x)[(size_t)r * 64 + cg]
                            : make_float4(0.f, 0.f, 0.f, 0.f);
        }
#pragma unroll
        for (int j = 0; j < 4; j++) {
            s.x += v[j].x; s.y += v[j].y; s.z += v[j].z; s.w += v[j].w;
            s2.x += v[j].x * v[j].x; s2.y += v[j].y * v[j].y;
            s2.z += v[j].z * v[j].z; s2.w += v[j].w * v[j].w;
        }
    }
    int c = cg * 4;
    atomicAdd(&g_colsum[c + 0], s.x); atomicAdd(&g_colsum[c + 1], s.y);
    atomicAdd(&g_colsum[c + 2], s.z); atomicAdd(&g_colsum[c + 3], s.w);
    atomicAdd(&g_colsumsq[c + 0], s2.x); atomicAdd(&g_colsumsq[c + 1], s2.y);
    atomicAdd(&g_colsumsq[c + 2], s2.z); atomicAdd(&g_colsumsq[c + 3], s2.w);
}

__global__ void finalize_kernel() {
    int c = threadIdx.x;
    float mean = g_colsum[c] / (float)NN;
    float var = (g_colsumsq[c] - (float)NN * mean * mean) / (float)(NN - 1);
    g_mean[c] = mean;
    g_istd[c] = rsqrtf(var);
}

__global__ void dinv_kernel() {
    int i = blockIdx.x * blockDim.x + threadIdx.x;
    if (i < NN) g_dinv[i] = rsqrtf((float)(g_counts[i] + 1));
}

// shfl-based scan, 4 barriers per 1024-chunk
__global__ void scan_kernel() {
    __shared__ int warpsum[32];
    __shared__ int s_off;
    int tid = threadIdx.x;
    int lane = tid & 31, wid = tid >> 5;
    if (tid == 0) s_off = 0;
    __syncthreads();
    for (int base = 0; base < NN; base += 1024) {
        int i = base + tid;
        int v = (i < NN) ? g_counts[i] : 0;
        int xs = v;
#pragma unroll
        for (int d = 1; d < 32; d <<= 1) {
            int t = __shfl_up_sync(0xffffffffu, xs, d);
            if (lane >= d) xs += t;
        }
        if (lane == 31) warpsum[wid] = xs;
        __syncthreads();
        if (wid == 0) {
            int w = warpsum[lane];
#pragma unroll
            for (int d = 1; d < 32; d <<= 1) {
                int t = __shfl_up_sync(0xffffffffu, w, d);
                if (lane >= d) w += t;
            }
            warpsum[lane] = w;
        }
        __syncthreads();
        int excl = xs - v + (wid ? warpsum[wid - 1] : 0);
        int off = s_off;
        if (i < NN) { g_rowptr[i] = off + excl; g_cursor[i] = off + excl; }
        __syncthreads();
        if (tid == 1023) s_off = off + excl + v;
        __syncthreads();
    }
    if (tid == 0) g_rowptr[NN] = s_off;
}

__global__ void fill_kernel() {
    int e = blockIdx.x * blockDim.x + threadIdx.x;
    if (e >= EE) return;
    int d = g_dst[e];
    int p = atomicAdd(&g_cursor[d], 1);
    g_col[p] = g_src[e];
}

// ---------------- weight transpose + hi/lo split: out[n][k] = split(W[k][n]) ---------------
__global__ void splitW_kernel(const float* __restrict__ W) {
    int idx = blockIdx.x * blockDim.x + threadIdx.x;
    if (idx >= 256 * 256) return;
    int k = idx >> 8;
    int n = idx & 255;
    float v = W[idx];
    __nv_bfloat16 h = __float2bfloat16(v);
    float r = v - __bfloat162float(h);
    __nv_bfloat16* whi = (__nv_bfloat16*)g_Whi4;
    __nv_bfloat16* wlo = (__nv_bfloat16*)g_Wlo4;
    whi[n * 256 + k] = h;
    wlo[n * 256 + k] = __float2bfloat16(r);
}

// ---------------- mma.sync GEMM: C[M,256] = A[M,256] @ Wsplit^T (bf16 hi/lo 3-term) --------
#define SO_AHI 0
#define SO_ALO 16384
#define SO_BHI 32768
#define SO_BLO 49152
#define MMA_SMEM 65536

__global__ void __launch_bounds__(256) mma_gemm_kernel(
    const float* __restrict__ A, const __nv_bfloat16* __restrict__ Bhi_g,
    const __nv_bfloat16* __restrict__ Blo_g, float* __restrict__ C, int M, int doStd) {
    extern __shared__ char smem[];
    uint32_t sb = smem_u32(smem);
    int tid = threadIdx.x;
    int wid = tid >> 5, lane = tid & 31;
    int bm = blockIdx.y * 128;
    int bn = blockIdx.x * 128;
    int wm = (wid >> 1) * 32;
    int wn = (wid & 1) * 64;

    float acc[2][8][4];
#pragma unroll
    for (int mt = 0; mt < 2; mt++)
#pragma unroll
        for (int nt = 0; nt < 8; nt++)
#pragma unroll
            for (int r = 0; r < 4; r++) acc[mt][nt][r] = 0.f;

    uint32_t b_row[4], b_cb;
#pragma unroll
    for (int ntp = 0; ntp < 4; ntp++)
        b_row[ntp] = (uint32_t)(wn + ntp * 16 + (lane & 7) + ((lane >> 4) << 3));
    b_cb = (uint32_t)(((lane >> 3) & 1) * 16);

    for (int ch = 0; ch < 4; ch++) {
        int k0 = ch * 64;
        __syncthreads();
        // ---- stage B chunk first (pure copies, MLP-friendly) ----
#pragma unroll
        for (int i = 0; i < 4; i++) {
            int lin = tid + i * 256;
            int row = lin >> 3;
            int u8 = lin & 7;
            uint32_t so = swz128((uint32_t)(row * 128 + u8 * 16));
            const uint4* sh = (const uint4*)(Bhi_g + (size_t)(bn + row) * 256 + k0);
            const uint4* sl = (const uint4*)(Blo_g + (size_t)(bn + row) * 256 + k0);
            *(uint4*)(smem + SO_BHI + so) = sh[u8];
            *(uint4*)(smem + SO_BLO + so) = sl[u8];
        }
        // ---- stage A chunk [128 x 64] fp32 -> (optional standardize) -> bf16 hi/lo ----
#pragma unroll
        for (int i = 0; i < 8; i++) {
            int lin = tid + i * 256;
            int row = lin >> 4;
            int c4 = (lin & 15) * 4;
            float4 v = make_float4(0.f, 0.f, 0.f, 0.f);
            int gr = bm + row;
            if (gr < M) v = *(const float4*)(A + (size_t)gr * 256 + k0 + c4);
            if (doStd) {
                int cc = k0 + c4;
                v.x = (v.x - g_mean[cc + 0]) * g_istd[cc + 0];
                v.y = (v.y - g_mean[cc + 1]) * g_istd[cc + 1];
                v.z = (v.z - g_mean[cc + 2]) * g_istd[cc + 2];
                v.w = (v.w - g_mean[cc + 3]) * g_istd[cc + 3];
            }
            __nv_bfloat16 hx = __float2bfloat16(v.x), hy = __float2bfloat16(v.y);
            __nv_bfloat16 hz = __float2bfloat16(v.z), hw = __float2bfloat16(v.w);
            __nv_bfloat16 lx = __float2bfloat16(v.x - __bfloat162float(hx));
            __nv_bfloat16 ly = __float2bfloat16(v.y - __bfloat162float(hy));
            __nv_bfloat16 lz = __float2bfloat16(v.z - __bfloat162float(hz));
            __nv_bfloat16 lw = __float2bfloat16(v.w - __bfloat162float(hw));
            uint32_t so = swz128((uint32_t)(row * 128 + c4 * 2));
            __nv_bfloat162 p0, p1;
            p0.x = hx; p0.y = hy; p1.x = hz; p1.y = hw;
            uint2 uh = make_uint2(*(unsigned*)&p0, *(unsigned*)&p1);
            p0.x = lx; p0.y = ly; p1.x = lz; p1.y = lw;
            uint2 ul = make_uint2(*(unsigned*)&p0, *(unsigned*)&p1);
            *(uint2*)(smem + SO_AHI + so) = uh;
            *(uint2*)(smem + SO_ALO + so) = ul;
        }
        __syncthreads();

#pragma unroll
        for (int ks = 0; ks < 4; ks++) {
            uint32_t kb = (uint32_t)(ks * 32);
            uint32_t ah[2][4], al[2][4];
#pragma unroll
            for (int mt = 0; mt < 2; mt++) {
                uint32_t row = (uint32_t)(wm + mt * 16 + (lane & 15));
                uint32_t cb = (uint32_t)((lane >> 4) * 16) + kb;
                uint32_t ad = sb + swz128(row * 128 + cb);
                LDSM_X4(ah[mt][0], ah[mt][1], ah[mt][2], ah[mt][3], ad + SO_AHI);
                LDSM_X4(al[mt][0], al[mt][1], al[mt][2], al[mt][3], ad + SO_ALO);
            }
            uint32_t bh[8][2], bl[8][2];
#pragma unroll
            for (int ntp = 0; ntp < 4; ntp++) {
                uint32_t bd = sb + swz128(b_row[ntp] * 128 + b_cb + kb);
                LDSM_X4(bh[2 * ntp][0], bh[2 * ntp][1], bh[2 * ntp + 1][0],
                        bh[2 * ntp + 1][1], bd + SO_BHI);
                LDSM_X4(bl[2 * ntp][0], bl[2 * ntp][1], bl[2 * ntp + 1][0],
                        bl[2 * ntp + 1][1], bd + SO_BLO);
            }
#pragma unroll
            for (int mt = 0; mt < 2; mt++)
#pragma unroll
                for (int nt = 0; nt < 8; nt++) {
                    MMA16816(acc[mt][nt], ah[mt], bh[nt]);
                    MMA16816(acc[mt][nt], ah[mt], bl[nt]);
                    MMA16816(acc[mt][nt], al[mt], bh[nt]);
                }
        }
    }

#pragma unroll
    for (int mt = 0; mt < 2; mt++) {
        int r0 = bm + wm + mt * 16 + (lane >> 2);
        int r1 = r0 + 8;
#pragma unroll
        for (int nt = 0; nt < 8; nt++) {
            int col = bn + wn + nt * 8 + (lane & 3) * 2;
            if (r0 < M) *(float2*)(C + (size_t)r0 * 256 + col) =
                make_float2(acc[mt][nt][0], acc[mt][nt][1]);
            if (r1 < M) *(float2*)(C + (size_t)r1 * 256 + col) =
                make_float2(acc[mt][nt][2], acc[mt][nt][3]);
        }
    }
}

// ---------------- SIMT GEMM (final 256x40 layer) ----------------
__global__ void gemm_kernel(const float* __restrict__ A, const float* __restrict__ B,
                            float* __restrict__ C, int M, int Nn) {
    const int K = 256;
    __shared__ float As[16][128];
    __shared__ float Bs[16][64];
    int tid = threadIdx.x;
    int bm = blockIdx.y * 128;
    int bn = blockIdx.x * 64;
    int tx = tid & 15;
    int ty = tid >> 4;
    float acc[8][4];
#pragma unroll
    for (int i = 0; i < 8; i++)
#pragma unroll
        for (int j = 0; j < 4; j++) acc[i][j] = 0.f;

    for (int k0 = 0; k0 < K; k0 += 16) {
#pragma unroll
        for (int l = 0; l < 2; l++) {
            int lin = tid + l * 256;
            int row = lin >> 2;
            int c4 = (lin & 3) * 4;
            float4 v = make_float4(0.f, 0.f, 0.f, 0.f);
            if (bm + row < M)
                v = *(const float4*)(A + (size_t)(bm + row) * K + k0 + c4);
            As[c4 + 0][row] = v.x;
            As[c4 + 1][row] = v.y;
            As[c4 + 2][row] = v.z;
            As[c4 + 3][row] = v.w;
        }
        {
            int row = tid >> 4;
            int c4 = (tid & 15) * 4;
#pragma unroll
            for (int j = 0; j < 4; j++) {
                int cc = bn + c4 + j;
                Bs[row][c4 + j] = (cc < Nn) ? B[(size_t)(k0 + row) * Nn + cc] : 0.f;
            }
        }
        __syncthreads();
#pragma unroll
        for (int k = 0; k < 16; k++) {
            float4 a0 = *(const float4*)&As[k][ty * 8];
            float4 a1 = *(const float4*)&As[k][ty * 8 + 4];
            float4 b0 = *(const float4*)&Bs[k][tx * 4];
            float a[8] = {a0.x, a0.y, a0.z, a0.w, a1.x, a1.y, a1.z, a1.w};
            float b[4] = {b0.x, b0.y, b0.z, b0.w};
#pragma unroll
            for (int i = 0; i < 8; i++)
#pragma unroll
                for (int j = 0; j < 4; j++) acc[i][j] += a[i] * b[j];
        }
        __syncthreads();
    }
#pragma unroll
    for (int i = 0; i < 8; i++) {
        int row = bm + ty * 8 + i;
        if (row >= M) continue;
#pragma unroll
        for (int j = 0; j < 4; j++) {
            int col = bn + tx * 4 + j;
            if (col < Nn) C[(size_t)row * Nn + col] = acc[i][j];
        }
    }
}

// ---------------- GCN aggregate (warp per dst node, unroll-2 edge loop) ----------------
__global__ void gcn_agg_kernel(const float* __restrict__ h, const float* __restrict__ bias,
                               float* __restrict__ out, int do_relu) {
    int t = blockIdx.x * blockDim.x + threadIdx.x;
    int node = t >> 5;
    int lane = t & 31;
    if (node >= NN) return;
    int beg = g_rowptr[node], end = g_rowptr[node + 1];
    float di = g_dinv[node];
    const float4* h4 = (const float4*)h;
    float w = di * di;
    float4 v0 = h4[node * 64 + lane];
    float4 v1 = h4[node * 64 + lane + 32];
    float4 a0 = make_float4(w * v0.x, w * v0.y, w * v0.z, w * v0.w);
    float4 a1 = make_float4(w * v1.x, w * v1.y, w * v1.z, w * v1.w);
    int e = beg;
    for (; e + 2 <= end; e += 2) {
        int s0 = g_col[e], s1 = g_col[e + 1];
        float w0 = g_dinv[s0] * di, w1 = g_dinv[s1] * di;
        float4 u0 = h4[s0 * 64 + lane];
        float4 u1 = h4[s0 * 64 + lane + 32];
        float4 p0 = h4[s1 * 64 + lane];
        float4 p1 = h4[s1 * 64 + lane + 32];
        a0.x += w0 * u0.x + w1 * p0.x; a0.y += w0 * u0.y + w1 * p0.y;
        a0.z += w0 * u0.z + w1 * p0.z; a0.w += w0 * u0.w + w1 * p0.w;
        a1.x += w0 * u1.x + w1 * p1.x; a1.y += w0 * u1.y + w1 * p1.y;
        a1.z += w0 * u1.z + w1 * p1.z; a1.w += w0 * u1.w + w1 * p1.w;
    }
    if (e < end) {
        int s = g_col[e];
        float we = g_dinv[s] * di;
        v0 = h4[s * 64 + lane];
        v1 = h4[s * 64 + lane + 32];
        a0.x += we * v0.x; a0.y += we * v0.y; a0.z += we * v0.z; a0.w += we * v0.w;
        a1.x += we * v1.x; a1.y += we * v1.y; a1.z += we * v1.z; a1.w += we * v1.w;
    }
    float4 b0 = ((const float4*)bias)[lane];
    float4 b1 = ((const float4*)bias)[lane + 32];
    a0.x += b0.x; a0.y += b0.y; a0.z += b0.z; a0.w += b0.w;
    a1.x += b1.x; a1.y += b1.y; a1.z += b1.z; a1.w += b1.w;
    if (do_relu) {
        a0.x = fmaxf(a0.x, 0.f); a0.y = fmaxf(a0.y, 0.f);
        a0.z = fmaxf(a0.z, 0.f); a0.w = fmaxf(a0.w, 0.f);
        a1.x = fmaxf(a1.x, 0.f); a1.y = fmaxf(a1.y, 0.f);
        a1.z = fmaxf(a1.z, 0.f); a1.w = fmaxf(a1.w, 0.f);
    }
    ((float4*)out)[node * 64 + lane] = a0;
    ((float4*)out)[node * 64 + lane + 32] = a1;
}

// ---------------- GAT attention logits ----------------
__global__ void al_kernel(const float* __restrict__ h, const float* __restrict__ asrc,
                          const float* __restrict__ adst) {
    int t = blockIdx.x * blockDim.x + threadIdx.x;
    int node = t >> 5;
    int lane = t & 31;
    if (node >= NN) return;
    const float4* h4 = (const float4*)h + node * 64;
    float4 v0 = h4[lane], v1 = h4[lane + 32];
    float4 s0 = ((const float4*)asrc)[lane], s1 = ((const float4*)asrc)[lane + 32];
    float4 d0 = ((const float4*)adst)[lane], d1 = ((const float4*)adst)[lane + 32];
    float ds = v0.x * s0.x + v0.y * s0.y + v0.z * s0.z + v0.w * s0.w +
               v1.x * s1.x + v1.y * s1.y + v1.z * s1.z + v1.w * s1.w;
    float dd = v0.x * d0.x + v0.y * d0.y + v0.z * d0.z + v0.w * d0.w +
               v1.x * d1.x + v1.y * d1.y + v1.z * d1.z + v1.w * d1.w;
    for (int o = 16; o; o >>= 1) {
        ds += __shfl_xor_sync(0xffffffffu, ds, o);
        dd += __shfl_xor_sync(0xffffffffu, dd, o);
    }
    if (lane == 0) { g_als[node] = ds; g_ald[node] = dd; }
}

// ---------------- GAT aggregate with segment softmax (unroll-2) ----------------
__global__ void gat_agg_kernel(const float* __restrict__ h, const float* __restrict__ bias,
                               float* __restrict__ out) {
    int t = blockIdx.x * blockDim.x + threadIdx.x;
    int node = t >> 5;
    int lane = t & 31;
    if (node >= NN) return;
    int beg = g_rowptr[node], end = g_rowptr[node + 1];
    float aldi = g_ald[node];
    float e_self = lrelu(g_als[node] + aldi);
    float m = e_self;
    for (int e = beg + lane; e < end; e += 32)
        m = fmaxf(m, lrelu(g_als[g_col[e]] + aldi));
    for (int o = 16; o; o >>= 1) m = fmaxf(m, __shfl_xor_sync(0xffffffffu, m, o));
    const float4* h4 = (const float4*)h;
    float z = __expf(e_self - m);
    float4 v0 = h4[node * 64 + lane];
    float4 v1 = h4[node * 64 + lane + 32];
    float4 a0 = make_float4(z * v0.x, z * v0.y, z * v0.z, z * v0.w);
    float4 a1 = make_float4(z * v1.x, z * v1.y, z * v1.z, z * v1.w);
    int e = beg;
    for (; e + 2 <= end; e += 2) {
        int s0 = g_col[e], s1 = g_col[e + 1];
        float w0 = __expf(lrelu(g_als[s0] + aldi) - m);
        float w1 = __expf(lrelu(g_als[s1] + aldi) - m);
        z += w0 + w1;
        float4 u0 = h4[s0 * 64 + lane];
        float4 u1 = h4[s0 * 64 + lane + 32];
        float4 p0 = h4[s1 * 64 + lane];
        float4 p1 = h4[s1 * 64 + lane + 32];
        a0.x += w0 * u0.x + w1 * p0.x; a0.y += w0 * u0.y + w1 * p0.y;
        a0.z += w0 * u0.z + w1 * p0.z; a0.w += w0 * u0.w + w1 * p0.w;
        a1.x += w0 * u1.x + w1 * p1.x; a1.y += w0 * u1.y + w1 * p1.y;
        a1.z += w0 * u1.z + w1 * p1.z; a1.w += w0 * u1.w + w1 * p1.w;
    }
    if (e < end) {
        int s = g_col[e];
        float w = __expf(lrelu(g_als[s] + aldi) - m);
        z += w;
        v0 = h4[s * 64 + lane];
        v1 = h4[s * 64 + lane + 32];
        a0.x += w * v0.x; a0.y += w * v0.y; a0.z += w * v0.z; a0.w += w * v0.w;
        a1.x += w * v1.x; a1.y += w * v1.y; a1.z += w * v1.z; a1.w += w * v1.w;
    }
    float inv = 1.0f / z;
    float4 b0 = ((const float4*)bias)[lane];
    float4 b1 = ((const float4*)bias)[lane + 32];
    a0.x = fmaxf(a0.x * inv + b0.x, 0.f); a0.y = fmaxf(a0.y * inv + b0.y, 0.f);
    a0.z = fmaxf(a0.z * inv + b0.z, 0.f); a0.w = fmaxf(a0.w * inv + b0.w, 0.f);
    a1.x = fmaxf(a1.x * inv + b1.x, 0.f); a1.y = fmaxf(a1.y * inv + b1.y, 0.f);
    a1.z = fmaxf(a1.z * inv + b1.z, 0.f); a1.w = fmaxf(a1.w * inv + b1.w, 0.f);
    ((float4*)out)[node * 64 + lane] = a0;
    ((float4*)out)[node * 64 + lane + 32] = a1;
}

// ---------------- final GCN (L=40) + log_softmax (unroll-2) ----------------
__global__ void gcn2_kernel(const float* __restrict__ h2, const float* __restrict__ b2,
                            float* __restrict__ out) {
    int t = blockIdx.x * blockDim.x + threadIdx.x;
    int node = t >> 5;
    int lane = t & 31;
    if (node >= NN) return;
    int beg = g_rowptr[node], end = g_rowptr[node + 1];
    float di = g_dinv[node];
    float w = di * di;
    float a0 = w * h2[(size_t)node * LL + lane];
    float a1 = (lane < 8) ? w * h2[(size_t)node * LL + lane + 32] : 0.f;
    int e = beg;
    for (; e + 2 <= end; e += 2) {
        int s0 = g_col[e], s1 = g_col[e + 1];
        float w0 = g_dinv[s0] * di, w1 = g_dinv[s1] * di;
        float x0 = h2[(size_t)s0 * LL + lane];
        float x1 = h2[(size_t)s1 * LL + lane];
        a0 += w0 * x0 + w1 * x1;
        if (lane < 8) {
            a1 += w0 * h2[(size_t)s0 * LL + lane + 32] + w1 * h2[(size_t)s1 * LL + lane + 32];
        }
    }
    if (e < end) {
        int s = g_col[e];
        float we = g_dinv[s] * di;
        a0 += we * h2[(size_t)s * LL + lane];
        if (lane < 8) a1 += we * h2[(size_t)s * LL + lane + 32];
    }
    float v0 = a0 + b2[lane];
    float v1 = (lane < 8) ? a1 + b2[lane + 32] : -INFINITY;
    float m = fmaxf(v0, v1);
    for (int o = 16; o; o >>= 1) m = fmaxf(m, __shfl_xor_sync(0xffffffffu, m, o));
    float z = expf(v0 - m) + ((lane < 8) ? expf(v1 - m) : 0.f);
    for (int o = 16; o; o >>= 1) z += __shfl_xor_sync(0xffffffffu, z, o);
    float ls = logf(z);
    out[(size_t)node * LL + lane] = v0 - m - ls;
    if (lane < 8) out[(size_t)node * LL + lane + 32] = v1 - m - ls;
}

// ---------------- launch ----------------
extern "C" void kernel_launch(void* const* d_in, const int* in_sizes, int n_in,
                              void* d_out, int out_size) {
    const float* x   = (const float*)d_in[0];
    const void*  ei  = d_in[1];
    const float* W1  = (const float*)d_in[2];
    const float* b1  = (const float*)d_in[3];
    const float* Wg  = (const float*)d_in[4];
    const float* a_s = (const float*)d_in[5];
    const float* a_d = (const float*)d_in[6];
    const float* bg  = (const float*)d_in[7];
    const float* W2  = (const float*)d_in[8];
    const float* b2  = (const float*)d_in[9];
    float* out = (float*)d_out;

    float *pA, *pB, *pH2;
    __nv_bfloat16 *pWhi, *pWlo;
    cudaGetSymbolAddress((void**)&pA, g_bufA);
    cudaGetSymbolAddress((void**)&pB, g_bufB);
    cudaGetSymbolAddress((void**)&pH2, g_h2);
    cudaGetSymbolAddress((void**)&pWhi, g_Whi4);
    cudaGetSymbolAddress((void**)&pWlo, g_Wlo4);

    cudaFuncSetAttribute(mma_gemm_kernel, cudaFuncAttributeMaxDynamicSharedMemorySize, MMA_SMEM);

    const int tpb = 256;
    zero_kernel<<<(NN + tpb - 1) / tpb, tpb>>>();
    detect_kernel<<<1, 32>>>((const unsigned int*)ei);
    convert_kernel<<<(EE + tpb - 1) / tpb, tpb>>>(ei);
    stats_kernel<<<(NN + 255) / 256, 256>>>(x);
    finalize_kernel<<<1, 256>>>();
    dinv_kernel<<<(NN + tpb - 1) / tpb, tpb>>>();
    scan_kernel<<<1, 1024>>>();
    fill_kernel<<<(EE + tpb - 1) / tpb, tpb>>>();

    dim3 gMMA(2, (NN + 127) / 128);
    dim3 g40((40 + 63) / 64, (NN + 127) / 128);
    int warpGrid = (NN * 32 + tpb - 1) / tpb;

    // GCN layer 1 (+ReLU): standardize fused into A-staging, reads x directly
    splitW_kernel<<<(256 * 256) / tpb, tpb>>>(W1);
    mma_gemm_kernel<<<gMMA, 256, MMA_SMEM>>>(x, pWhi, pWlo, pB, NN, 1);
    gcn_agg_kernel<<<warpGrid, tpb>>>(pB, b1, pA, 1);

    // GAT layer 1 (+ReLU)
    splitW_kernel<<<(256 * 256) / tpb, tpb>>>(Wg);
    mma_gemm_kernel<<<gMMA, 256, MMA_SMEM>>>(pA, pWhi, pWlo, pB, NN, 0);
    al_kernel<<<warpGrid, tpb>>>(pB, a_s, a_d);
    gat_agg_kernel<<<warpGrid, tpb>>>(pB, bg, pA);

    // GAT layer 2 (+ReLU) — Wg planes already split
    mma_gemm_kernel<<<gMMA, 256, MMA_SMEM>>>(pA, pWhi, pWlo, pB, NN, 0);
    al_kernel<<<warpGrid, tpb>>>(pB, a_s, a_d);
    gat_agg_kernel<<<warpGrid, tpb>>>(pB, bg, pA);

    // GCN layer 2 + log_softmax
    gemm_kernel<<<g40, 256>>>(pA, W2, pH2, NN, 40);
    gcn2_kernel<<<warpGrid, tpb>>>(pH2, b2, out);
}

// round 5
// speedup vs baseline: 1.5811x; 1.0455x over previous
#include <cuda_runtime.h>
#include <cuda_bf16.h>
#include <cuda_fp16.h>
#include <math.h>
#include <stdint.h>

#define NN 50000
#define EE 800000
#define DD 256
#define HH 256
#define LL 40

// ---------------- scratch (device globals; no allocation allowed) ----------------
__device__ float g_bufA[(size_t)NN * HH];   // 51.2 MB (fp32 agg outputs / GEMM A inputs)
__device__ uint2 g_h16[(size_t)NN * 64];    // 25.6 MB (fp16 GEMM outputs, half2-packed)
__device__ float g_h2[(size_t)NN * LL];     // 8 MB
__device__ int   g_src[EE];
__device__ int   g_dst[EE];
__device__ int   g_col[EE];
__device__ int   g_counts[NN];
__device__ int   g_rowptr[NN + 1];
__device__ int   g_cursor[NN];
__device__ float g_dinv[NN];
__device__ float g_als[NN];
__device__ float g_ald[NN];
__device__ float g_colsum[DD];
__device__ float g_colsumsq[DD];
__device__ float g_mean[DD];
__device__ float g_istd[DD];
__device__ int   g_flag;  // 1 = edge_index is int64, 0 = int32
__device__ uint4 g_Whi4[(256 * 256) / 8];
__device__ uint4 g_Wlo4[(256 * 256) / 8];

__device__ __forceinline__ float lrelu(float v) { return v > 0.f ? v : 0.2f * v; }
__device__ __forceinline__ uint32_t swz128(uint32_t o) { return o ^ ((o >> 3) & 0x70); }

__device__ __forceinline__ uint32_t smem_u32(const void* p) {
    uint32_t a;
    asm("{ .reg .u64 t; cvta.to.shared.u64 t, %1; cvt.u32.u64 %0, t; }" : "=r"(a) : "l"(p));
    return a;
}

#define LDSM_X4(r0, r1, r2, r3, addr)                                               \
    asm volatile("ldmatrix.sync.aligned.m8n8.x4.shared.b16 {%0,%1,%2,%3}, [%4];"    \
                 : "=r"(r0), "=r"(r1), "=r"(r2), "=r"(r3) : "r"(addr))

#define MMA16816(d, a, b)                                                           \
    asm volatile("mma.sync.aligned.m16n8k16.row.col.f32.bf16.bf16.f32 "             \
                 "{%0,%1,%2,%3}, {%4,%5,%6,%7}, {%8,%9}, {%0,%1,%2,%3};"            \
                 : "+f"((d)[0]), "+f"((d)[1]), "+f"((d)[2]), "+f"((d)[3])           \
                 : "r"((a)[0]), "r"((a)[1]), "r"((a)[2]), "r"((a)[3]),              \
                   "r"((b)[0]), "r"((b)[1]))

// ---------------- setup kernels ----------------
__global__ void zero_kernel() {
    int i = blockIdx.x * blockDim.x + threadIdx.x;
    if (i < NN) g_counts[i] = 0;
    if (i < DD) { g_colsum[i] = 0.f; g_colsumsq[i] = 0.f; }
}

__global__ void zero_al_kernel() {
    int i = blockIdx.x * blockDim.x + threadIdx.x;
    if (i < NN) { g_als[i] = 0.f; g_ald[i] = 0.f; }
}

__global__ void detect_kernel(const unsigned int* __restrict__ p) {
    if (blockIdx.x == 0 && threadIdx.x == 0) {
        int is64 = 1;
        for (int i = 0; i < 64; i++)
            if (p[2 * i + 1] != 0u) { is64 = 0; break; }
        g_flag = is64;
    }
}

__global__ void convert_kernel(const void* __restrict__ ei) {
    int e = blockIdx.x * blockDim.x + threadIdx.x;
    if (e >= EE) return;
    int s, d;
    if (g_flag) {
        const long long* p = (const long long*)ei;
        s = (int)p[e]; d = (int)p[EE + e];
    } else {
        const int* p = (const int*)ei;
        s = p[e]; d = p[EE + e];
    }
    g_src[e] = s;
    g_dst[e] = d;
    atomicAdd(&g_counts[d], 1);
}

// 1563 blocks x 256 thr; thread: 8-row burst (MLP=8); block-level smem reduce
__global__ void stats_kernel(const float* __restrict__ x) {
    __shared__ float4 ss[256], ss2[256];
    int cg = threadIdx.x & 63;
    int r0 = (blockIdx.x * 4 + (threadIdx.x >> 6)) * 8;
    float4 s = make_float4(0.f, 0.f, 0.f, 0.f);
    float4 s2 = make_float4(0.f, 0.f, 0.f, 0.f);
    float4 v[8];
#pragma unroll
    for (int j = 0; j < 8; j++) {
        int r = r0 + j;
        v[j] = (r < NN) ? ((const float4*)x)[(size_t)r * 64 + cg]
                        : make_float4(0.f, 0.f, 0.f, 0.f);
    }
#pragma unroll
    for (int j = 0; j < 8; j++) {
        s.x += v[j].x; s.y += v[j].y; s.z += v[j].z; s.w += v[j].w;
        s2.x += v[j].x * v[j].x; s2.y += v[j].y * v[j].y;
        s2.z += v[j].z * v[j].z; s2.w += v[j].w * v[j].w;
    }
    ss[threadIdx.x] = s; ss2[threadIdx.x] = s2;
    __syncthreads();
    if (threadIdx.x < 64) {
#pragma unroll
        for (int k = 1; k < 4; k++) {
            float4 t = ss[threadIdx.x + 64 * k], t2 = ss2[threadIdx.x + 64 * k];
            s.x += t.x; s.y += t.y; s.z += t.z; s.w += t.w;
            s2.x += t2.x; s2.y += t2.y; s2.z += t2.z; s2.w += t2.w;
        }
        int c = threadIdx.x * 4;
        atomicAdd(&g_colsum[c + 0], s.x); atomicAdd(&g_colsum[c + 1], s.y);
        atomicAdd(&g_colsum[c + 2], s.z); atomicAdd(&g_colsum[c + 3], s.w);
        atomicAdd(&g_colsumsq[c + 0], s2.x); atomicAdd(&g_colsumsq[c + 1], s2.y);
        atomicAdd(&g_colsumsq[c + 2], s2.z); atomicAdd(&g_colsumsq[c + 3], s2.w);
    }
}

__global__ void finalize_kernel() {
    int c = threadIdx.x;
    float mean = g_colsum[c] / (float)NN;
    float var = (g_colsumsq[c] - (float)NN * mean * mean) / (float)(NN - 1);
    g_mean[c] = mean;
    g_istd[c] = rsqrtf(var);
}

__global__ void dinv_kernel() {
    int i = blockIdx.x * blockDim.x + threadIdx.x;
    if (i < NN) g_dinv[i] = rsqrtf((float)(g_counts[i] + 1));
}

__global__ void scan_kernel() {
    __shared__ int warpsum[32];
    __shared__ int s_off;
    int tid = threadIdx.x;
    int lane = tid & 31, wid = tid >> 5;
    if (tid == 0) s_off = 0;
    __syncthreads();
    for (int base = 0; base < NN; base += 1024) {
        int i = base + tid;
        int v = (i < NN) ? g_counts[i] : 0;
        int xs = v;
#pragma unroll
        for (int d = 1; d < 32; d <<= 1) {
            int t = __shfl_up_sync(0xffffffffu, xs, d);
            if (lane >= d) xs += t;
        }
        if (lane == 31) warpsum[wid] = xs;
        __syncthreads();
        if (wid == 0) {
            int w = warpsum[lane];
#pragma unroll
            for (int d = 1; d < 32; d <<= 1) {
                int t = __shfl_up_sync(0xffffffffu, w, d);
                if (lane >= d) w += t;
            }
            warpsum[lane] = w;
        }
        __syncthreads();
        int excl = xs - v + (wid ? warpsum[wid - 1] : 0);
        int off = s_off;
        if (i < NN) { g_rowptr[i] = off + excl; g_cursor[i] = off + excl; }
        __syncthreads();
        if (tid == 1023) s_off = off + excl + v;
        __syncthreads();
    }
    if (tid == 0) g_rowptr[NN] = s_off;
}

__global__ void fill_kernel() {
    int e = blockIdx.x * blockDim.x + threadIdx.x;
    if (e >= EE) return;
    int d = g_dst[e];
    int p = atomicAdd(&g_cursor[d], 1);
    g_col[p] = g_src[e];
}

// ---------------- weight transpose + hi/lo split ----------------
__global__ void splitW_kernel(const float* __restrict__ W) {
    int idx = blockIdx.x * blockDim.x + threadIdx.x;
    if (idx >= 256 * 256) return;
    int k = idx >> 8;
    int n = idx & 255;
    float v = W[idx];
    __nv_bfloat16 h = __float2bfloat16(v);
    float r = v - __bfloat162float(h);
    __nv_bfloat16* whi = (__nv_bfloat16*)g_Whi4;
    __nv_bfloat16* wlo = (__nv_bfloat16*)g_Wlo4;
    whi[n * 256 + k] = h;
    wlo[n * 256 + k] = __float2bfloat16(r);
}

// ---------------- mma.sync GEMM: h16[M,256] = A[M,256] @ Wsplit^T, fused al ---------------
#define SO_AHI 0
#define SO_ALO 16384
#define SO_BHI 32768
#define SO_BLO 49152
#define MMA_SMEM 65536

__global__ void __launch_bounds__(256) mma_gemm_kernel(
    const float* __restrict__ A, const __nv_bfloat16* __restrict__ Bhi_g,
    const __nv_bfloat16* __restrict__ Blo_g, __half* __restrict__ C16, int M,
    int doStd, int doAl, const float* __restrict__ a_src, const float* __restrict__ a_dst) {
    extern __shared__ char smem[];
    uint32_t sb = smem_u32(smem);
    int tid = threadIdx.x;
    int wid = tid >> 5, lane = tid & 31;
    int bm = blockIdx.y * 128;
    int bn = blockIdx.x * 128;
    int wm = (wid >> 1) * 32;
    int wn = (wid & 1) * 64;

    float acc[2][8][4];
#pragma unroll
    for (int mt = 0; mt < 2; mt++)
#pragma unroll
        for (int nt = 0; nt < 8; nt++)
#pragma unroll
            for (int r = 0; r < 4; r++) acc[mt][nt][r] = 0.f;

    uint32_t b_row[4], b_cb;
#pragma unroll
    for (int ntp = 0; ntp < 4; ntp++)
        b_row[ntp] = (uint32_t)(wn + ntp * 16 + (lane & 7) + ((lane >> 4) << 3));
    b_cb = (uint32_t)(((lane >> 3) & 1) * 16);

    for (int ch = 0; ch < 4; ch++) {
        int k0 = ch * 64;
        __syncthreads();
#pragma unroll
        for (int i = 0; i < 4; i++) {
            int lin = tid + i * 256;
            int row = lin >> 3;
            int u8 = lin & 7;
            uint32_t so = swz128((uint32_t)(row * 128 + u8 * 16));
            const uint4* sh = (const uint4*)(Bhi_g + (size_t)(bn + row) * 256 + k0);
            const uint4* sl = (const uint4*)(Blo_g + (size_t)(bn + row) * 256 + k0);
            *(uint4*)(smem + SO_BHI + so) = sh[u8];
            *(uint4*)(smem + SO_BLO + so) = sl[u8];
        }
#pragma unroll
        for (int i = 0; i < 8; i++) {
            int lin = tid + i * 256;
            int row = lin >> 4;
            int c4 = (lin & 15) * 4;
            float4 v = make_float4(0.f, 0.f, 0.f, 0.f);
            int gr = bm + row;
            if (gr < M) v = *(const float4*)(A + (size_t)gr * 256 + k0 + c4);
            if (doStd) {
                int cc = k0 + c4;
                v.x = (v.x - g_mean[cc + 0]) * g_istd[cc + 0];
                v.y = (v.y - g_mean[cc + 1]) * g_istd[cc + 1];
                v.z = (v.z - g_mean[cc + 2]) * g_istd[cc + 2];
                v.w = (v.w - g_mean[cc + 3]) * g_istd[cc + 3];
            }
            __nv_bfloat16 hx = __float2bfloat16(v.x), hy = __float2bfloat16(v.y);
            __nv_bfloat16 hz = __float2bfloat16(v.z), hw = __float2bfloat16(v.w);
            __nv_bfloat16 lx = __float2bfloat16(v.x - __bfloat162float(hx));
            __nv_bfloat16 ly = __float2bfloat16(v.y - __bfloat162float(hy));
            __nv_bfloat16 lz = __float2bfloat16(v.z - __bfloat162float(hz));
            __nv_bfloat16 lw = __float2bfloat16(v.w - __bfloat162float(hw));
            uint32_t so = swz128((uint32_t)(row * 128 + c4 * 2));
            __nv_bfloat162 p0, p1;
            p0.x = hx; p0.y = hy; p1.x = hz; p1.y = hw;
            uint2 uh = make_uint2(*(unsigned*)&p0, *(unsigned*)&p1);
            p0.x = lx; p0.y = ly; p1.x = lz; p1.y = lw;
            uint2 ul = make_uint2(*(unsigned*)&p0, *(unsigned*)&p1);
            *(uint2*)(smem + SO_AHI + so) = uh;
            *(uint2*)(smem + SO_ALO + so) = ul;
        }
        __syncthreads();

#pragma unroll
        for (int ks = 0; ks < 4; ks++) {
            uint32_t kb = (uint32_t)(ks * 32);
            uint32_t ah[2][4], al[2][4];
#pragma unroll
            for (int mt = 0; mt < 2; mt++) {
                uint32_t row = (uint32_t)(wm + mt * 16 + (lane & 15));
                uint32_t cb = (uint32_t)((lane >> 4) * 16) + kb;
                uint32_t ad = sb + swz128(row * 128 + cb);
                LDSM_X4(ah[mt][0], ah[mt][1], ah[mt][2], ah[mt][3], ad + SO_AHI);
                LDSM_X4(al[mt][0], al[mt][1], al[mt][2], al[mt][3], ad + SO_ALO);
            }
            uint32_t bh[8][2], bl[8][2];
#pragma unroll
            for (int ntp = 0; ntp < 4; ntp++) {
                uint32_t bd = sb + swz128(b_row[ntp] * 128 + b_cb + kb);
                LDSM_X4(bh[2 * ntp][0], bh[2 * ntp][1], bh[2 * ntp + 1][0],
                        bh[2 * ntp + 1][1], bd + SO_BHI);
                LDSM_X4(bl[2 * ntp][0], bl[2 * ntp][1], bl[2 * ntp + 1][0],
                        bl[2 * ntp + 1][1], bd + SO_BLO);
            }
#pragma unroll
            for (int mt = 0; mt < 2; mt++)
#pragma unroll
                for (int nt = 0; nt < 8; nt++) {
                    MMA16816(acc[mt][nt], ah[mt], bh[nt]);
                    MMA16816(acc[mt][nt], ah[mt], bl[nt]);
                    MMA16816(acc[mt][nt], al[mt], bh[nt]);
                }
        }
    }

    // ---- epilogue: fp16 store + optional fused attention logits ----
#pragma unroll
    for (int mt = 0; mt < 2; mt++) {
        int r0 = bm + wm + mt * 16 + (lane >> 2);
        int r1 = r0 + 8;
        float ds0 = 0.f, dd0 = 0.f, ds1 = 0.f, dd1 = 0.f;
#pragma unroll
        for (int nt = 0; nt < 8; nt++) {
            int col = bn + wn + nt * 8 + (lane & 3) * 2;
            if (r0 < M) *(__half2*)(C16 + (size_t)r0 * 256 + col) =
                __floats2half2_rn(acc[mt][nt][0], acc[mt][nt][1]);
            if (r1 < M) *(__half2*)(C16 + (size_t)r1 * 256 + col) =
                __floats2half2_rn(acc[mt][nt][2], acc[mt][nt][3]);
            if (doAl) {
                float as0 = a_src[col], as1 = a_src[col + 1];
                float ad0 = a_dst[col], ad1 = a_dst[col + 1];
                ds0 += acc[mt][nt][0] * as0 + acc[mt][nt][1] * as1;
                dd0 += acc[mt][nt][0] * ad0 + acc[mt][nt][1] * ad1;
                ds1 += acc[mt][nt][2] * as0 + acc[mt][nt][3] * as1;
                dd1 += acc[mt][nt][2] * ad0 + acc[mt][nt][3] * ad1;
            }
        }
        if (doAl) {
#pragma unroll
            for (int o = 1; o < 4; o <<= 1) {
                ds0 += __shfl_xor_sync(0xffffffffu, ds0, o);
                dd0 += __shfl_xor_sync(0xffffffffu, dd0, o);
                ds1 += __shfl_xor_sync(0xffffffffu, ds1, o);
                dd1 += __shfl_xor_sync(0xffffffffu, dd1, o);
            }
            if ((lane & 3) == 0) {
                if (r0 < M) { atomicAdd(&g_als[r0], ds0); atomicAdd(&g_ald[r0], dd0); }
                if (r1 < M) { atomicAdd(&g_als[r1], ds1); atomicAdd(&g_ald[r1], dd1); }
            }
        }
    }
}

// ---------------- SIMT GEMM (final 256x40 layer) ----------------
__global__ void gemm_kernel(const float* __restrict__ A, const float* __restrict__ B,
                            float* __restrict__ C, int M, int Nn) {
    const int K = 256;
    __shared__ float As[16][128];
    __shared__ float Bs[16][64];
    int tid = threadIdx.x;
    int bm = blockIdx.y * 128;
    int bn = blockIdx.x * 64;
    int tx = tid & 15;
    int ty = tid >> 4;
    float acc[8][4];
#pragma unroll
    for (int i = 0; i < 8; i++)
#pragma unroll
        for (int j = 0; j < 4; j++) acc[i][j] = 0.f;

    for (int k0 = 0; k0 < K; k0 += 16) {
#pragma unroll
        for (int l = 0; l < 2; l++) {
            int lin = tid + l * 256;
            int row = lin >> 2;
            int c4 = (lin & 3) * 4;
            float4 v = make_float4(0.f, 0.f, 0.f, 0.f);
            if (bm + row < M)
                v = *(const float4*)(A + (size_t)(bm + row) * K + k0 + c4);
            As[c4 + 0][row] = v.x;
            As[c4 + 1][row] = v.y;
            As[c4 + 2][row] = v.z;
            As[c4 + 3][row] = v.w;
        }
        {
            int row = tid >> 4;
            int c4 = (tid & 15) * 4;
#pragma unroll
            for (int j = 0; j < 4; j++) {
                int cc = bn + c4 + j;
                Bs[row][c4 + j] = (cc < Nn) ? B[(size_t)(k0 + row) * Nn + cc] : 0.f;
            }
        }
        __syncthreads();
#pragma unroll
        for (int k = 0; k < 16; k++) {
            float4 a0 = *(const float4*)&As[k][ty * 8];
            float4 a1 = *(const float4*)&As[k][ty * 8 + 4];
            float4 b0 = *(const float4*)&Bs[k][tx * 4];
            float a[8] = {a0.x, a0.y, a0.z, a0.w, a1.x, a1.y, a1.z, a1.w};
            float b[4] = {b0.x, b0.y, b0.z, b0.w};
#pragma unroll
            for (int i = 0; i < 8; i++)
#pragma unroll
                for (int j = 0; j < 4; j++) acc[i][j] += a[i] * b[j];
        }
        __syncthreads();
    }
#pragma unroll
    for (int i = 0; i < 8; i++) {
        int row = bm + ty * 8 + i;
        if (row >= M) continue;
#pragma unroll
        for (int j = 0; j < 4; j++) {
            int col = bn + tx * 4 + j;
            if (col < Nn) C[(size_t)row * Nn + col] = acc[i][j];
        }
    }
}

// ---- fp16 row gather helpers ----
__device__ __forceinline__ void h16_accum(const uint2* __restrict__ hp, int idx, float w,
                                          float4& a0, float4& a1) {
    uint2 u0 = hp[idx];
    uint2 u1 = hp[idx + 32];
    float2 f0 = __half22float2(*(__half2*)&u0.x);
    float2 f1 = __half22float2(*(__half2*)&u0.y);
    float2 f2 = __half22float2(*(__half2*)&u1.x);
    float2 f3 = __half22float2(*(__half2*)&u1.y);
    a0.x += w * f0.x; a0.y += w * f0.y; a0.z += w * f1.x; a0.w += w * f1.y;
    a1.x += w * f2.x; a1.y += w * f2.y; a1.z += w * f3.x; a1.w += w * f3.y;
}

// ---------------- GCN aggregate (warp per dst node, fp16 gather, unroll-2) ---------------
__global__ void gcn_agg_kernel(const uint2* __restrict__ h, const float* __restrict__ bias,
                               float* __restrict__ out, int do_relu) {
    int t = blockIdx.x * blockDim.x + threadIdx.x;
    int node = t >> 5;
    int lane = t & 31;
    if (node >= NN) return;
    int beg = g_rowptr[node], end = g_rowptr[node + 1];
    float di = g_dinv[node];
    float4 a0 = make_float4(0.f, 0.f, 0.f, 0.f);
    float4 a1 = make_float4(0.f, 0.f, 0.f, 0.f);
    h16_accum(h, node * 64 + lane, di * di, a0, a1);
    int e = beg;
    for (; e + 2 <= end; e += 2) {
        int s0 = g_col[e], s1 = g_col[e + 1];
        float w0 = g_dinv[s0] * di, w1 = g_dinv[s1] * di;
        h16_accum(h, s0 * 64 + lane, w0, a0, a1);
        h16_accum(h, s1 * 64 + lane, w1, a0, a1);
    }
    if (e < end) {
        int s = g_col[e];
        h16_accum(h, s * 64 + lane, g_dinv[s] * di, a0, a1);
    }
    float4 b0 = ((const float4*)bias)[lane];
    float4 b1 = ((const float4*)bias)[lane + 32];
    a0.x += b0.x; a0.y += b0.y; a0.z += b0.z; a0.w += b0.w;
    a1.x += b1.x; a1.y += b1.y; a1.z += b1.z; a1.w += b1.w;
    if (do_relu) {
        a0.x = fmaxf(a0.x, 0.f); a0.y = fmaxf(a0.y, 0.f);
        a0.z = fmaxf(a0.z, 0.f); a0.w = fmaxf(a0.w, 0.f);
        a1.x = fmaxf(a1.x, 0.f); a1.y = fmaxf(a1.y, 0.f);
        a1.z = fmaxf(a1.z, 0.f); a1.w = fmaxf(a1.w, 0.f);
    }
    ((float4*)out)[node * 64 + lane] = a0;
    ((float4*)out)[node * 64 + lane + 32] = a1;
}

// ---------------- GAT aggregate with segment softmax (fp16 gather, unroll-2) -------------
__global__ void gat_agg_kernel(const uint2* __restrict__ h, const float* __restrict__ bias,
                               float* __restrict__ out) {
    int t = blockIdx.x * blockDim.x + threadIdx.x;
    int node = t >> 5;
    int lane = t & 31;
    if (node >= NN) return;
    int beg = g_rowptr[node], end = g_rowptr[node + 1];
    float aldi = g_ald[node];
    float e_self = lrelu(g_als[node] + aldi);
    float m = e_self;
    for (int e = beg + lane; e < end; e += 32)
        m = fmaxf(m, lrelu(g_als[g_col[e]] + aldi));
    for (int o = 16; o; o >>= 1) m = fmaxf(m, __shfl_xor_sync(0xffffffffu, m, o));
    float z = __expf(e_self - m);
    float4 a0 = make_float4(0.f, 0.f, 0.f, 0.f);
    float4 a1 = make_float4(0.f, 0.f, 0.f, 0.f);
    h16_accum(h, node * 64 + lane, z, a0, a1);
    int e = beg;
    for (; e + 2 <= end; e += 2) {
        int s0 = g_col[e], s1 = g_col[e + 1];
        float w0 = __expf(lrelu(g_als[s0] + aldi) - m);
        float w1 = __expf(lrelu(g_als[s1] + aldi) - m);
        z += w0 + w1;
        h16_accum(h, s0 * 64 + lane, w0, a0, a1);
        h16_accum(h, s1 * 64 + lane, w1, a0, a1);
    }
    if (e < end) {
        int s = g_col[e];
        float w = __expf(lrelu(g_als[s] + aldi) - m);
        z += w;
        h16_accum(h, s * 64 + lane, w, a0, a1);
    }
    float inv = 1.0f / z;
    float4 b0 = ((const float4*)bias)[lane];
    float4 b1 = ((const float4*)bias)[lane + 32];
    a0.x = fmaxf(a0.x * inv + b0.x, 0.f); a0.y = fmaxf(a0.y * inv + b0.y, 0.f);
    a0.z = fmaxf(a0.z * inv + b0.z, 0.f); a0.w = fmaxf(a0.w * inv + b0.w, 0.f);
    a1.x = fmaxf(a1.x * inv + b1.x, 0.f); a1.y = fmaxf(a1.y * inv + b1.y, 0.f);
    a1.z = fmaxf(a1.z * inv + b1.z, 0.f); a1.w = fmaxf(a1.w * inv + b1.w, 0.f);
    ((float4*)out)[node * 64 + lane] = a0;
    ((float4*)out)[node * 64 + lane + 32] = a1;
}

// ---------------- final GCN (L=40) + log_softmax (unroll-2) ----------------
__global__ void gcn2_kernel(const float* __restrict__ h2, const float* __restrict__ b2,
                            float* __restrict__ out) {
    int t = blockIdx.x * blockDim.x + threadIdx.x;
    int node = t >> 5;
    int lane = t & 31;
    if (node >= NN) return;
    int beg = g_rowptr[node], end = g_rowptr[node + 1];
    float di = g_dinv[node];
    float w = di * di;
    float a0 = w * h2[(size_t)node * LL + lane];
    float a1 = (lane < 8) ? w * h2[(size_t)node * LL + lane + 32] : 0.f;
    int e = beg;
    for (; e + 2 <= end; e += 2) {
        int s0 = g_col[e], s1 = g_col[e + 1];
        float w0 = g_dinv[s0] * di, w1 = g_dinv[s1] * di;
        float x0 = h2[(size_t)s0 * LL + lane];
        float x1 = h2[(size_t)s1 * LL + lane];
        a0 += w0 * x0 + w1 * x1;
        if (lane < 8) {
            a1 += w0 * h2[(size_t)s0 * LL + lane + 32] + w1 * h2[(size_t)s1 * LL + lane + 32];
        }
    }
    if (e < end) {
        int s = g_col[e];
        float we = g_dinv[s] * di;
        a0 += we * h2[(size_t)s * LL + lane];
        if (lane < 8) a1 += we * h2[(size_t)s * LL + lane + 32];
    }
    float v0 = a0 + b2[lane];
    float v1 = (lane < 8) ? a1 + b2[lane + 32] : -INFINITY;
    float m = fmaxf(v0, v1);
    for (int o = 16; o; o >>= 1) m = fmaxf(m, __shfl_xor_sync(0xffffffffu, m, o));
    float z = expf(v0 - m) + ((lane < 8) ? expf(v1 - m) : 0.f);
    for (int o = 16; o; o >>= 1) z += __shfl_xor_sync(0xffffffffu, z, o);
    float ls = logf(z);
    out[(size_t)node * LL + lane] = v0 - m - ls;
    if (lane < 8) out[(size_t)node * LL + lane + 32] = v1 - m - ls;
}

// ---------------- launch ----------------
extern "C" void kernel_launch(void* const* d_in, const int* in_sizes, int n_in,
                              void* d_out, int out_size) {
    const float* x   = (const float*)d_in[0];
    const void*  ei  = d_in[1];
    const float* W1  = (const float*)d_in[2];
    const float* b1  = (const float*)d_in[3];
    const float* Wg  = (const float*)d_in[4];
    const float* a_s = (const float*)d_in[5];
    const float* a_d = (const float*)d_in[6];
    const float* bg  = (const float*)d_in[7];
    const float* W2  = (const float*)d_in[8];
    const float* b2  = (const float*)d_in[9];
    float* out = (float*)d_out;

    float *pA, *pH2;
    uint2* pH16;
    __nv_bfloat16 *pWhi, *pWlo;
    cudaGetSymbolAddress((void**)&pA, g_bufA);
    cudaGetSymbolAddress((void**)&pH16, g_h16);
    cudaGetSymbolAddress((void**)&pH2, g_h2);
    cudaGetSymbolAddress((void**)&pWhi, g_Whi4);
    cudaGetSymbolAddress((void**)&pWlo, g_Wlo4);

    cudaFuncSetAttribute(mma_gemm_kernel, cudaFuncAttributeMaxDynamicSharedMemorySize, MMA_SMEM);

    const int tpb = 256;
    zero_kernel<<<(NN + tpb - 1) / tpb, tpb>>>();
    detect_kernel<<<1, 32>>>((const unsigned int*)ei);
    convert_kernel<<<(EE + tpb - 1) / tpb, tpb>>>(ei);
    stats_kernel<<<(NN / 32) + 1, 256>>>(x);
    finalize_kernel<<<1, 256>>>();
    dinv_kernel<<<(NN + tpb - 1) / tpb, tpb>>>();
    scan_kernel<<<1, 1024>>>();
    fill_kernel<<<(EE + tpb - 1) / tpb, tpb>>>();

    dim3 gMMA(2, (NN + 127) / 128);
    dim3 g40((40 + 63) / 64, (NN + 127) / 128);
    int warpGrid = (NN * 32 + tpb - 1) / tpb;
    int zg = (NN + tpb - 1) / tpb;

    // GCN layer 1 (+ReLU): standardize fused into A-staging, reads x directly
    splitW_kernel<<<(256 * 256) / tpb, tpb>>>(W1);
    mma_gemm_kernel<<<gMMA, 256, MMA_SMEM>>>((const float*)x, pWhi, pWlo,
                                             (__half*)pH16, NN, 1, 0, a_s, a_d);
    gcn_agg_kernel<<<warpGrid, tpb>>>(pH16, b1, pA, 1);

    // GAT layer 1 (+ReLU): al fused into GEMM epilogue
    splitW_kernel<<<(256 * 256) / tpb, tpb>>>(Wg);
    zero_al_kernel<<<zg, tpb>>>();
    mma_gemm_kernel<<<gMMA, 256, MMA_SMEM>>>(pA, pWhi, pWlo,
                                             (__half*)pH16, NN, 0, 1, a_s, a_d);
    gat_agg_kernel<<<warpGrid, tpb>>>(pH16, bg, pA);

    // GAT layer 2 (+ReLU) — Wg planes already split
    zero_al_kernel<<<zg, tpb>>>();
    mma_gemm_kernel<<<gMMA, 256, MMA_SMEM>>>(pA, pWhi, pWlo,
                                             (__half*)pH16, NN, 0, 1, a_s, a_d);
    gat_agg_kernel<<<warpGrid, tpb>>>(pH16, bg, pA);

    // GCN layer 2 + log_softmax
    gemm_kernel<<<g40, 256>>>(pA, W2, pH2, NN, 40);
    gcn2_kernel<<<warpGrid, tpb>>>(pH2, b2, out);
}

// round 6
// speedup vs baseline: 1.7116x; 1.0825x over previous
#include <cuda_runtime.h>
#include <cuda_bf16.h>
#include <cuda_fp16.h>
#include <math.h>
#include <stdint.h>

#define NN 50000
#define EE 800000
#define DD 256
#define HH 256
#define LL 40

// ---------------- scratch (device globals; no allocation allowed) ----------------
__device__ uint2  g_h16[(size_t)NN * 64];   // 25.6 MB (GEMM outputs, half2-packed)
__device__ uint2  g_x16[(size_t)NN * 64];   // 25.6 MB (agg outputs, half2-packed)
__device__ __half g_h2[(size_t)NN * LL];    // 4 MB (final-layer logits input)
__device__ int   g_src[EE];
__device__ int   g_dst[EE];
__device__ int   g_col[EE];
__device__ int   g_counts[NN];
__device__ int   g_rowptr[NN + 1];
__device__ int   g_cursor[NN];
__device__ float g_dinv[NN];
__device__ float g_als[NN];
__device__ float g_ald[NN];
__device__ float g_colsum[DD];
__device__ float g_colsumsq[DD];
__device__ float g_mean[DD];
__device__ float g_istd[DD];
__device__ int   g_flag;  // 1 = edge_index is int64, 0 = int32
__device__ uint4 g_Whi4[(256 * 256) / 8];
__device__ uint4 g_Wlo4[(256 * 256) / 8];

__device__ __forceinline__ float lrelu(float v) { return v > 0.f ? v : 0.2f * v; }
__device__ __forceinline__ uint32_t swz128(uint32_t o) { return o ^ ((o >> 3) & 0x70); }

__device__ __forceinline__ uint32_t smem_u32(const void* p) {
    uint32_t a;
    asm("{ .reg .u64 t; cvta.to.shared.u64 t, %1; cvt.u32.u64 %0, t; }" : "=r"(a) : "l"(p));
    return a;
}

#define LDSM_X4(r0, r1, r2, r3, addr)                                               \
    asm volatile("ldmatrix.sync.aligned.m8n8.x4.shared.b16 {%0,%1,%2,%3}, [%4];"    \
                 : "=r"(r0), "=r"(r1), "=r"(r2), "=r"(r3) : "r"(addr))

#define MMA16816(d, a, b)                                                           \
    asm volatile("mma.sync.aligned.m16n8k16.row.col.f32.bf16.bf16.f32 "             \
                 "{%0,%1,%2,%3}, {%4,%5,%6,%7}, {%8,%9}, {%0,%1,%2,%3};"            \
                 : "+f"((d)[0]), "+f"((d)[1]), "+f"((d)[2]), "+f"((d)[3])           \
                 : "r"((a)[0]), "r"((a)[1]), "r"((a)[2]), "r"((a)[3]),              \
                   "r"((b)[0]), "r"((b)[1]))

// ---------------- setup kernels ----------------
__global__ void zero_kernel() {
    int i = blockIdx.x * blockDim.x + threadIdx.x;
    if (i < NN) g_counts[i] = 0;
}

__global__ void zero_al_kernel() {
    int i = blockIdx.x * blockDim.x + threadIdx.x;
    if (i < NN) { g_als[i] = 0.f; g_ald[i] = 0.f; }
}

__global__ void detect_kernel(const unsigned int* __restrict__ p) {
    if (blockIdx.x == 0 && threadIdx.x == 0) {
        int is64 = 1;
        for (int i = 0; i < 64; i++)
            if (p[2 * i + 1] != 0u) { is64 = 0; break; }
        g_flag = is64;
    }
}

__global__ void convert_kernel(const void* __restrict__ ei) {
    int e = blockIdx.x * blockDim.x + threadIdx.x;
    if (e >= EE) return;
    int s, d;
    if (g_flag) {
        const long long* p = (const long long*)ei;
        s = (int)p[e]; d = (int)p[EE + e];
    } else {
        const int* p = (const int*)ei;
        s = p[e]; d = p[EE + e];
    }
    g_src[e] = s;
    g_dst[e] = d;
    atomicAdd(&g_counts[d], 1);
}

// 296 blocks; MLP-4 row batching; smem reduce -> 512 atomics/block (296/address)
__global__ void stats_kernel(const float* __restrict__ x) {
    __shared__ float4 ss[256], ss2[256];
    int cg = threadIdx.x & 63;
    int rl = threadIdx.x >> 6;   // 0..3
    int g4 = gridDim.x * 4;      // row-lane stride
    float4 s = make_float4(0.f, 0.f, 0.f, 0.f);
    float4 s2 = make_float4(0.f, 0.f, 0.f, 0.f);
    for (int r = blockIdx.x * 4 + rl; r < NN; r += g4 * 4) {
        float4 v[4];
#pragma unroll
        for (int j = 0; j < 4; j++) {
            int rr = r + j * g4;
            v[j] = (rr < NN) ? ((const float4*)x)[(size_t)rr * 64 + cg]
                             : make_float4(0.f, 0.f, 0.f, 0.f);
        }
#pragma unroll
        for (int j = 0; j < 4; j++) {
            s.x += v[j].x; s.y += v[j].y; s.z += v[j].z; s.w += v[j].w;
            s2.x += v[j].x * v[j].x; s2.y += v[j].y * v[j].y;
            s2.z += v[j].z * v[j].z; s2.w += v[j].w * v[j].w;
        }
    }
    ss[threadIdx.x] = s; ss2[threadIdx.x] = s2;
    __syncthreads();
    if (threadIdx.x < 64) {
#pragma unroll
        for (int k = 1; k < 4; k++) {
            float4 t = ss[threadIdx.x + 64 * k], t2 = ss2[threadIdx.x + 64 * k];
            s.x += t.x; s.y += t.y; s.z += t.z; s.w += t.w;
            s2.x += t2.x; s2.y += t2.y; s2.z += t2.z; s2.w += t2.w;
        }
        int c = threadIdx.x * 4;
        atomicAdd(&g_colsum[c + 0], s.x); atomicAdd(&g_colsum[c + 1], s.y);
        atomicAdd(&g_colsum[c + 2], s.z); atomicAdd(&g_colsum[c + 3], s.w);
        atomicAdd(&g_colsumsq[c + 0], s2.x); atomicAdd(&g_colsumsq[c + 1], s2.y);
        atomicAdd(&g_colsumsq[c + 2], s2.z); atomicAdd(&g_colsumsq[c + 3], s2.w);
    }
}

__global__ void finalize_kernel() {
    int c = threadIdx.x;
    float mean = g_colsum[c] / (float)NN;
    float var = (g_colsumsq[c] - (float)NN * mean * mean) / (float)(NN - 1);
    g_mean[c] = mean;
    g_istd[c] = rsqrtf(var);
}

__global__ void dinv_kernel() {
    int i = blockIdx.x * blockDim.x + threadIdx.x;
    if (i < NN) g_dinv[i] = rsqrtf((float)(g_counts[i] + 1));
}

__global__ void scan_kernel() {
    __shared__ int warpsum[32];
    __shared__ int s_off;
    int tid = threadIdx.x;
    int lane = tid & 31, wid = tid >> 5;
    if (tid == 0) s_off = 0;
    __syncthreads();
    for (int base = 0; base < NN; base += 1024) {
        int i = base + tid;
        int v = (i < NN) ? g_counts[i] : 0;
        int xs = v;
#pragma unroll
        for (int d = 1; d < 32; d <<= 1) {
            int t = __shfl_up_sync(0xffffffffu, xs, d);
            if (lane >= d) xs += t;
        }
        if (lane == 31) warpsum[wid] = xs;
        __syncthreads();
        if (wid == 0) {
            int w = warpsum[lane];
#pragma unroll
            for (int d = 1; d < 32; d <<= 1) {
                int t = __shfl_up_sync(0xffffffffu, w, d);
                if (lane >= d) w += t;
            }
            warpsum[lane] = w;
        }
        __syncthreads();
        int excl = xs - v + (wid ? warpsum[wid - 1] : 0);
        int off = s_off;
        if (i < NN) { g_rowptr[i] = off + excl; g_cursor[i] = off + excl; }
        __syncthreads();
        if (tid == 1023) s_off = off + excl + v;
        __syncthreads();
    }
    if (tid == 0) g_rowptr[NN] = s_off;
}

__global__ void fill_kernel() {
    int e = blockIdx.x * blockDim.x + threadIdx.x;
    if (e >= EE) return;
    int d = g_dst[e];
    int p = atomicAdd(&g_cursor[d], 1);
    g_col[p] = g_src[e];
}

// ---------------- weight transpose + hi/lo split (also zeroes stats accumulators) --------
__global__ void splitW_kernel(const float* __restrict__ W) {
    int idx = blockIdx.x * blockDim.x + threadIdx.x;
    if (idx < 256) { g_colsum[idx] = 0.f; g_colsumsq[idx] = 0.f; }
    if (idx >= 256 * 256) return;
    int k = idx >> 8;
    int n = idx & 255;
    float v = W[idx];
    __nv_bfloat16 h = __float2bfloat16(v);
    float r = v - __bfloat162float(h);
    __nv_bfloat16* whi = (__nv_bfloat16*)g_Whi4;
    __nv_bfloat16* wlo = (__nv_bfloat16*)g_Wlo4;
    whi[n * 256 + k] = h;
    wlo[n * 256 + k] = __float2bfloat16(r);
}

// ---------------- mma.sync GEMM: h16 = A @ Wsplit^T (bf16 hi/lo 3-term), fused al --------
#define SO_AHI 0
#define SO_ALO 16384
#define SO_BHI 32768
#define SO_BLO 49152
#define MMA_SMEM 65536

__global__ void __launch_bounds__(256) mma_gemm_kernel(
    const float* __restrict__ A32, const __half* __restrict__ A16,
    const __nv_bfloat16* __restrict__ Bhi_g, const __nv_bfloat16* __restrict__ Blo_g,
    __half* __restrict__ C16, int M, int doStd, int doAl,
    const float* __restrict__ a_src, const float* __restrict__ a_dst) {
    extern __shared__ char smem[];
    uint32_t sb = smem_u32(smem);
    int tid = threadIdx.x;
    int wid = tid >> 5, lane = tid & 31;
    int bm = blockIdx.y * 128;
    int bn = blockIdx.x * 128;
    int wm = (wid >> 1) * 32;
    int wn = (wid & 1) * 64;

    float acc[2][8][4];
#pragma unroll
    for (int mt = 0; mt < 2; mt++)
#pragma unroll
        for (int nt = 0; nt < 8; nt++)
#pragma unroll
            for (int r = 0; r < 4; r++) acc[mt][nt][r] = 0.f;

    uint32_t b_row[4], b_cb;
#pragma unroll
    for (int ntp = 0; ntp < 4; ntp++)
        b_row[ntp] = (uint32_t)(wn + ntp * 16 + (lane & 7) + ((lane >> 4) << 3));
    b_cb = (uint32_t)(((lane >> 3) & 1) * 16);

    for (int ch = 0; ch < 4; ch++) {
        int k0 = ch * 64;
        __syncthreads();
#pragma unroll
        for (int i = 0; i < 4; i++) {
            int lin = tid + i * 256;
            int row = lin >> 3;
            int u8 = lin & 7;
            uint32_t so = swz128((uint32_t)(row * 128 + u8 * 16));
            const uint4* sh = (const uint4*)(Bhi_g + (size_t)(bn + row) * 256 + k0);
            const uint4* sl = (const uint4*)(Blo_g + (size_t)(bn + row) * 256 + k0);
            *(uint4*)(smem + SO_BHI + so) = sh[u8];
            *(uint4*)(smem + SO_BLO + so) = sl[u8];
        }
#pragma unroll
        for (int i = 0; i < 8; i++) {
            int lin = tid + i * 256;
            int row = lin >> 4;
            int c4 = (lin & 15) * 4;
            float4 v = make_float4(0.f, 0.f, 0.f, 0.f);
            int gr = bm + row;
            if (A16) {
                if (gr < M) {
                    uint2 u = *(const uint2*)(A16 + (size_t)gr * 256 + k0 + c4);
                    float2 f01 = __half22float2(*(__half2*)&u.x);
                    float2 f23 = __half22float2(*(__half2*)&u.y);
                    v = make_float4(f01.x, f01.y, f23.x, f23.y);
                }
            } else {
                if (gr < M) v = *(const float4*)(A32 + (size_t)gr * 256 + k0 + c4);
                if (doStd) {
                    int cc = k0 + c4;
                    v.x = (v.x - g_mean[cc + 0]) * g_istd[cc + 0];
                    v.y = (v.y - g_mean[cc + 1]) * g_istd[cc + 1];
                    v.z = (v.z - g_mean[cc + 2]) * g_istd[cc + 2];
                    v.w = (v.w - g_mean[cc + 3]) * g_istd[cc + 3];
                }
            }
            __nv_bfloat16 hx = __float2bfloat16(v.x), hy = __float2bfloat16(v.y);
            __nv_bfloat16 hz = __float2bfloat16(v.z), hw = __float2bfloat16(v.w);
            __nv_bfloat16 lx = __float2bfloat16(v.x - __bfloat162float(hx));
            __nv_bfloat16 ly = __float2bfloat16(v.y - __bfloat162float(hy));
            __nv_bfloat16 lz = __float2bfloat16(v.z - __bfloat162float(hz));
            __nv_bfloat16 lw = __float2bfloat16(v.w - __bfloat162float(hw));
            uint32_t so = swz128((uint32_t)(row * 128 + c4 * 2));
            __nv_bfloat162 p0, p1;
            p0.x = hx; p0.y = hy; p1.x = hz; p1.y = hw;
            uint2 uh = make_uint2(*(unsigned*)&p0, *(unsigned*)&p1);
            p0.x = lx; p0.y = ly; p1.x = lz; p1.y = lw;
            uint2 ul = make_uint2(*(unsigned*)&p0, *(unsigned*)&p1);
            *(uint2*)(smem + SO_AHI + so) = uh;
            *(uint2*)(smem + SO_ALO + so) = ul;
        }
        __syncthreads();

#pragma unroll
        for (int ks = 0; ks < 4; ks++) {
            uint32_t kb = (uint32_t)(ks * 32);
            uint32_t ah[2][4], al[2][4];
#pragma unroll
            for (int mt = 0; mt < 2; mt++) {
                uint32_t row = (uint32_t)(wm + mt * 16 + (lane & 15));
                uint32_t cb = (uint32_t)((lane >> 4) * 16) + kb;
                uint32_t ad = sb + swz128(row * 128 + cb);
                LDSM_X4(ah[mt][0], ah[mt][1], ah[mt][2], ah[mt][3], ad + SO_AHI);
                LDSM_X4(al[mt][0], al[mt][1], al[mt][2], al[mt][3], ad + SO_ALO);
            }
            uint32_t bh[8][2], bl[8][2];
#pragma unroll
            for (int ntp = 0; ntp < 4; ntp++) {
                uint32_t bd = sb + swz128(b_row[ntp] * 128 + b_cb + kb);
                LDSM_X4(bh[2 * ntp][0], bh[2 * ntp][1], bh[2 * ntp + 1][0],
                        bh[2 * ntp + 1][1], bd + SO_BHI);
                LDSM_X4(bl[2 * ntp][0], bl[2 * ntp][1], bl[2 * ntp + 1][0],
                        bl[2 * ntp + 1][1], bd + SO_BLO);
            }
#pragma unroll
            for (int mt = 0; mt < 2; mt++)
#pragma unroll
                for (int nt = 0; nt < 8; nt++) {
                    MMA16816(acc[mt][nt], ah[mt], bh[nt]);
                    MMA16816(acc[mt][nt], ah[mt], bl[nt]);
                    MMA16816(acc[mt][nt], al[mt], bh[nt]);
                }
        }
    }

    // ---- epilogue: fp16 store + optional fused attention logits ----
#pragma unroll
    for (int mt = 0; mt < 2; mt++) {
        int r0 = bm + wm + mt * 16 + (lane >> 2);
        int r1 = r0 + 8;
        float ds0 = 0.f, dd0 = 0.f, ds1 = 0.f, dd1 = 0.f;
#pragma unroll
        for (int nt = 0; nt < 8; nt++) {
            int col = bn + wn + nt * 8 + (lane & 3) * 2;
            if (r0 < M) *(__half2*)(C16 + (size_t)r0 * 256 + col) =
                __floats2half2_rn(acc[mt][nt][0], acc[mt][nt][1]);
            if (r1 < M) *(__half2*)(C16 + (size_t)r1 * 256 + col) =
                __floats2half2_rn(acc[mt][nt][2], acc[mt][nt][3]);
            if (doAl) {
                float as0 = a_src[col], as1 = a_src[col + 1];
                float ad0 = a_dst[col], ad1 = a_dst[col + 1];
                ds0 += acc[mt][nt][0] * as0 + acc[mt][nt][1] * as1;
                dd0 += acc[mt][nt][0] * ad0 + acc[mt][nt][1] * ad1;
                ds1 += acc[mt][nt][2] * as0 + acc[mt][nt][3] * as1;
                dd1 += acc[mt][nt][2] * ad0 + acc[mt][nt][3] * ad1;
            }
        }
        if (doAl) {
#pragma unroll
            for (int o = 1; o < 4; o <<= 1) {
                ds0 += __shfl_xor_sync(0xffffffffu, ds0, o);
                dd0 += __shfl_xor_sync(0xffffffffu, dd0, o);
                ds1 += __shfl_xor_sync(0xffffffffu, ds1, o);
                dd1 += __shfl_xor_sync(0xffffffffu, dd1, o);
            }
            if ((lane & 3) == 0) {
                if (r0 < M) { atomicAdd(&g_als[r0], ds0); atomicAdd(&g_ald[r0], dd0); }
                if (r1 < M) { atomicAdd(&g_als[r1], ds1); atomicAdd(&g_ald[r1], dd1); }
            }
        }
    }
}

// ---------------- SIMT GEMM (final 256x40 layer; fp16 A in, fp16 C out) -----------------
__global__ void gemm_kernel(const __half* __restrict__ A16, const float* __restrict__ B,
                            __half* __restrict__ C, int M, int Nn) {
    const int K = 256;
    __shared__ float As[16][128];
    __shared__ float Bs[16][64];
    int tid = threadIdx.x;
    int bm = blockIdx.y * 128;
    int bn = blockIdx.x * 64;
    int tx = tid & 15;
    int ty = tid >> 4;
    float acc[8][4];
#pragma unroll
    for (int i = 0; i < 8; i++)
#pragma unroll
        for (int j = 0; j < 4; j++) acc[i][j] = 0.f;

    for (int k0 = 0; k0 < K; k0 += 16) {
#pragma unroll
        for (int l = 0; l < 2; l++) {
            int lin = tid + l * 256;
            int row = lin >> 2;
            int c4 = (lin & 3) * 4;
            float4 v = make_float4(0.f, 0.f, 0.f, 0.f);
            if (bm + row < M) {
                uint2 u = *(const uint2*)(A16 + (size_t)(bm + row) * K + k0 + c4);
                float2 f01 = __half22float2(*(__half2*)&u.x);
                float2 f23 = __half22float2(*(__half2*)&u.y);
                v = make_float4(f01.x, f01.y, f23.x, f23.y);
            }
            As[c4 + 0][row] = v.x;
            As[c4 + 1][row] = v.y;
            As[c4 + 2][row] = v.z;
            As[c4 + 3][row] = v.w;
        }
        {
            int row = tid >> 4;
            int c4 = (tid & 15) * 4;
#pragma unroll
            for (int j = 0; j < 4; j++) {
                int cc = bn + c4 + j;
                Bs[row][c4 + j] = (cc < Nn) ? B[(size_t)(k0 + row) * Nn + cc] : 0.f;
            }
        }
        __syncthreads();
#pragma unroll
        for (int k = 0; k < 16; k++) {
            float4 a0 = *(const float4*)&As[k][ty * 8];
            float4 a1 = *(const float4*)&As[k][ty * 8 + 4];
            float4 b0 = *(const float4*)&Bs[k][tx * 4];
            float a[8] = {a0.x, a0.y, a0.z, a0.w, a1.x, a1.y, a1.z, a1.w};
            float b[4] = {b0.x, b0.y, b0.z, b0.w};
#pragma unroll
            for (int i = 0; i < 8; i++)
#pragma unroll
                for (int j = 0; j < 4; j++) acc[i][j] += a[i] * b[j];
        }
        __syncthreads();
    }
#pragma unroll
    for (int i = 0; i < 8; i++) {
        int row = bm + ty * 8 + i;
        if (row >= M) continue;
#pragma unroll
        for (int j = 0; j < 4; j++) {
            int col = bn + tx * 4 + j;
            if (col < Nn) C[(size_t)row * Nn + col] = __float2half(acc[i][j]);
        }
    }
}

// ---- fp16 row gather/store helpers ----
__device__ __forceinline__ void h16_accum(const uint2* __restrict__ hp, int idx, float w,
                                          float4& a0, float4& a1) {
    uint2 u0 = hp[idx];
    uint2 u1 = hp[idx + 32];
    float2 f0 = __half22float2(*(__half2*)&u0.x);
    float2 f1 = __half22float2(*(__half2*)&u0.y);
    float2 f2 = __half22float2(*(__half2*)&u1.x);
    float2 f3 = __half22float2(*(__half2*)&u1.y);
    a0.x += w * f0.x; a0.y += w * f0.y; a0.z += w * f1.x; a0.w += w * f1.y;
    a1.x += w * f2.x; a1.y += w * f2.y; a1.z += w * f3.x; a1.w += w * f3.y;
}

__device__ __forceinline__ void h16_store(uint2* __restrict__ o, int node, int lane,
                                          const float4& a0, const float4& a1) {
    __half2 h01 = __floats2half2_rn(a0.x, a0.y);
    __half2 h23 = __floats2half2_rn(a0.z, a0.w);
    uint2 u0 = make_uint2(*(uint32_t*)&h01, *(uint32_t*)&h23);
    __half2 h45 = __floats2half2_rn(a1.x, a1.y);
    __half2 h67 = __floats2half2_rn(a1.z, a1.w);
    uint2 u1 = make_uint2(*(uint32_t*)&h45, *(uint32_t*)&h67);
    o[(size_t)node * 64 + lane] = u0;
    o[(size_t)node * 64 + lane + 32] = u1;
}

// ---------------- GCN aggregate (warp per dst node, fp16 in/out, unroll-4) ---------------
__global__ void gcn_agg_kernel(const uint2* __restrict__ h, const float* __restrict__ bias,
                               uint2* __restrict__ out) {
    int t = blockIdx.x * blockDim.x + threadIdx.x;
    int node = t >> 5;
    int lane = t & 31;
    if (node >= NN) return;
    int beg = g_rowptr[node], end = g_rowptr[node + 1];
    float di = g_dinv[node];
    float4 a0 = make_float4(0.f, 0.f, 0.f, 0.f);
    float4 a1 = make_float4(0.f, 0.f, 0.f, 0.f);
    h16_accum(h, node * 64 + lane, di * di, a0, a1);
    int e = beg;
    for (; e + 4 <= end; e += 4) {
        int s0 = g_col[e], s1 = g_col[e + 1], s2 = g_col[e + 2], s3 = g_col[e + 3];
        float w0 = g_dinv[s0] * di, w1 = g_dinv[s1] * di;
        float w2 = g_dinv[s2] * di, w3 = g_dinv[s3] * di;
        h16_accum(h, s0 * 64 + lane, w0, a0, a1);
        h16_accum(h, s1 * 64 + lane, w1, a0, a1);
        h16_accum(h, s2 * 64 + lane, w2, a0, a1);
        h16_accum(h, s3 * 64 + lane, w3, a0, a1);
    }
    for (; e < end; e++) {
        int s = g_col[e];
        h16_accum(h, s * 64 + lane, g_dinv[s] * di, a0, a1);
    }
    float4 b0 = ((const float4*)bias)[lane];
    float4 b1 = ((const float4*)bias)[lane + 32];
    a0.x = fmaxf(a0.x + b0.x, 0.f); a0.y = fmaxf(a0.y + b0.y, 0.f);
    a0.z = fmaxf(a0.z + b0.z, 0.f); a0.w = fmaxf(a0.w + b0.w, 0.f);
    a1.x = fmaxf(a1.x + b1.x, 0.f); a1.y = fmaxf(a1.y + b1.y, 0.f);
    a1.z = fmaxf(a1.z + b1.z, 0.f); a1.w = fmaxf(a1.w + b1.w, 0.f);
    h16_store(out, node, lane, a0, a1);
}

// ---------------- GAT aggregate with segment softmax (fp16 in/out, unroll-4) -------------
__global__ void gat_agg_kernel(const uint2* __restrict__ h, const float* __restrict__ bias,
                               uint2* __restrict__ out) {
    int t = blockIdx.x * blockDim.x + threadIdx.x;
    int node = t >> 5;
    int lane = t & 31;
    if (node >= NN) return;
    int beg = g_rowptr[node], end = g_rowptr[node + 1];
    float aldi = g_ald[node];
    float e_self = lrelu(g_als[node] + aldi);
    float m = e_self;
    for (int e = beg + lane; e < end; e += 32)
        m = fmaxf(m, lrelu(g_als[g_col[e]] + aldi));
    for (int o = 16; o; o >>= 1) m = fmaxf(m, __shfl_xor_sync(0xffffffffu, m, o));
    float z = __expf(e_self - m);
    float4 a0 = make_float4(0.f, 0.f, 0.f, 0.f);
    float4 a1 = make_float4(0.f, 0.f, 0.f, 0.f);
    h16_accum(h, node * 64 + lane, z, a0, a1);
    int e = beg;
    for (; e + 4 <= end; e += 4) {
        int s0 = g_col[e], s1 = g_col[e + 1], s2 = g_col[e + 2], s3 = g_col[e + 3];
        float w0 = __expf(lrelu(g_als[s0] + aldi) - m);
        float w1 = __expf(lrelu(g_als[s1] + aldi) - m);
        float w2 = __expf(lrelu(g_als[s2] + aldi) - m);
        float w3 = __expf(lrelu(g_als[s3] + aldi) - m);
        z += w0 + w1 + w2 + w3;
        h16_accum(h, s0 * 64 + lane, w0, a0, a1);
        h16_accum(h, s1 * 64 + lane, w1, a0, a1);
        h16_accum(h, s2 * 64 + lane, w2, a0, a1);
        h16_accum(h, s3 * 64 + lane, w3, a0, a1);
    }
    for (; e < end; e++) {
        int s = g_col[e];
        float w = __expf(lrelu(g_als[s] + aldi) - m);
        z += w;
        h16_accum(h, s * 64 + lane, w, a0, a1);
    }
    float inv = 1.0f / z;
    float4 b0 = ((const float4*)bias)[lane];
    float4 b1 = ((const float4*)bias)[lane + 32];
    a0.x = fmaxf(a0.x * inv + b0.x, 0.f); a0.y = fmaxf(a0.y * inv + b0.y, 0.f);
    a0.z = fmaxf(a0.z * inv + b0.z, 0.f); a0.w = fmaxf(a0.w * inv + b0.w, 0.f);
    a1.x = fmaxf(a1.x * inv + b1.x, 0.f); a1.y = fmaxf(a1.y * inv + b1.y, 0.f);
    a1.z = fmaxf(a1.z * inv + b1.z, 0.f); a1.w = fmaxf(a1.w * inv + b1.w, 0.f);
    h16_store(out, node, lane, a0, a1);
}

// ---------------- final GCN (L=40, fp16 h2) + log_softmax (unroll-2) ----------------
__global__ void gcn2_kernel(const __half* __restrict__ h2, const float* __restrict__ b2,
                            float* __restrict__ out) {
    int t = blockIdx.x * blockDim.x + threadIdx.x;
    int node = t >> 5;
    int lane = t & 31;
    if (node >= NN) return;
    int beg = g_rowptr[node], end = g_rowptr[node + 1];
    float di = g_dinv[node];
    float w = di * di;
    float a0 = w * __half2float(h2[(size_t)node * LL + lane]);
    float a1 = (lane < 8) ? w * __half2float(h2[(size_t)node * LL + lane + 32]) : 0.f;
    int e = beg;
    for (; e + 2 <= end; e += 2) {
        int s0 = g_col[e], s1 = g_col[e + 1];
        float w0 = g_dinv[s0] * di, w1 = g_dinv[s1] * di;
        float x0 = __half2float(h2[(size_t)s0 * LL + lane]);
        float x1 = __half2float(h2[(size_t)s1 * LL + lane]);
        a0 += w0 * x0 + w1 * x1;
        if (lane < 8) {
            a1 += w0 * __half2float(h2[(size_t)s0 * LL + lane + 32]) +
                  w1 * __half2float(h2[(size_t)s1 * LL + lane + 32]);
        }
    }
    if (e < end) {
        int s = g_col[e];
        float we = g_dinv[s] * di;
        a0 += we * __half2float(h2[(size_t)s * LL + lane]);
        if (lane < 8) a1 += we * __half2float(h2[(size_t)s * LL + lane + 32]);
    }
    float v0 = a0 + b2[lane];
    float v1 = (lane < 8) ? a1 + b2[lane + 32] : -INFINITY;
    float m = fmaxf(v0, v1);
    for (int o = 16; o; o >>= 1) m = fmaxf(m, __shfl_xor_sync(0xffffffffu, m, o));
    float z = expf(v0 - m) + ((lane < 8) ? expf(v1 - m) : 0.f);
    for (int o = 16; o; o >>= 1) z += __shfl_xor_sync(0xffffffffu, z, o);
    float ls = logf(z);
    out[(size_t)node * LL + lane] = v0 - m - ls;
    if (lane < 8) out[(size_t)node * LL + lane + 32] = v1 - m - ls;
}

// ---------------- launch ----------------
extern "C" void kernel_launch(void* const* d_in, const int* in_sizes, int n_in,
                              void* d_out, int out_size) {
    const float* x   = (const float*)d_in[0];
    const void*  ei  = d_in[1];
    const float* W1  = (const float*)d_in[2];
    const float* b1  = (const float*)d_in[3];
    const float* Wg  = (const float*)d_in[4];
    const float* a_s = (const float*)d_in[5];
    const float* a_d = (const float*)d_in[6];
    const float* bg  = (const float*)d_in[7];
    const float* W2  = (const float*)d_in[8];
    const float* b2  = (const float*)d_in[9];
    float* out = (float*)d_out;

    uint2 *pH16, *pX16;
    __half* pH2;
    __nv_bfloat16 *pWhi, *pWlo;
    cudaGetSymbolAddress((void**)&pH16, g_h16);
    cudaGetSymbolAddress((void**)&pX16, g_x16);
    cudaGetSymbolAddress((void**)&pH2, g_h2);
    cudaGetSymbolAddress((void**)&pWhi, g_Whi4);
    cudaGetSymbolAddress((void**)&pWlo, g_Wlo4);

    cudaFuncSetAttribute(mma_gemm_kernel, cudaFuncAttributeMaxDynamicSharedMemorySize, MMA_SMEM);

    const int tpb = 256;
    dim3 gMMA(2, (NN + 127) / 128);
    dim3 g40((40 + 63) / 64, (NN + 127) / 128);
    int warpGrid = (NN * 32 + tpb - 1) / tpb;
    int zg = (NN + tpb - 1) / tpb;

    // --- GEMM-1 path first (so mma_gemm sits in the ncu capture slot) ---
    splitW_kernel<<<(256 * 256) / tpb, tpb>>>(W1);   // also zeroes colsum/colsumsq
    stats_kernel<<<296, 256>>>(x);
    finalize_kernel<<<1, 256>>>();
    mma_gemm_kernel<<<gMMA, 256, MMA_SMEM>>>(x, (const __half*)0, pWhi, pWlo,
                                             (__half*)pH16, NN, 1, 0, a_s, a_d);

    // --- CSR build (independent of GEMM-1) ---
    zero_kernel<<<(NN + tpb - 1) / tpb, tpb>>>();
    detect_kernel<<<1, 32>>>((const unsigned int*)ei);
    convert_kernel<<<(EE + tpb - 1) / tpb, tpb>>>(ei);
    dinv_kernel<<<(NN + tpb - 1) / tpb, tpb>>>();
    scan_kernel<<<1, 1024>>>();
    fill_kernel<<<(EE + tpb - 1) / tpb, tpb>>>();

    // GCN layer 1 aggregate (+ReLU) -> x16 fp16
    gcn_agg_kernel<<<warpGrid, tpb>>>(pH16, b1, pX16);

    // GAT layer 1 (+ReLU)
    splitW_kernel<<<(256 * 256) / tpb, tpb>>>(Wg);
    zero_al_kernel<<<zg, tpb>>>();
    mma_gemm_kernel<<<gMMA, 256, MMA_SMEM>>>((const float*)0, (const __half*)pX16,
                                             pWhi, pWlo, (__half*)pH16, NN, 0, 1, a_s, a_d);
    gat_agg_kernel<<<warpGrid, tpb>>>(pH16, bg, pX16);

    // GAT layer 2 (+ReLU) — Wg planes already split
    zero_al_kernel<<<zg, tpb>>>();
    mma_gemm_kernel<<<gMMA, 256, MMA_SMEM>>>((const float*)0, (const __half*)pX16,
                                             pWhi, pWlo, (__half*)pH16, NN, 0, 1, a_s, a_d);
    gat_agg_kernel<<<warpGrid, tpb>>>(pH16, bg, pX16);

    // GCN layer 2 + log_softmax
    gemm_kernel<<<g40, 256>>>((const __half*)pX16, W2, pH2, NN, 40);
    gcn2_kernel<<<warpGrid, tpb>>>(pH2, b2, out);
}

// round 7
// speedup vs baseline: 2.0692x; 1.2089x over previous
#include <cuda_runtime.h>
#include <cuda_fp16.h>
#include <math.h>
#include <stdint.h>

#define NN 50000
#define EE 800000
#define DD 256
#define HH 256
#define LL 40

// ---------------- scratch (device globals; no allocation allowed) ----------------
__device__ uint2  g_h16[(size_t)NN * 64];   // 25.6 MB (GEMM outputs, half2-packed)
__device__ uint2  g_x16[(size_t)NN * 64];   // 25.6 MB (agg outputs / std input, half2-packed)
__device__ __half g_h2[(size_t)NN * LL];    // 4 MB (final-layer logits input)
__device__ int   g_src[EE];
__device__ int   g_dst[EE];
__device__ int   g_col[EE];
__device__ int   g_counts[NN];
__device__ int   g_rowptr[NN + 1];
__device__ int   g_cursor[NN];
__device__ float g_dinv[NN];
__device__ float g_als[NN];
__device__ float g_ald[NN];
__device__ float g_colsum[DD];
__device__ float g_colsumsq[DD];
__device__ float g_mean[DD];
__device__ float g_istd[DD];
__device__ int   g_flag;  // 1 = edge_index is int64, 0 = int32
__device__ uint4 g_Whi4[(256 * 256) / 8];   // fp16 [n][k] transposed weight hi plane
__device__ uint4 g_Wlo4[(256 * 256) / 8];   // fp16 [n][k] residual plane

__device__ __forceinline__ float lrelu(float v) { return v > 0.f ? v : 0.2f * v; }
__device__ __forceinline__ uint32_t swz128(uint32_t o) { return o ^ ((o >> 3) & 0x70); }

__device__ __forceinline__ uint32_t smem_u32(const void* p) {
    uint32_t a;
    asm("{ .reg .u64 t; cvta.to.shared.u64 t, %1; cvt.u32.u64 %0, t; }" : "=r"(a) : "l"(p));
    return a;
}

#define LDSM_X4(r0, r1, r2, r3, addr)                                               \
    asm volatile("ldmatrix.sync.aligned.m8n8.x4.shared.b16 {%0,%1,%2,%3}, [%4];"    \
                 : "=r"(r0), "=r"(r1), "=r"(r2), "=r"(r3) : "r"(addr))

#define MMAF16(d, a, b)                                                             \
    asm volatile("mma.sync.aligned.m16n8k16.row.col.f32.f16.f16.f32 "               \
                 "{%0,%1,%2,%3}, {%4,%5,%6,%7}, {%8,%9}, {%0,%1,%2,%3};"            \
                 : "+f"((d)[0]), "+f"((d)[1]), "+f"((d)[2]), "+f"((d)[3])           \
                 : "r"((a)[0]), "r"((a)[1]), "r"((a)[2]), "r"((a)[3]),              \
                   "r"((b)[0]), "r"((b)[1]))

#define CP_ASYNC16(dst, src, sz)                                                    \
    asm volatile("cp.async.cg.shared.global [%0], [%1], 16, %2;"                    \
                 :: "r"(dst), "l"(src), "r"(sz))
#define CP_COMMIT()  asm volatile("cp.async.commit_group;" ::: "memory")
#define CP_WAIT1()   asm volatile("cp.async.wait_group 1;" ::: "memory")
#define CP_WAIT0()   asm volatile("cp.async.wait_group 0;" ::: "memory")

// ---------------- setup kernels ----------------
__global__ void zero_kernel() {
    int i = blockIdx.x * blockDim.x + threadIdx.x;
    if (i < NN) g_counts[i] = 0;
}

__global__ void zero_al_kernel() {
    int i = blockIdx.x * blockDim.x + threadIdx.x;
    if (i < NN) { g_als[i] = 0.f; g_ald[i] = 0.f; }
}

__global__ void detect_kernel(const unsigned int* __restrict__ p) {
    if (blockIdx.x == 0 && threadIdx.x == 0) {
        int is64 = 1;
        for (int i = 0; i < 64; i++)
            if (p[2 * i + 1] != 0u) { is64 = 0; break; }
        g_flag = is64;
    }
}

__global__ void convert_kernel(const void* __restrict__ ei) {
    int e = blockIdx.x * blockDim.x + threadIdx.x;
    if (e >= EE) return;
    int s, d;
    if (g_flag) {
        const long long* p = (const long long*)ei;
        s = (int)p[e]; d = (int)p[EE + e];
    } else {
        const int* p = (const int*)ei;
        s = p[e]; d = p[EE + e];
    }
    g_src[e] = s;
    g_dst[e] = d;
    atomicAdd(&g_counts[d], 1);
}

// 296 blocks; MLP-4 row batching; smem reduce -> 296 atomics/address
__global__ void stats_kernel(const float* __restrict__ x) {
    __shared__ float4 ss[256], ss2[256];
    int cg = threadIdx.x & 63;
    int rl = threadIdx.x >> 6;
    int g4 = gridDim.x * 4;
    float4 s = make_float4(0.f, 0.f, 0.f, 0.f);
    float4 s2 = make_float4(0.f, 0.f, 0.f, 0.f);
    for (int r = blockIdx.x * 4 + rl; r < NN; r += g4 * 4) {
        float4 v[4];
#pragma unroll
        for (int j = 0; j < 4; j++) {
            int rr = r + j * g4;
            v[j] = (rr < NN) ? ((const float4*)x)[(size_t)rr * 64 + cg]
                             : make_float4(0.f, 0.f, 0.f, 0.f);
        }
#pragma unroll
        for (int j = 0; j < 4; j++) {
            s.x += v[j].x; s.y += v[j].y; s.z += v[j].z; s.w += v[j].w;
            s2.x += v[j].x * v[j].x; s2.y += v[j].y * v[j].y;
            s2.z += v[j].z * v[j].z; s2.w += v[j].w * v[j].w;
        }
    }
    ss[threadIdx.x] = s; ss2[threadIdx.x] = s2;
    __syncthreads();
    if (threadIdx.x < 64) {
#pragma unroll
        for (int k = 1; k < 4; k++) {
            float4 t = ss[threadIdx.x + 64 * k], t2 = ss2[threadIdx.x + 64 * k];
            s.x += t.x; s.y += t.y; s.z += t.z; s.w += t.w;
            s2.x += t2.x; s2.y += t2.y; s2.z += t2.z; s2.w += t2.w;
        }
        int c = threadIdx.x * 4;
        atomicAdd(&g_colsum[c + 0], s.x); atomicAdd(&g_colsum[c + 1], s.y);
        atomicAdd(&g_colsum[c + 2], s.z); atomicAdd(&g_colsum[c + 3], s.w);
        atomicAdd(&g_colsumsq[c + 0], s2.x); atomicAdd(&g_colsumsq[c + 1], s2.y);
        atomicAdd(&g_colsumsq[c + 2], s2.z); atomicAdd(&g_colsumsq[c + 3], s2.w);
    }
}

__global__ void finalize_kernel() {
    int c = threadIdx.x;
    float mean = g_colsum[c] / (float)NN;
    float var = (g_colsumsq[c] - (float)NN * mean * mean) / (float)(NN - 1);
    g_mean[c] = mean;
    g_istd[c] = rsqrtf(var);
}

// x fp32 -> standardized fp16 plane
__global__ void std16_kernel(const float* __restrict__ x) {
    int idx = blockIdx.x * blockDim.x + threadIdx.x;
    if (idx >= NN * 64) return;
    int c4 = (idx & 63) * 4;
    float4 v = ((const float4*)x)[idx];
    v.x = (v.x - g_mean[c4 + 0]) * g_istd[c4 + 0];
    v.y = (v.y - g_mean[c4 + 1]) * g_istd[c4 + 1];
    v.z = (v.z - g_mean[c4 + 2]) * g_istd[c4 + 2];
    v.w = (v.w - g_mean[c4 + 3]) * g_istd[c4 + 3];
    __half2 h01 = __floats2half2_rn(v.x, v.y);
    __half2 h23 = __floats2half2_rn(v.z, v.w);
    g_x16[idx] = make_uint2(*(uint32_t*)&h01, *(uint32_t*)&h23);
}

__global__ void dinv_kernel() {
    int i = blockIdx.x * blockDim.x + threadIdx.x;
    if (i < NN) g_dinv[i] = rsqrtf((float)(g_counts[i] + 1));
}

__global__ void scan_kernel() {
    __shared__ int warpsum[32];
    __shared__ int s_off;
    int tid = threadIdx.x;
    int lane = tid & 31, wid = tid >> 5;
    if (tid == 0) s_off = 0;
    __syncthreads();
    for (int base = 0; base < NN; base += 1024) {
        int i = base + tid;
        int v = (i < NN) ? g_counts[i] : 0;
        int xs = v;
#pragma unroll
        for (int d = 1; d < 32; d <<= 1) {
            int t = __shfl_up_sync(0xffffffffu, xs, d);
            if (lane >= d) xs += t;
        }
        if (lane == 31) warpsum[wid] = xs;
        __syncthreads();
        if (wid == 0) {
            int w = warpsum[lane];
#pragma unroll
            for (int d = 1; d < 32; d <<= 1) {
                int t = __shfl_up_sync(0xffffffffu, w, d);
                if (lane >= d) w += t;
            }
            warpsum[lane] = w;
        }
        __syncthreads();
        int excl = xs - v + (wid ? warpsum[wid - 1] : 0);
        int off = s_off;
        if (i < NN) { g_rowptr[i] = off + excl; g_cursor[i] = off + excl; }
        __syncthreads();
        if (tid == 1023) s_off = off + excl + v;
        __syncthreads();
    }
    if (tid == 0) g_rowptr[NN] = s_off;
}

__global__ void fill_kernel() {
    int e = blockIdx.x * blockDim.x + threadIdx.x;
    if (e >= EE) return;
    int d = g_dst[e];
    int p = atomicAdd(&g_cursor[d], 1);
    g_col[p] = g_src[e];
}

// ---------------- weight transpose + fp16 hi/lo split (zeroes stats accumulators) --------
__global__ void splitW_kernel(const float* __restrict__ W) {
    int idx = blockIdx.x * blockDim.x + threadIdx.x;
    if (idx < 256) { g_colsum[idx] = 0.f; g_colsumsq[idx] = 0.f; }
    if (idx >= 256 * 256) return;
    int k = idx >> 8;
    int n = idx & 255;
    float v = W[idx];
    __half h = __float2half_rn(v);
    float r = v - __half2float(h);
    __half* whi = (__half*)g_Whi4;
    __half* wlo = (__half*)g_Wlo4;
    whi[n * 256 + k] = h;
    wlo[n * 256 + k] = __float2half_rn(r);
}

// ---------------- mma.sync fp16 GEMM with cp.async double-buffered pipeline --------------
// Tile 128x128, 8 warps. A fp16 exact, W = Whi + Wlo (fp16 planes), 2 MMA terms.
// Per-chunk buffer: A 16KB | BHI 16KB | BLO 16KB. Two buffers = 96KB.
#define CB_A   0
#define CB_BHI 16384
#define CB_BLO 32768
#define CB_SZ  49152
#define MMA_SMEM (2 * CB_SZ)

__global__ void __launch_bounds__(256) mma_gemm_kernel(
    const __half* __restrict__ A16, const __half* __restrict__ Bhi_g,
    const __half* __restrict__ Blo_g, __half* __restrict__ C16, int M,
    int doAl, const float* __restrict__ a_src, const float* __restrict__ a_dst) {
    extern __shared__ char smem[];
    uint32_t sb = smem_u32(smem);
    int tid = threadIdx.x;
    int wid = tid >> 5, lane = tid & 31;
    int bm = blockIdx.y * 128;
    int bn = blockIdx.x * 128;
    int wm = (wid >> 1) * 32;
    int wn = (wid & 1) * 64;

    float acc[2][8][4];
#pragma unroll
    for (int mt = 0; mt < 2; mt++)
#pragma unroll
        for (int nt = 0; nt < 8; nt++)
#pragma unroll
            for (int r = 0; r < 4; r++) acc[mt][nt][r] = 0.f;

    // staging indices: 1024 16B-segments per plane, 4 per thread
    int srow = tid >> 1;                    // 0..127 (2 threads per row, 4 rows-worth each? no:)
    // lin scheme: lin = tid + i*256, row = lin>>3, seg = lin&7
    uint32_t b_row[4], b_cb;
#pragma unroll
    for (int ntp = 0; ntp < 4; ntp++)
        b_row[ntp] = (uint32_t)(wn + ntp * 16 + (lane & 7) + ((lane >> 4) << 3));
    b_cb = (uint32_t)(((lane >> 3) & 1) * 16);
    (void)srow;

    // ---- stage chunk ch into buffer buf ----
#define STAGE(ch, buf)                                                                  \
    do {                                                                                \
        int _k0 = (ch) * 64;                                                            \
        uint32_t _base = sb + (buf) * CB_SZ;                                            \
        _Pragma("unroll")                                                               \
        for (int _i = 0; _i < 4; _i++) {                                                \
            int _lin = tid + _i * 256;                                                  \
            int _row = _lin >> 3, _sg = _lin & 7;                                       \
            uint32_t _so = swz128((uint32_t)(_row * 128 + _sg * 16));                   \
            int _gr = bm + _row;                                                        \
            const __half* _sa = A16 + (size_t)(_gr < M ? _gr : M - 1) * 256 + _k0 + _sg * 8; \
            CP_ASYNC16(_base + CB_A + _so, _sa, (_gr < M) ? 16 : 0);                    \
            const __half* _sh = Bhi_g + (size_t)(bn + _row) * 256 + _k0 + _sg * 8;      \
            const __half* _sl = Blo_g + (size_t)(bn + _row) * 256 + _k0 + _sg * 8;      \
            CP_ASYNC16(_base + CB_BHI + _so, _sh, 16);                                  \
            CP_ASYNC16(_base + CB_BLO + _so, _sl, 16);                                  \
        }                                                                               \
        CP_COMMIT();                                                                    \
    } while (0)

    STAGE(0, 0);
    for (int ch = 0; ch < 4; ch++) {
        int buf = ch & 1;
        if (ch < 3) { STAGE(ch + 1, buf ^ 1); CP_WAIT1(); }
        else        { CP_WAIT0(); }
        __syncthreads();
        uint32_t base = sb + buf * CB_SZ;
#pragma unroll
        for (int ks = 0; ks < 4; ks++) {
            uint32_t kb = (uint32_t)(ks * 32);
            uint32_t a[2][4];
#pragma unroll
            for (int mt = 0; mt < 2; mt++) {
                uint32_t row = (uint32_t)(wm + mt * 16 + (lane & 15));
                uint32_t cb = (uint32_t)((lane >> 4) * 16) + kb;
                uint32_t ad = base + CB_A + swz128(row * 128 + cb);
                LDSM_X4(a[mt][0], a[mt][1], a[mt][2], a[mt][3], ad);
            }
            uint32_t bh[8][2], bl[8][2];
#pragma unroll
            for (int ntp = 0; ntp < 4; ntp++) {
                uint32_t bo = swz128(b_row[ntp] * 128 + b_cb + kb);
                LDSM_X4(bh[2 * ntp][0], bh[2 * ntp][1], bh[2 * ntp + 1][0],
                        bh[2 * ntp + 1][1], base + CB_BHI + bo);
                LDSM_X4(bl[2 * ntp][0], bl[2 * ntp][1], bl[2 * ntp + 1][0],
                        bl[2 * ntp + 1][1], base + CB_BLO + bo);
            }
#pragma unroll
            for (int mt = 0; mt < 2; mt++)
#pragma unroll
                for (int nt = 0; nt < 8; nt++) {
                    MMAF16(acc[mt][nt], a[mt], bh[nt]);
                    MMAF16(acc[mt][nt], a[mt], bl[nt]);
                }
        }
        __syncthreads();
    }
#undef STAGE

    // ---- epilogue: fp16 store + optional fused attention logits ----
#pragma unroll
    for (int mt = 0; mt < 2; mt++) {
        int r0 = bm + wm + mt * 16 + (lane >> 2);
        int r1 = r0 + 8;
        float ds0 = 0.f, dd0 = 0.f, ds1 = 0.f, dd1 = 0.f;
#pragma unroll
        for (int nt = 0; nt < 8; nt++) {
            int col = bn + wn + nt * 8 + (lane & 3) * 2;
            if (r0 < M) *(__half2*)(C16 + (size_t)r0 * 256 + col) =
                __floats2half2_rn(acc[mt][nt][0], acc[mt][nt][1]);
            if (r1 < M) *(__half2*)(C16 + (size_t)r1 * 256 + col) =
                __floats2half2_rn(acc[mt][nt][2], acc[mt][nt][3]);
            if (doAl) {
                float as0 = a_src[col], as1 = a_src[col + 1];
                float ad0 = a_dst[col], ad1 = a_dst[col + 1];
                ds0 += acc[mt][nt][0] * as0 + acc[mt][nt][1] * as1;
                dd0 += acc[mt][nt][0] * ad0 + acc[mt][nt][1] * ad1;
                ds1 += acc[mt][nt][2] * as0 + acc[mt][nt][3] * as1;
                dd1 += acc[mt][nt][2] * ad0 + acc[mt][nt][3] * ad1;
            }
        }
        if (doAl) {
#pragma unroll
            for (int o = 1; o < 4; o <<= 1) {
                ds0 += __shfl_xor_sync(0xffffffffu, ds0, o);
                dd0 += __shfl_xor_sync(0xffffffffu, dd0, o);
                ds1 += __shfl_xor_sync(0xffffffffu, ds1, o);
                dd1 += __shfl_xor_sync(0xffffffffu, dd1, o);
            }
            if ((lane & 3) == 0) {
                if (r0 < M) { atomicAdd(&g_als[r0], ds0); atomicAdd(&g_ald[r0], dd0); }
                if (r1 < M) { atomicAdd(&g_als[r1], ds1); atomicAdd(&g_ald[r1], dd1); }
            }
        }
    }
}

// ---------------- SIMT GEMM (final 256x40 layer; fp16 A in, fp16 C out) -----------------
__global__ void gemm_kernel(const __half* __restrict__ A16, const float* __restrict__ B,
                            __half* __restrict__ C, int M, int Nn) {
    const int K = 256;
    __shared__ float As[16][128];
    __shared__ float Bs[16][64];
    int tid = threadIdx.x;
    int bm = blockIdx.y * 128;
    int bn = blockIdx.x * 64;
    int tx = tid & 15;
    int ty = tid >> 4;
    float acc[8][4];
#pragma unroll
    for (int i = 0; i < 8; i++)
#pragma unroll
        for (int j = 0; j < 4; j++) acc[i][j] = 0.f;

    for (int k0 = 0; k0 < K; k0 += 16) {
#pragma unroll
        for (int l = 0; l < 2; l++) {
            int lin = tid + l * 256;
            int row = lin >> 2;
            int c4 = (lin & 3) * 4;
            float4 v = make_float4(0.f, 0.f, 0.f, 0.f);
            if (bm + row < M) {
                uint2 u = *(const uint2*)(A16 + (size_t)(bm + row) * K + k0 + c4);
                float2 f01 = __half22float2(*(__half2*)&u.x);
                float2 f23 = __half22float2(*(__half2*)&u.y);
                v = make_float4(f01.x, f01.y, f23.x, f23.y);
            }
            As[c4 + 0][row] = v.x;
            As[c4 + 1][row] = v.y;
            As[c4 + 2][row] = v.z;
            As[c4 + 3][row] = v.w;
        }
        {
            int row = tid >> 4;
            int c4 = (tid & 15) * 4;
#pragma unroll
            for (int j = 0; j < 4; j++) {
                int cc = bn + c4 + j;
                Bs[row][c4 + j] = (cc < Nn) ? B[(size_t)(k0 + row) * Nn + cc] : 0.f;
            }
        }
        __syncthreads();
#pragma unroll
        for (int k = 0; k < 16; k++) {
            float4 a0 = *(const float4*)&As[k][ty * 8];
            float4 a1 = *(const float4*)&As[k][ty * 8 + 4];
            float4 b0 = *(const float4*)&Bs[k][tx * 4];
            float a[8] = {a0.x, a0.y, a0.z, a0.w, a1.x, a1.y, a1.z, a1.w};
            float b[4] = {b0.x, b0.y, b0.z, b0.w};
#pragma unroll
            for (int i = 0; i < 8; i++)
#pragma unroll
                for (int j = 0; j < 4; j++) acc[i][j] += a[i] * b[j];
        }
        __syncthreads();
    }
#pragma unroll
    for (int i = 0; i < 8; i++) {
        int row = bm + ty * 8 + i;
        if (row >= M) continue;
#pragma unroll
        for (int j = 0; j < 4; j++) {
            int col = bn + tx * 4 + j;
            if (col < Nn) C[(size_t)row * Nn + col] = __float2half(acc[i][j]);
        }
    }
}

// ---- fp16 row gather/store helpers ----
__device__ __forceinline__ void h16_accum(const uint2* __restrict__ hp, int idx, float w,
                                          float4& a0, float4& a1) {
    uint2 u0 = hp[idx];
    uint2 u1 = hp[idx + 32];
    float2 f0 = __half22float2(*(__half2*)&u0.x);
    float2 f1 = __half22float2(*(__half2*)&u0.y);
    float2 f2 = __half22float2(*(__half2*)&u1.x);
    float2 f3 = __half22float2(*(__half2*)&u1.y);
    a0.x += w * f0.x; a0.y += w * f0.y; a0.z += w * f1.x; a0.w += w * f1.y;
    a1.x += w * f2.x; a1.y += w * f2.y; a1.z += w * f3.x; a1.w += w * f3.y;
}

__device__ __forceinline__ void h16_store(uint2* __restrict__ o, int node, int lane,
                                          const float4& a0, const float4& a1) {
    __half2 h01 = __floats2half2_rn(a0.x, a0.y);
    __half2 h23 = __floats2half2_rn(a0.z, a0.w);
    uint2 u0 = make_uint2(*(uint32_t*)&h01, *(uint32_t*)&h23);
    __half2 h45 = __floats2half2_rn(a1.x, a1.y);
    __half2 h67 = __floats2half2_rn(a1.z, a1.w);
    uint2 u1 = make_uint2(*(uint32_t*)&h45, *(uint32_t*)&h67);
    o[(size_t)node * 64 + lane] = u0;
    o[(size_t)node * 64 + lane + 32] = u1;
}

// ---------------- GCN aggregate (warp per dst node, fp16 in/out, unroll-4) ---------------
__global__ void gcn_agg_kernel(const uint2* __restrict__ h, const float* __restrict__ bias,
                               uint2* __restrict__ out) {
    int t = blockIdx.x * blockDim.x + threadIdx.x;
    int node = t >> 5;
    int lane = t & 31;
    if (node >= NN) return;
    int beg = g_rowptr[node], end = g_rowptr[node + 1];
    float di = g_dinv[node];
    float4 a0 = make_float4(0.f, 0.f, 0.f, 0.f);
    float4 a1 = make_float4(0.f, 0.f, 0.f, 0.f);
    h16_accum(h, node * 64 + lane, di * di, a0, a1);
    int e = beg;
    for (; e + 4 <= end; e += 4) {
        int s0 = g_col[e], s1 = g_col[e + 1], s2 = g_col[e + 2], s3 = g_col[e + 3];
        float w0 = g_dinv[s0] * di, w1 = g_dinv[s1] * di;
        float w2 = g_dinv[s2] * di, w3 = g_dinv[s3] * di;
        h16_accum(h, s0 * 64 + lane, w0, a0, a1);
        h16_accum(h, s1 * 64 + lane, w1, a0, a1);
        h16_accum(h, s2 * 64 + lane, w2, a0, a1);
        h16_accum(h, s3 * 64 + lane, w3, a0, a1);
    }
    for (; e < end; e++) {
        int s = g_col[e];
        h16_accum(h, s * 64 + lane, g_dinv[s] * di, a0, a1);
    }
    float4 b0 = ((const float4*)bias)[lane];
    float4 b1 = ((const float4*)bias)[lane + 32];
    a0.x = fmaxf(a0.x + b0.x, 0.f); a0.y = fmaxf(a0.y + b0.y, 0.f);
    a0.z = fmaxf(a0.z + b0.z, 0.f); a0.w = fmaxf(a0.w + b0.w, 0.f);
    a1.x = fmaxf(a1.x + b1.x, 0.f); a1.y = fmaxf(a1.y + b1.y, 0.f);
    a1.z = fmaxf(a1.z + b1.z, 0.f); a1.w = fmaxf(a1.w + b1.w, 0.f);
    h16_store(out, node, lane, a0, a1);
}

// ---------------- GAT aggregate with segment softmax (fp16 in/out, unroll-4) -------------
__global__ void gat_agg_kernel(const uint2* __restrict__ h, const float* __restrict__ bias,
                               uint2* __restrict__ out) {
    int t = blockIdx.x * blockDim.x + threadIdx.x;
    int node = t >> 5;
    int lane = t & 31;
    if (node >= NN) return;
    int beg = g_rowptr[node], end = g_rowptr[node + 1];
    float aldi = g_ald[node];
    float e_self = lrelu(g_als[node] + aldi);
    float m = e_self;
    for (int e = beg + lane; e < end; e += 32)
        m = fmaxf(m, lrelu(g_als[g_col[e]] + aldi));
    for (int o = 16; o; o >>= 1) m = fmaxf(m, __shfl_xor_sync(0xffffffffu, m, o));
    float z = __expf(e_self - m);
    float4 a0 = make_float4(0.f, 0.f, 0.f, 0.f);
    float4 a1 = make_float4(0.f, 0.f, 0.f, 0.f);
    h16_accum(h, node * 64 + lane, z, a0, a1);
    int e = beg;
    for (; e + 4 <= end; e += 4) {
        int s0 = g_col[e], s1 = g_col[e + 1], s2 = g_col[e + 2], s3 = g_col[e + 3];
        float w0 = __expf(lrelu(g_als[s0] + aldi) - m);
        float w1 = __expf(lrelu(g_als[s1] + aldi) - m);
        float w2 = __expf(lrelu(g_als[s2] + aldi) - m);
        float w3 = __expf(lrelu(g_als[s3] + aldi) - m);
        z += w0 + w1 + w2 + w3;
        h16_accum(h, s0 * 64 + lane, w0, a0, a1);
        h16_accum(h, s1 * 64 + lane, w1, a0, a1);
        h16_accum(h, s2 * 64 + lane, w2, a0, a1);
        h16_accum(h, s3 * 64 + lane, w3, a0, a1);
    }
    for (; e < end; e++) {
        int s = g_col[e];
        float w = __expf(lrelu(g_als[s] + aldi) - m);
        z += w;
        h16_accum(h, s * 64 + lane, w, a0, a1);
    }
    float inv = 1.0f / z;
    float4 b0 = ((const float4*)bias)[lane];
    float4 b1 = ((const float4*)bias)[lane + 32];
    a0.x = fmaxf(a0.x * inv + b0.x, 0.f); a0.y = fmaxf(a0.y * inv + b0.y, 0.f);
    a0.z = fmaxf(a0.z * inv + b0.z, 0.f); a0.w = fmaxf(a0.w * inv + b0.w, 0.f);
    a1.x = fmaxf(a1.x * inv + b1.x, 0.f); a1.y = fmaxf(a1.y * inv + b1.y, 0.f);
    a1.z = fmaxf(a1.z * inv + b1.z, 0.f); a1.w = fmaxf(a1.w * inv + b1.w, 0.f);
    h16_store(out, node, lane, a0, a1);
}

// ---------------- final GCN (L=40, fp16 h2) + log_softmax (unroll-2) ----------------
__global__ void gcn2_kernel(const __half* __restrict__ h2, const float* __restrict__ b2,
                            float* __restrict__ out) {
    int t = blockIdx.x * blockDim.x + threadIdx.x;
    int node = t >> 5;
    int lane = t & 31;
    if (node >= NN) return;
    int beg = g_rowptr[node], end = g_rowptr[node + 1];
    float di = g_dinv[node];
    float w = di * di;
    float a0 = w * __half2float(h2[(size_t)node * LL + lane]);
    float a1 = (lane < 8) ? w * __half2float(h2[(size_t)node * LL + lane + 32]) : 0.f;
    int e = beg;
    for (; e + 2 <= end; e += 2) {
        int s0 = g_col[e], s1 = g_col[e + 1];
        float w0 = g_dinv[s0] * di, w1 = g_dinv[s1] * di;
        float x0 = __half2float(h2[(size_t)s0 * LL + lane]);
        float x1 = __half2float(h2[(size_t)s1 * LL + lane]);
        a0 += w0 * x0 + w1 * x1;
        if (lane < 8) {
            a1 += w0 * __half2float(h2[(size_t)s0 * LL + lane + 32]) +
                  w1 * __half2float(h2[(size_t)s1 * LL + lane + 32]);
        }
    }
    if (e < end) {
        int s = g_col[e];
        float we = g_dinv[s] * di;
        a0 += we * __half2float(h2[(size_t)s * LL + lane]);
        if (lane < 8) a1 += we * __half2float(h2[(size_t)s * LL + lane + 32]);
    }
    float v0 = a0 + b2[lane];
    float v1 = (lane < 8) ? a1 + b2[lane + 32] : -INFINITY;
    float m = fmaxf(v0, v1);
    for (int o = 16; o; o >>= 1) m = fmaxf(m, __shfl_xor_sync(0xffffffffu, m, o));
    float z = expf(v0 - m) + ((lane < 8) ? expf(v1 - m) : 0.f);
    for (int o = 16; o; o >>= 1) z += __shfl_xor_sync(0xffffffffu, z, o);
    float ls = logf(z);
    out[(size_t)node * LL + lane] = v0 - m - ls;
    if (lane < 8) out[(size_t)node * LL + lane + 32] = v1 - m - ls;
}

// ---------------- launch ----------------
extern "C" void kernel_launch(void* const* d_in, const int* in_sizes, int n_in,
                              void* d_out, int out_size) {
    const float* x   = (const float*)d_in[0];
    const void*  ei  = d_in[1];
    const float* W1  = (const float*)d_in[2];
    const float* b1  = (const float*)d_in[3];
    const float* Wg  = (const float*)d_in[4];
    const float* a_s = (const float*)d_in[5];
    const float* a_d = (const float*)d_in[6];
    const float* bg  = (const float*)d_in[7];
    const float* W2  = (const float*)d_in[8];
    const float* b2  = (const float*)d_in[9];
    float* out = (float*)d_out;

    uint2 *pH16, *pX16;
    __half* pH2;
    __half *pWhi, *pWlo;
    cudaGetSymbolAddress((void**)&pH16, g_h16);
    cudaGetSymbolAddress((void**)&pX16, g_x16);
    cudaGetSymbolAddress((void**)&pH2, g_h2);
    cudaGetSymbolAddress((void**)&pWhi, g_Whi4);
    cudaGetSymbolAddress((void**)&pWlo, g_Wlo4);

    cudaFuncSetAttribute(mma_gemm_kernel, cudaFuncAttributeMaxDynamicSharedMemorySize, MMA_SMEM);

    const int tpb = 256;
    dim3 gMMA(2, (NN + 127) / 128);
    dim3 g40((40 + 63) / 64, (NN + 127) / 128);
    int warpGrid = (NN * 32 + tpb - 1) / tpb;
    int zg = (NN + tpb - 1) / tpb;

    // --- GEMM-1 path ---
    splitW_kernel<<<(256 * 256) / tpb, tpb>>>(W1);   // also zeroes colsum/colsumsq
    stats_kernel<<<296, 256>>>(x);
    finalize_kernel<<<1, 256>>>();
    std16_kernel<<<(NN * 64 + tpb - 1) / tpb, tpb>>>(x);
    mma_gemm_kernel<<<gMMA, 256, MMA_SMEM>>>((const __half*)pX16, pWhi, pWlo,
                                             (__half*)pH16, NN, 0, a_s, a_d);

    // --- CSR build (independent of GEMM-1) ---
    zero_kernel<<<(NN + tpb - 1) / tpb, tpb>>>();
    detect_kernel<<<1, 32>>>((const unsigned int*)ei);
    convert_kernel<<<(EE + tpb - 1) / tpb, tpb>>>(ei);
    dinv_kernel<<<(NN + tpb - 1) / tpb, tpb>>>();
    scan_kernel<<<1, 1024>>>();
    fill_kernel<<<(EE + tpb - 1) / tpb, tpb>>>();

    // GCN layer 1 aggregate (+ReLU) -> x16 fp16
    gcn_agg_kernel<<<warpGrid, tpb>>>(pH16, b1, pX16);

    // GAT layer 1 (+ReLU)
    splitW_kernel<<<(256 * 256) / tpb, tpb>>>(Wg);
    zero_al_kernel<<<zg, tpb>>>();
    mma_gemm_kernel<<<gMMA, 256, MMA_SMEM>>>((const __half*)pX16, pWhi, pWlo,
                                             (__half*)pH16, NN, 1, a_s, a_d);
    gat_agg_kernel<<<warpGrid, tpb>>>(pH16, bg, pX16);

    // GAT layer 2 (+ReLU) — Wg planes already split
    zero_al_kernel<<<zg, tpb>>>();
    mma_gemm_kernel<<<gMMA, 256, MMA_SMEM>>>((const __half*)pX16, pWhi, pWlo,
                                             (__half*)pH16, NN, 1, a_s, a_d);
    gat_agg_kernel<<<warpGrid, tpb>>>(pH16, bg, pX16);

    // GCN layer 2 + log_softmax
    gemm_kernel<<<g40, 256>>>((const __half*)pX16, W2, pH2, NN, 40);
    gcn2_kernel<<<warpGrid, tpb>>>(pH2, b2, out);
}

// round 8
// speedup vs baseline: 2.4599x; 1.1888x over previous
#include <cuda_runtime.h>
#include <cuda_fp16.h>
#include <math.h>
#include <stdint.h>

#define NN 50000
#define EE 800000
#define DD 256
#define HH 256
#define LL 40

// ---------------- scratch (device globals; no allocation allowed) ----------------
__device__ uint2  g_h16[(size_t)NN * 64];   // 25.6 MB (GEMM outputs, half2-packed)
__device__ uint2  g_x16[(size_t)NN * 64];   // 25.6 MB (agg outputs / std input, half2-packed)
__device__ __half g_h2[(size_t)NN * LL];    // 4 MB (final-layer logits, fp16, stride 40)
__device__ int   g_src[EE];
__device__ int   g_dst[EE];
__device__ int   g_col[EE];
__device__ int   g_counts[NN];
__device__ int   g_rowptr[NN + 1];
__device__ int   g_cursor[NN];
__device__ float g_dinv[NN];
__device__ float g_als[NN];
__device__ float g_ald[NN];
__device__ float g_colsum[DD];
__device__ float g_colsumsq[DD];
__device__ float g_mean[DD];
__device__ float g_istd[DD];
__device__ int   g_flag;  // 1 = edge_index is int64, 0 = int32
__device__ uint4 g_Whi4[(256 * 256) / 8];   // fp16 [n][k] transposed weight hi plane
__device__ uint4 g_Wlo4[(256 * 256) / 8];   // fp16 [n][k] residual plane

__device__ __forceinline__ float lrelu(float v) { return v > 0.f ? v : 0.2f * v; }
__device__ __forceinline__ uint32_t swz128(uint32_t o) { return o ^ ((o >> 3) & 0x70); }

__device__ __forceinline__ uint32_t smem_u32(const void* p) {
    uint32_t a;
    asm("{ .reg .u64 t; cvta.to.shared.u64 t, %1; cvt.u32.u64 %0, t; }" : "=r"(a) : "l"(p));
    return a;
}

#define LDSM_X4(r0, r1, r2, r3, addr)                                               \
    asm volatile("ldmatrix.sync.aligned.m8n8.x4.shared.b16 {%0,%1,%2,%3}, [%4];"    \
                 : "=r"(r0), "=r"(r1), "=r"(r2), "=r"(r3) : "r"(addr))

#define MMAF16(d, a, b)                                                             \
    asm volatile("mma.sync.aligned.m16n8k16.row.col.f32.f16.f16.f32 "               \
                 "{%0,%1,%2,%3}, {%4,%5,%6,%7}, {%8,%9}, {%0,%1,%2,%3};"            \
                 : "+f"((d)[0]), "+f"((d)[1]), "+f"((d)[2]), "+f"((d)[3])           \
                 : "r"((a)[0]), "r"((a)[1]), "r"((a)[2]), "r"((a)[3]),              \
                   "r"((b)[0]), "r"((b)[1]))

#define CP_ASYNC16(dst, src, sz)                                                    \
    asm volatile("cp.async.cg.shared.global [%0], [%1], 16, %2;"                    \
                 :: "r"(dst), "l"(src), "r"(sz))
#define CP_COMMIT()  asm volatile("cp.async.commit_group;" ::: "memory")
#define CP_WAIT1()   asm volatile("cp.async.wait_group 1;" ::: "memory")
#define CP_WAIT0()   asm volatile("cp.async.wait_group 0;" ::: "memory")

// ---------------- setup kernels ----------------
__global__ void zero_kernel() {
    int i = blockIdx.x * blockDim.x + threadIdx.x;
    if (i < NN) g_counts[i] = 0;
}

__global__ void zero_al_kernel() {
    int i = blockIdx.x * blockDim.x + threadIdx.x;
    if (i < NN) { g_als[i] = 0.f; g_ald[i] = 0.f; }
}

__global__ void detect_kernel(const unsigned int* __restrict__ p) {
    if (blockIdx.x == 0 && threadIdx.x == 0) {
        int is64 = 1;
        for (int i = 0; i < 64; i++)
            if (p[2 * i + 1] != 0u) { is64 = 0; break; }
        g_flag = is64;
    }
}

__global__ void convert_kernel(const void* __restrict__ ei) {
    int e = blockIdx.x * blockDim.x + threadIdx.x;
    if (e >= EE) return;
    int s, d;
    if (g_flag) {
        const long long* p = (const long long*)ei;
        s = (int)p[e]; d = (int)p[EE + e];
    } else {
        const int* p = (const int*)ei;
        s = p[e]; d = p[EE + e];
    }
    g_src[e] = s;
    g_dst[e] = d;
    atomicAdd(&g_counts[d], 1);
}

// 296 blocks; MLP-4 row batching; smem reduce -> 296 atomics/address
__global__ void stats_kernel(const float* __restrict__ x) {
    __shared__ float4 ss[256], ss2[256];
    int cg = threadIdx.x & 63;
    int rl = threadIdx.x >> 6;
    int g4 = gridDim.x * 4;
    float4 s = make_float4(0.f, 0.f, 0.f, 0.f);
    float4 s2 = make_float4(0.f, 0.f, 0.f, 0.f);
    for (int r = blockIdx.x * 4 + rl; r < NN; r += g4 * 4) {
        float4 v[4];
#pragma unroll
        for (int j = 0; j < 4; j++) {
            int rr = r + j * g4;
            v[j] = (rr < NN) ? ((const float4*)x)[(size_t)rr * 64 + cg]
                             : make_float4(0.f, 0.f, 0.f, 0.f);
        }
#pragma unroll
        for (int j = 0; j < 4; j++) {
            s.x += v[j].x; s.y += v[j].y; s.z += v[j].z; s.w += v[j].w;
            s2.x += v[j].x * v[j].x; s2.y += v[j].y * v[j].y;
            s2.z += v[j].z * v[j].z; s2.w += v[j].w * v[j].w;
        }
    }
    ss[threadIdx.x] = s; ss2[threadIdx.x] = s2;
    __syncthreads();
    if (threadIdx.x < 64) {
#pragma unroll
        for (int k = 1; k < 4; k++) {
            float4 t = ss[threadIdx.x + 64 * k], t2 = ss2[threadIdx.x + 64 * k];
            s.x += t.x; s.y += t.y; s.z += t.z; s.w += t.w;
            s2.x += t2.x; s2.y += t2.y; s2.z += t2.z; s2.w += t2.w;
        }
        int c = threadIdx.x * 4;
        atomicAdd(&g_colsum[c + 0], s.x); atomicAdd(&g_colsum[c + 1], s.y);
        atomicAdd(&g_colsum[c + 2], s.z); atomicAdd(&g_colsum[c + 3], s.w);
        atomicAdd(&g_colsumsq[c + 0], s2.x); atomicAdd(&g_colsumsq[c + 1], s2.y);
        atomicAdd(&g_colsumsq[c + 2], s2.z); atomicAdd(&g_colsumsq[c + 3], s2.w);
    }
}

__global__ void finalize_kernel() {
    int c = threadIdx.x;
    float mean = g_colsum[c] / (float)NN;
    float var = (g_colsumsq[c] - (float)NN * mean * mean) / (float)(NN - 1);
    g_mean[c] = mean;
    g_istd[c] = rsqrtf(var);
}

// x fp32 -> standardized fp16 plane
__global__ void std16_kernel(const float* __restrict__ x) {
    int idx = blockIdx.x * blockDim.x + threadIdx.x;
    if (idx >= NN * 64) return;
    int c4 = (idx & 63) * 4;
    float4 v = ((const float4*)x)[idx];
    v.x = (v.x - g_mean[c4 + 0]) * g_istd[c4 + 0];
    v.y = (v.y - g_mean[c4 + 1]) * g_istd[c4 + 1];
    v.z = (v.z - g_mean[c4 + 2]) * g_istd[c4 + 2];
    v.w = (v.w - g_mean[c4 + 3]) * g_istd[c4 + 3];
    __half2 h01 = __floats2half2_rn(v.x, v.y);
    __half2 h23 = __floats2half2_rn(v.z, v.w);
    g_x16[idx] = make_uint2(*(uint32_t*)&h01, *(uint32_t*)&h23);
}

__global__ void dinv_kernel() {
    int i = blockIdx.x * blockDim.x + threadIdx.x;
    if (i < NN) g_dinv[i] = rsqrtf((float)(g_counts[i] + 1));
}

__global__ void scan_kernel() {
    __shared__ int warpsum[32];
    __shared__ int s_off;
    int tid = threadIdx.x;
    int lane = tid & 31, wid = tid >> 5;
    if (tid == 0) s_off = 0;
    __syncthreads();
    for (int base = 0; base < NN; base += 1024) {
        int i = base + tid;
        int v = (i < NN) ? g_counts[i] : 0;
        int xs = v;
#pragma unroll
        for (int d = 1; d < 32; d <<= 1) {
            int t = __shfl_up_sync(0xffffffffu, xs, d);
            if (lane >= d) xs += t;
        }
        if (lane == 31) warpsum[wid] = xs;
        __syncthreads();
        if (wid == 0) {
            int w = warpsum[lane];
#pragma unroll
            for (int d = 1; d < 32; d <<= 1) {
                int t = __shfl_up_sync(0xffffffffu, w, d);
                if (lane >= d) w += t;
            }
            warpsum[lane] = w;
        }
        __syncthreads();
        int excl = xs - v + (wid ? warpsum[wid - 1] : 0);
        int off = s_off;
        if (i < NN) { g_rowptr[i] = off + excl; g_cursor[i] = off + excl; }
        __syncthreads();
        if (tid == 1023) s_off = off + excl + v;
        __syncthreads();
    }
    if (tid == 0) g_rowptr[NN] = s_off;
}

__global__ void fill_kernel() {
    int e = blockIdx.x * blockDim.x + threadIdx.x;
    if (e >= EE) return;
    int d = g_dst[e];
    int p = atomicAdd(&g_cursor[d], 1);
    g_col[p] = g_src[e];
}

// ---------------- weight transpose + fp16 hi/lo split (zeroes stats accumulators) --------
__global__ void splitW_kernel(const float* __restrict__ W) {
    int idx = blockIdx.x * blockDim.x + threadIdx.x;
    if (idx < 256) { g_colsum[idx] = 0.f; g_colsumsq[idx] = 0.f; }
    if (idx >= 256 * 256) return;
    int k = idx >> 8;
    int n = idx & 255;
    float v = W[idx];
    __half h = __float2half_rn(v);
    float r = v - __half2float(h);
    __half* whi = (__half*)g_Whi4;
    __half* wlo = (__half*)g_Wlo4;
    whi[n * 256 + k] = h;
    wlo[n * 256 + k] = __float2half_rn(r);
}

// W2 [256,40] -> planes rows 0..127 (rows 40..127 zero), [n][k] fp16
__global__ void splitW2_kernel(const float* __restrict__ W2) {
    int idx = blockIdx.x * blockDim.x + threadIdx.x;   // 128*256
    if (idx >= 128 * 256) return;
    int n = idx >> 8;
    int k = idx & 255;
    float v = (n < LL) ? W2[k * LL + n] : 0.f;
    __half h = __float2half_rn(v);
    float r = v - __half2float(h);
    ((__half*)g_Whi4)[n * 256 + k] = h;
    ((__half*)g_Wlo4)[n * 256 + k] = __float2half_rn(r);
}

// ---------------- mma.sync fp16 GEMM with cp.async double-buffered pipeline --------------
#define CB_A   0
#define CB_BHI 16384
#define CB_BLO 32768
#define CB_SZ  49152
#define MMA_SMEM (2 * CB_SZ)

__global__ void __launch_bounds__(256) mma_gemm_kernel(
    const __half* __restrict__ A16, const __half* __restrict__ Bhi_g,
    const __half* __restrict__ Blo_g, __half* __restrict__ C16, int M,
    int ostride, int ncols,
    int doAl, const float* __restrict__ a_src, const float* __restrict__ a_dst) {
    extern __shared__ char smem[];
    uint32_t sb = smem_u32(smem);
    int tid = threadIdx.x;
    int wid = tid >> 5, lane = tid & 31;
    int bm = blockIdx.y * 128;
    int bn = blockIdx.x * 128;
    int wm = (wid >> 1) * 32;
    int wn = (wid & 1) * 64;

    float acc[2][8][4];
#pragma unroll
    for (int mt = 0; mt < 2; mt++)
#pragma unroll
        for (int nt = 0; nt < 8; nt++)
#pragma unroll
            for (int r = 0; r < 4; r++) acc[mt][nt][r] = 0.f;

    uint32_t b_row[4], b_cb;
#pragma unroll
    for (int ntp = 0; ntp < 4; ntp++)
        b_row[ntp] = (uint32_t)(wn + ntp * 16 + (lane & 7) + ((lane >> 4) << 3));
    b_cb = (uint32_t)(((lane >> 3) & 1) * 16);

#define STAGE(ch, buf)                                                                  \
    do {                                                                                \
        int _k0 = (ch) * 64;                                                            \
        uint32_t _base = sb + (buf) * CB_SZ;                                            \
        _Pragma("unroll")                                                               \
        for (int _i = 0; _i < 4; _i++) {                                                \
            int _lin = tid + _i * 256;                                                  \
            int _row = _lin >> 3, _sg = _lin & 7;                                       \
            uint32_t _so = swz128((uint32_t)(_row * 128 + _sg * 16));                   \
            int _gr = bm + _row;                                                        \
            const __half* _sa = A16 + (size_t)(_gr < M ? _gr : M - 1) * 256 + _k0 + _sg * 8; \
            CP_ASYNC16(_base + CB_A + _so, _sa, (_gr < M) ? 16 : 0);                    \
            const __half* _sh = Bhi_g + (size_t)(bn + _row) * 256 + _k0 + _sg * 8;      \
            const __half* _sl = Blo_g + (size_t)(bn + _row) * 256 + _k0 + _sg * 8;      \
            CP_ASYNC16(_base + CB_BHI + _so, _sh, 16);                                  \
            CP_ASYNC16(_base + CB_BLO + _so, _sl, 16);                                  \
        }                                                                               \
        CP_COMMIT();                                                                    \
    } while (0)

    STAGE(0, 0);
    for (int ch = 0; ch < 4; ch++) {
        int buf = ch & 1;
        if (ch < 3) { STAGE(ch + 1, buf ^ 1); CP_WAIT1(); }
        else        { CP_WAIT0(); }
        __syncthreads();
        uint32_t base = sb + buf * CB_SZ;
#pragma unroll
        for (int ks = 0; ks < 4; ks++) {
            uint32_t kb = (uint32_t)(ks * 32);
            uint32_t a[2][4];
#pragma unroll
            for (int mt = 0; mt < 2; mt++) {
                uint32_t row = (uint32_t)(wm + mt * 16 + (lane & 15));
                uint32_t cb = (uint32_t)((lane >> 4) * 16) + kb;
                uint32_t ad = base + CB_A + swz128(row * 128 + cb);
                LDSM_X4(a[mt][0], a[mt][1], a[mt][2], a[mt][3], ad);
            }
            uint32_t bh[8][2], bl[8][2];
#pragma unroll
            for (int ntp = 0; ntp < 4; ntp++) {
                uint32_t bo = swz128(b_row[ntp] * 128 + b_cb + kb);
                LDSM_X4(bh[2 * ntp][0], bh[2 * ntp][1], bh[2 * ntp + 1][0],
                        bh[2 * ntp + 1][1], base + CB_BHI + bo);
                LDSM_X4(bl[2 * ntp][0], bl[2 * ntp][1], bl[2 * ntp + 1][0],
                        bl[2 * ntp + 1][1], base + CB_BLO + bo);
            }
#pragma unroll
            for (int mt = 0; mt < 2; mt++)
#pragma unroll
                for (int nt = 0; nt < 8; nt++) {
                    MMAF16(acc[mt][nt], a[mt], bh[nt]);
                    MMAF16(acc[mt][nt], a[mt], bl[nt]);
                }
        }
        __syncthreads();
    }
#undef STAGE

    // ---- epilogue: fp16 store (guarded by ncols) + optional fused attention logits ----
#pragma unroll
    for (int mt = 0; mt < 2; mt++) {
        int r0 = bm + wm + mt * 16 + (lane >> 2);
        int r1 = r0 + 8;
        float ds0 = 0.f, dd0 = 0.f, ds1 = 0.f, dd1 = 0.f;
#pragma unroll
        for (int nt = 0; nt < 8; nt++) {
            int col = bn + wn + nt * 8 + (lane & 3) * 2;
            if (col < ncols) {
                if (r0 < M) *(__half2*)(C16 + (size_t)r0 * ostride + col) =
                    __floats2half2_rn(acc[mt][nt][0], acc[mt][nt][1]);
                if (r1 < M) *(__half2*)(C16 + (size_t)r1 * ostride + col) =
                    __floats2half2_rn(acc[mt][nt][2], acc[mt][nt][3]);
            }
            if (doAl) {
                float as0 = a_src[col], as1 = a_src[col + 1];
                float ad0 = a_dst[col], ad1 = a_dst[col + 1];
                ds0 += acc[mt][nt][0] * as0 + acc[mt][nt][1] * as1;
                dd0 += acc[mt][nt][0] * ad0 + acc[mt][nt][1] * ad1;
                ds1 += acc[mt][nt][2] * as0 + acc[mt][nt][3] * as1;
                dd1 += acc[mt][nt][2] * ad0 + acc[mt][nt][3] * ad1;
            }
        }
        if (doAl) {
#pragma unroll
            for (int o = 1; o < 4; o <<= 1) {
                ds0 += __shfl_xor_sync(0xffffffffu, ds0, o);
                dd0 += __shfl_xor_sync(0xffffffffu, dd0, o);
                ds1 += __shfl_xor_sync(0xffffffffu, ds1, o);
                dd1 += __shfl_xor_sync(0xffffffffu, dd1, o);
            }
            if ((lane & 3) == 0) {
                if (r0 < M) { atomicAdd(&g_als[r0], ds0); atomicAdd(&g_ald[r0], dd0); }
                if (r1 < M) { atomicAdd(&g_als[r1], ds1); atomicAdd(&g_ald[r1], dd1); }
            }
        }
    }
}

// ---- fp16 row gather/store helpers ----
__device__ __forceinline__ void h16_accum(const uint2* __restrict__ hp, int idx, float w,
                                          float4& a0, float4& a1) {
    uint2 u0 = hp[idx];
    uint2 u1 = hp[idx + 32];
    float2 f0 = __half22float2(*(__half2*)&u0.x);
    float2 f1 = __half22float2(*(__half2*)&u0.y);
    float2 f2 = __half22float2(*(__half2*)&u1.x);
    float2 f3 = __half22float2(*(__half2*)&u1.y);
    a0.x += w * f0.x; a0.y += w * f0.y; a0.z += w * f1.x; a0.w += w * f1.y;
    a1.x += w * f2.x; a1.y += w * f2.y; a1.z += w * f3.x; a1.w += w * f3.y;
}

__device__ __forceinline__ void h16_store(uint2* __restrict__ o, int node, int lane,
                                          const float4& a0, const float4& a1) {
    __half2 h01 = __floats2half2_rn(a0.x, a0.y);
    __half2 h23 = __floats2half2_rn(a0.z, a0.w);
    uint2 u0 = make_uint2(*(uint32_t*)&h01, *(uint32_t*)&h23);
    __half2 h45 = __floats2half2_rn(a1.x, a1.y);
    __half2 h67 = __floats2half2_rn(a1.z, a1.w);
    uint2 u1 = make_uint2(*(uint32_t*)&h45, *(uint32_t*)&h67);
    o[(size_t)node * 64 + lane] = u0;
    o[(size_t)node * 64 + lane + 32] = u1;
}

// ---------------- GCN aggregate (warp per dst node, fp16 in/out, unroll-4) ---------------
__global__ void gcn_agg_kernel(const uint2* __restrict__ h, const float* __restrict__ bias,
                               uint2* __restrict__ out) {
    int t = blockIdx.x * blockDim.x + threadIdx.x;
    int node = t >> 5;
    int lane = t & 31;
    if (node >= NN) return;
    int beg = g_rowptr[node], end = g_rowptr[node + 1];
    float di = g_dinv[node];
    float4 a0 = make_float4(0.f, 0.f, 0.f, 0.f);
    float4 a1 = make_float4(0.f, 0.f, 0.f, 0.f);
    h16_accum(h, node * 64 + lane, di * di, a0, a1);
    int e = beg;
    for (; e + 4 <= end; e += 4) {
        int s0 = g_col[e], s1 = g_col[e + 1], s2 = g_col[e + 2], s3 = g_col[e + 3];
        float w0 = g_dinv[s0] * di, w1 = g_dinv[s1] * di;
        float w2 = g_dinv[s2] * di, w3 = g_dinv[s3] * di;
        h16_accum(h, s0 * 64 + lane, w0, a0, a1);
        h16_accum(h, s1 * 64 + lane, w1, a0, a1);
        h16_accum(h, s2 * 64 + lane, w2, a0, a1);
        h16_accum(h, s3 * 64 + lane, w3, a0, a1);
    }
    for (; e < end; e++) {
        int s = g_col[e];
        h16_accum(h, s * 64 + lane, g_dinv[s] * di, a0, a1);
    }
    float4 b0 = ((const float4*)bias)[lane];
    float4 b1 = ((const float4*)bias)[lane + 32];
    a0.x = fmaxf(a0.x + b0.x, 0.f); a0.y = fmaxf(a0.y + b0.y, 0.f);
    a0.z = fmaxf(a0.z + b0.z, 0.f); a0.w = fmaxf(a0.w + b0.w, 0.f);
    a1.x = fmaxf(a1.x + b1.x, 0.f); a1.y = fmaxf(a1.y + b1.y, 0.f);
    a1.z = fmaxf(a1.z + b1.z, 0.f); a1.w = fmaxf(a1.w + b1.w, 0.f);
    h16_store(out, node, lane, a0, a1);
}

// ---------------- GAT aggregate with segment softmax (fp16 in/out, unroll-4) -------------
__global__ void gat_agg_kernel(const uint2* __restrict__ h, const float* __restrict__ bias,
                               uint2* __restrict__ out) {
    int t = blockIdx.x * blockDim.x + threadIdx.x;
    int node = t >> 5;
    int lane = t & 31;
    if (node >= NN) return;
    int beg = g_rowptr[node], end = g_rowptr[node + 1];
    float aldi = g_ald[node];
    float e_self = lrelu(g_als[node] + aldi);
    float m = e_self;
    for (int e = beg + lane; e < end; e += 32)
        m = fmaxf(m, lrelu(g_als[g_col[e]] + aldi));
    for (int o = 16; o; o >>= 1) m = fmaxf(m, __shfl_xor_sync(0xffffffffu, m, o));
    float z = __expf(e_self - m);
    float4 a0 = make_float4(0.f, 0.f, 0.f, 0.f);
    float4 a1 = make_float4(0.f, 0.f, 0.f, 0.f);
    h16_accum(h, node * 64 + lane, z, a0, a1);
    int e = beg;
    for (; e + 4 <= end; e += 4) {
        int s0 = g_col[e], s1 = g_col[e + 1], s2 = g_col[e + 2], s3 = g_col[e + 3];
        float w0 = __expf(lrelu(g_als[s0] + aldi) - m);
        float w1 = __expf(lrelu(g_als[s1] + aldi) - m);
        float w2 = __expf(lrelu(g_als[s2] + aldi) - m);
        float w3 = __expf(lrelu(g_als[s3] + aldi) - m);
        z += w0 + w1 + w2 + w3;
        h16_accum(h, s0 * 64 + lane, w0, a0, a1);
        h16_accum(h, s1 * 64 + lane, w1, a0, a1);
        h16_accum(h, s2 * 64 + lane, w2, a0, a1);
        h16_accum(h, s3 * 64 + lane, w3, a0, a1);
    }
    for (; e < end; e++) {
        int s = g_col[e];
        float w = __expf(lrelu(g_als[s] + aldi) - m);
        z += w;
        h16_accum(h, s * 64 + lane, w, a0, a1);
    }
    float inv = 1.0f / z;
    float4 b0 = ((const float4*)bias)[lane];
    float4 b1 = ((const float4*)bias)[lane + 32];
    a0.x = fmaxf(a0.x * inv + b0.x, 0.f); a0.y = fmaxf(a0.y * inv + b0.y, 0.f);
    a0.z = fmaxf(a0.z * inv + b0.z, 0.f); a0.w = fmaxf(a0.w * inv + b0.w, 0.f);
    a1.x = fmaxf(a1.x * inv + b1.x, 0.f); a1.y = fmaxf(a1.y * inv + b1.y, 0.f);
    a1.z = fmaxf(a1.z * inv + b1.z, 0.f); a1.w = fmaxf(a1.w * inv + b1.w, 0.f);
    h16_store(out, node, lane, a0, a1);
}

// ---------------- final GCN (L=40, fp16 h2) + log_softmax (unroll-2) ----------------
__global__ void gcn2_kernel(const __half* __restrict__ h2, const float* __restrict__ b2,
                            float* __restrict__ out) {
    int t = blockIdx.x * blockDim.x + threadIdx.x;
    int node = t >> 5;
    int lane = t & 31;
    if (node >= NN) return;
    int beg = g_rowptr[node], end = g_rowptr[node + 1];
    float di = g_dinv[node];
    float w = di * di;
    float a0 = w * __half2float(h2[(size_t)node * LL + lane]);
    float a1 = (lane < 8) ? w * __half2float(h2[(size_t)node * LL + lane + 32]) : 0.f;
    int e = beg;
    for (; e + 2 <= end; e += 2) {
        int s0 = g_col[e], s1 = g_col[e + 1];
        float w0 = g_dinv[s0] * di, w1 = g_dinv[s1] * di;
        float x0 = __half2float(h2[(size_t)s0 * LL + lane]);
        float x1 = __half2float(h2[(size_t)s1 * LL + lane]);
        a0 += w0 * x0 + w1 * x1;
        if (lane < 8) {
            a1 += w0 * __half2float(h2[(size_t)s0 * LL + lane + 32]) +
                  w1 * __half2float(h2[(size_t)s1 * LL + lane + 32]);
        }
    }
    if (e < end) {
        int s = g_col[e];
        float we = g_dinv[s] * di;
        a0 += we * __half2float(h2[(size_t)s * LL + lane]);
        if (lane < 8) a1 += we * __half2float(h2[(size_t)s * LL + lane + 32]);
    }
    float v0 = a0 + b2[lane];
    float v1 = (lane < 8) ? a1 + b2[lane + 32] : -INFINITY;
    float m = fmaxf(v0, v1);
    for (int o = 16; o; o >>= 1) m = fmaxf(m, __shfl_xor_sync(0xffffffffu, m, o));
    float z = expf(v0 - m) + ((lane < 8) ? expf(v1 - m) : 0.f);
    for (int o = 16; o; o >>= 1) z += __shfl_xor_sync(0xffffffffu, z, o);
    float ls = logf(z);
    out[(size_t)node * LL + lane] = v0 - m - ls;
    if (lane < 8) out[(size_t)node * LL + lane + 32] = v1 - m - ls;
}

// ---------------- launch ----------------
extern "C" void kernel_launch(void* const* d_in, const int* in_sizes, int n_in,
                              void* d_out, int out_size) {
    const float* x   = (const float*)d_in[0];
    const void*  ei  = d_in[1];
    const float* W1  = (const float*)d_in[2];
    const float* b1  = (const float*)d_in[3];
    const float* Wg  = (const float*)d_in[4];
    const float* a_s = (const float*)d_in[5];
    const float* a_d = (const float*)d_in[6];
    const float* bg  = (const float*)d_in[7];
    const float* W2  = (const float*)d_in[8];
    const float* b2  = (const float*)d_in[9];
    float* out = (float*)d_out;

    uint2 *pH16, *pX16;
    __half* pH2;
    __half *pWhi, *pWlo;
    cudaGetSymbolAddress((void**)&pH16, g_h16);
    cudaGetSymbolAddress((void**)&pX16, g_x16);
    cudaGetSymbolAddress((void**)&pH2, g_h2);
    cudaGetSymbolAddress((void**)&pWhi, g_Whi4);
    cudaGetSymbolAddress((void**)&pWlo, g_Wlo4);

    cudaFuncSetAttribute(mma_gemm_kernel, cudaFuncAttributeMaxDynamicSharedMemorySize, MMA_SMEM);

    const int tpb = 256;
    dim3 gMMA(2, (NN + 127) / 128);
    dim3 gMMA2(1, (NN + 127) / 128);
    int warpGrid = (NN * 32 + tpb - 1) / tpb;
    int zg = (NN + tpb - 1) / tpb;

    // side stream + fork/join events (created/destroyed every call; capture-compatible)
    cudaStream_t s2;
    cudaStreamCreateWithFlags(&s2, cudaStreamNonBlocking);
    cudaEvent_t evFork, evCsr, evG1, evW, evG3;
    cudaEventCreateWithFlags(&evFork, cudaEventDisableTiming);
    cudaEventCreateWithFlags(&evCsr, cudaEventDisableTiming);
    cudaEventCreateWithFlags(&evG1, cudaEventDisableTiming);
    cudaEventCreateWithFlags(&evW, cudaEventDisableTiming);
    cudaEventCreateWithFlags(&evG3, cudaEventDisableTiming);

    // ---- fork: CSR build on s2, concurrent with stats/std16/GEMM-1 on main ----
    cudaEventRecord(evFork, 0);
    cudaStreamWaitEvent(s2, evFork, 0);
    zero_kernel<<<zg, tpb, 0, s2>>>();
    detect_kernel<<<1, 32, 0, s2>>>((const unsigned int*)ei);
    convert_kernel<<<(EE + tpb - 1) / tpb, tpb, 0, s2>>>(ei);
    dinv_kernel<<<zg, tpb, 0, s2>>>();
    scan_kernel<<<1, 1024, 0, s2>>>();
    fill_kernel<<<(EE + tpb - 1) / tpb, tpb, 0, s2>>>();
    cudaEventRecord(evCsr, s2);

    // ---- main: GEMM-1 path ----
    splitW_kernel<<<(256 * 256) / tpb, tpb>>>(W1);   // also zeroes colsum/colsumsq
    stats_kernel<<<296, 256>>>(x);
    finalize_kernel<<<1, 256>>>();
    std16_kernel<<<(NN * 64 + tpb - 1) / tpb, tpb>>>(x);
    mma_gemm_kernel<<<gMMA, 256, MMA_SMEM>>>((const __half*)pX16, pWhi, pWlo,
                                             (__half*)pH16, NN, 256, 256, 0, a_s, a_d);
    cudaEventRecord(evG1, 0);

    // fork: splitW(Wg)+zero_al on s2 overlapping gcn_agg on main
    cudaStreamWaitEvent(s2, evG1, 0);
    splitW_kernel<<<(256 * 256) / tpb, tpb, 0, s2>>>(Wg);
    zero_al_kernel<<<zg, tpb, 0, s2>>>();
    cudaEventRecord(evW, s2);

    // main: join CSR, then GCN aggregate (+ReLU) -> x16
    cudaStreamWaitEvent(0, evCsr, 0);
    gcn_agg_kernel<<<warpGrid, tpb>>>(pH16, b1, pX16);

    // GAT layer 1 (+ReLU)
    cudaStreamWaitEvent(0, evW, 0);
    mma_gemm_kernel<<<gMMA, 256, MMA_SMEM>>>((const __half*)pX16, pWhi, pWlo,
                                             (__half*)pH16, NN, 256, 256, 1, a_s, a_d);
    gat_agg_kernel<<<warpGrid, tpb>>>(pH16, bg, pX16);

    // GAT layer 2 (+ReLU) — zero_al must follow gat_agg1 (it reads g_als)
    zero_al_kernel<<<zg, tpb>>>();
    mma_gemm_kernel<<<gMMA, 256, MMA_SMEM>>>((const __half*)pX16, pWhi, pWlo,
                                             (__half*)pH16, NN, 256, 256, 1, a_s, a_d);
    cudaEventRecord(evG3, 0);

    // fork: splitW2(W2) on s2 overlapping gat_agg2 on main
    cudaStreamWaitEvent(s2, evG3, 0);
    splitW2_kernel<<<(128 * 256) / tpb, tpb, 0, s2>>>(W2);
    cudaEventRecord(evW, s2);

    gat_agg_kernel<<<warpGrid, tpb>>>(pH16, bg, pX16);

    // GCN layer 2 (tensor-core, N padded to 128) + log_softmax
    cudaStreamWaitEvent(0, evW, 0);
    mma_gemm_kernel<<<gMMA2, 256, MMA_SMEM>>>((const __half*)pX16, pWhi, pWlo,
                                              pH2, NN, LL, LL, 0, a_s, a_d);
    gcn2_kernel<<<warpGrid, tpb>>>(pH2, b2, out);

    cudaEventDestroy(evFork);
    cudaEventDestroy(evCsr);
    cudaEventDestroy(evG1);
    cudaEventDestroy(evW);
    cudaEventDestroy(evG3);
    cudaStreamDestroy(s2);
}

// round 10
// speedup vs baseline: 3.0414x; 1.2364x over previous
#include <cuda_runtime.h>
#include <cuda_fp16.h>
#include <math.h>
#include <stdint.h>

#define NN 50000
#define EE 800000
#define DD 256
#define HH 256
#define LL 40

// ---------------- scratch (device globals; no allocation allowed) ----------------
__device__ uint2  g_h16[(size_t)NN * 64];   // 25.6 MB (GEMM outputs, half2-packed)
__device__ uint2  g_x16[(size_t)NN * 64];   // 25.6 MB (agg outputs / std input, half2-packed)
__device__ __half g_h2[(size_t)NN * LL];    // 4 MB (final-layer logits, fp16, stride 40)
__device__ int   g_src[EE];
__device__ int   g_dst[EE];
__device__ int   g_col[EE];
__device__ int   g_counts[NN];
__device__ int   g_rowptr[NN + 1];
__device__ int   g_cursor[NN];
__device__ float g_dinv[NN];
__device__ float g_als[NN];
__device__ float g_ald[NN];
__device__ float g_als2[NN];
__device__ float g_ald2[NN];
__device__ float g_colsum[DD];
__device__ float g_colsumsq[DD];
__device__ float g_mean[DD];
__device__ float g_istd[DD];
__device__ int   g_flag;  // 1 = edge_index is int64, 0 = int32
__device__ uint4 g_Whi4[(256 * 256) / 8];   // fp16 [n][k] transposed weight plane

__device__ __forceinline__ float lrelu(float v) { return v > 0.f ? v : 0.2f * v; }
__device__ __forceinline__ uint32_t swz128(uint32_t o) { return o ^ ((o >> 3) & 0x70); }

__device__ __forceinline__ uint32_t smem_u32(const void* p) {
    uint32_t a;
    asm("{ .reg .u64 t; cvta.to.shared.u64 t, %1; cvt.u32.u64 %0, t; }" : "=r"(a) : "l"(p));
    return a;
}

#define LDSM_X4(r0, r1, r2, r3, addr)                                               \
    asm volatile("ldmatrix.sync.aligned.m8n8.x4.shared.b16 {%0,%1,%2,%3}, [%4];"    \
                 : "=r"(r0), "=r"(r1), "=r"(r2), "=r"(r3) : "r"(addr))

#define MMAF16(d, a, b)                                                             \
    asm volatile("mma.sync.aligned.m16n8k16.row.col.f32.f16.f16.f32 "               \
                 "{%0,%1,%2,%3}, {%4,%5,%6,%7}, {%8,%9}, {%0,%1,%2,%3};"            \
                 : "+f"((d)[0]), "+f"((d)[1]), "+f"((d)[2]), "+f"((d)[3])           \
                 : "r"((a)[0]), "r"((a)[1]), "r"((a)[2]), "r"((a)[3]),              \
                   "r"((b)[0]), "r"((b)[1]))

#define CP_ASYNC16(dst, src, sz)                                                    \
    asm volatile("cp.async.cg.shared.global [%0], [%1], 16, %2;"                    \
                 :: "r"(dst), "l"(src), "r"(sz))
#define CP_COMMIT()  asm volatile("cp.async.commit_group;" ::: "memory")
#define CP_WAIT1()   asm volatile("cp.async.wait_group 1;" ::: "memory")
#define CP_WAIT0()   asm volatile("cp.async.wait_group 0;" ::: "memory")

// ---------------- setup kernels ----------------
__global__ void zero_kernel() {
    int i = blockIdx.x * blockDim.x + threadIdx.x;
    if (i < NN) g_counts[i] = 0;
}

__global__ void zero_al_kernel() {
    int i = blockIdx.x * blockDim.x + threadIdx.x;
    if (i < NN) { g_als[i] = 0.f; g_ald[i] = 0.f; g_als2[i] = 0.f; g_ald2[i] = 0.f; }
}

__global__ void detect_kernel(const unsigned int* __restrict__ p) {
    if (blockIdx.x == 0 && threadIdx.x == 0) {
        int is64 = 1;
        for (int i = 0; i < 64; i++)
            if (p[2 * i + 1] != 0u) { is64 = 0; break; }
        g_flag = is64;
    }
}

__global__ void convert_kernel(const void* __restrict__ ei) {
    int e = blockIdx.x * blockDim.x + threadIdx.x;
    if (e >= EE) return;
    int s, d;
    if (g_flag) {
        const long long* p = (const long long*)ei;
        s = (int)p[e]; d = (int)p[EE + e];
    } else {
        const int* p = (const int*)ei;
        s = p[e]; d = p[EE + e];
    }
    g_src[e] = s;
    g_dst[e] = d;
    atomicAdd(&g_counts[d], 1);
}

__global__ void stats_kernel(const float* __restrict__ x) {
    __shared__ float4 ss[256], ss2[256];
    int cg = threadIdx.x & 63;
    int rl = threadIdx.x >> 6;
    int g4 = gridDim.x * 4;
    float4 s = make_float4(0.f, 0.f, 0.f, 0.f);
    float4 s2 = make_float4(0.f, 0.f, 0.f, 0.f);
    for (int r = blockIdx.x * 4 + rl; r < NN; r += g4 * 4) {
        float4 v[4];
#pragma unroll
        for (int j = 0; j < 4; j++) {
            int rr = r + j * g4;
            v[j] = (rr < NN) ? ((const float4*)x)[(size_t)rr * 64 + cg]
                             : make_float4(0.f, 0.f, 0.f, 0.f);
        }
#pragma unroll
        for (int j = 0; j < 4; j++) {
            s.x += v[j].x; s.y += v[j].y; s.z += v[j].z; s.w += v[j].w;
            s2.x += v[j].x * v[j].x; s2.y += v[j].y * v[j].y;
            s2.z += v[j].z * v[j].z; s2.w += v[j].w * v[j].w;
        }
    }
    ss[threadIdx.x] = s; ss2[threadIdx.x] = s2;
    __syncthreads();
    if (threadIdx.x < 64) {
#pragma unroll
        for (int k = 1; k < 4; k++) {
            float4 t = ss[threadIdx.x + 64 * k], t2 = ss2[threadIdx.x + 64 * k];
            s.x += t.x; s.y += t.y; s.z += t.z; s.w += t.w;
            s2.x += t2.x; s2.y += t2.y; s2.z += t2.z; s2.w += t2.w;
        }
        int c = threadIdx.x * 4;
        atomicAdd(&g_colsum[c + 0], s.x); atomicAdd(&g_colsum[c + 1], s.y);
        atomicAdd(&g_colsum[c + 2], s.z); atomicAdd(&g_colsum[c + 3], s.w);
        atomicAdd(&g_colsumsq[c + 0], s2.x); atomicAdd(&g_colsumsq[c + 1], s2.y);
        atomicAdd(&g_colsumsq[c + 2], s2.z); atomicAdd(&g_colsumsq[c + 3], s2.w);
    }
}

__global__ void finalize_kernel() {
    int c = threadIdx.x;
    float mean = g_colsum[c] / (float)NN;
    float var = (g_colsumsq[c] - (float)NN * mean * mean) / (float)(NN - 1);
    g_mean[c] = mean;
    g_istd[c] = rsqrtf(var);
}

// x fp32 -> standardized fp16 plane
__global__ void std16_kernel(const float* __restrict__ x) {
    int idx = blockIdx.x * blockDim.x + threadIdx.x;
    if (idx >= NN * 64) return;
    int c4 = (idx & 63) * 4;
    float4 v = ((const float4*)x)[idx];
    v.x = (v.x - g_mean[c4 + 0]) * g_istd[c4 + 0];
    v.y = (v.y - g_mean[c4 + 1]) * g_istd[c4 + 1];
    v.z = (v.z - g_mean[c4 + 2]) * g_istd[c4 + 2];
    v.w = (v.w - g_mean[c4 + 3]) * g_istd[c4 + 3];
    __half2 h01 = __floats2half2_rn(v.x, v.y);
    __half2 h23 = __floats2half2_rn(v.z, v.w);
    g_x16[idx] = make_uint2(*(uint32_t*)&h01, *(uint32_t*)&h23);
}

__global__ void dinv_kernel() {
    int i = blockIdx.x * blockDim.x + threadIdx.x;
    if (i < NN) g_dinv[i] = rsqrtf((float)(g_counts[i] + 1));
}

__global__ void scan_kernel() {
    __shared__ int warpsum[32];
    __shared__ int s_off;
    int tid = threadIdx.x;
    int lane = tid & 31, wid = tid >> 5;
    if (tid == 0) s_off = 0;
    __syncthreads();
    for (int base = 0; base < NN; base += 1024) {
        int i = base + tid;
        int v = (i < NN) ? g_counts[i] : 0;
        int xs = v;
#pragma unroll
        for (int d = 1; d < 32; d <<= 1) {
            int t = __shfl_up_sync(0xffffffffu, xs, d);
            if (lane >= d) xs += t;
        }
        if (lane == 31) warpsum[wid] = xs;
        __syncthreads();
        if (wid == 0) {
            int w = warpsum[lane];
#pragma unroll
            for (int d = 1; d < 32; d <<= 1) {
                int t = __shfl_up_sync(0xffffffffu, w, d);
                if (lane >= d) w += t;
            }
            warpsum[lane] = w;
        }
        __syncthreads();
        int excl = xs - v + (wid ? warpsum[wid - 1] : 0);
        int off = s_off;
        if (i < NN) { g_rowptr[i] = off + excl; g_cursor[i] = off + excl; }
        __syncthreads();
        if (tid == 1023) s_off = off + excl + v;
        __syncthreads();
    }
    if (tid == 0) g_rowptr[NN] = s_off;
}

__global__ void fill_kernel() {
    int e = blockIdx.x * blockDim.x + threadIdx.x;
    if (e >= EE) return;
    int d = g_dst[e];
    int p = atomicAdd(&g_cursor[d], 1);
    g_col[p] = g_src[e];
}

// ---------------- weight transpose -> fp16 plane (zeroes stats accumulators) --------------
__global__ void splitW_kernel(const float* __restrict__ W) {
    int idx = blockIdx.x * blockDim.x + threadIdx.x;
    if (idx < 256) { g_colsum[idx] = 0.f; g_colsumsq[idx] = 0.f; }
    if (idx >= 256 * 256) return;
    int k = idx >> 8;
    int n = idx & 255;
    ((__half*)g_Whi4)[n * 256 + k] = __float2half_rn(W[idx]);
}

// W2 [256,40] -> plane rows 0..127 (rows 40..127 zero), [n][k] fp16
__global__ void splitW2_kernel(const float* __restrict__ W2) {
    int idx = blockIdx.x * blockDim.x + threadIdx.x;   // 128*256
    if (idx >= 128 * 256) return;
    int n = idx >> 8;
    int k = idx & 255;
    float v = (n < LL) ? W2[k * LL + n] : 0.f;
    ((__half*)g_Whi4)[n * 256 + k] = __float2half_rn(v);
}

// ---------------- mma.sync fp16 GEMM with cp.async double-buffered pipeline --------------
// Tile 128x128, 8 warps, single weight plane. Per buffer: A 16KB | B 16KB. 64KB total.
#define CB_A   0
#define CB_B   16384
#define CB_SZ  32768
#define MMA_SMEM (2 * CB_SZ)

__global__ void __launch_bounds__(256, 2) mma_gemm_kernel(
    const __half* __restrict__ A16, const __half* __restrict__ B_g,
    __half* __restrict__ C16, int M, int ostride, int ncols,
    int doAl, float* __restrict__ alsP, float* __restrict__ aldP,
    const float* __restrict__ a_src, const float* __restrict__ a_dst) {
    extern __shared__ char smem[];
    uint32_t sb = smem_u32(smem);
    int tid = threadIdx.x;
    int wid = tid >> 5, lane = tid & 31;
    int bm = blockIdx.y * 128;
    int bn = blockIdx.x * 128;
    int wm = (wid >> 1) * 32;
    int wn = (wid & 1) * 64;

    float acc[2][8][4];
#pragma unroll
    for (int mt = 0; mt < 2; mt++)
#pragma unroll
        for (int nt = 0; nt < 8; nt++)
#pragma unroll
            for (int r = 0; r < 4; r++) acc[mt][nt][r] = 0.f;

    uint32_t b_row[4], b_cb;
#pragma unroll
    for (int ntp = 0; ntp < 4; ntp++)
        b_row[ntp] = (uint32_t)(wn + ntp * 16 + (lane & 7) + ((lane >> 4) << 3));
    b_cb = (uint32_t)(((lane >> 3) & 1) * 16);

#define STAGE(ch, buf)                                                                  \
    do {                                                                                \
        int _k0 = (ch) * 64;                                                            \
        uint32_t _base = sb + (buf) * CB_SZ;                                            \
        _Pragma("unroll")                                                               \
        for (int _i = 0; _i < 4; _i++) {                                                \
            int _lin = tid + _i * 256;                                                  \
            int _row = _lin >> 3, _sg = _lin & 7;                                       \
            uint32_t _so = swz128((uint32_t)(_row * 128 + _sg * 16));                   \
            int _gr = bm + _row;                                                        \
            const __half* _sa = A16 + (size_t)(_gr < M ? _gr : M - 1) * 256 + _k0 + _sg * 8; \
            CP_ASYNC16(_base + CB_A + _so, _sa, (_gr < M) ? 16 : 0);                    \
            const __half* _sb2 = B_g + (size_t)(bn + _row) * 256 + _k0 + _sg * 8;       \
            CP_ASYNC16(_base + CB_B + _so, _sb2, 16);                                   \
        }                                                                               \
        CP_COMMIT();                                                                    \
    } while (0)

    STAGE(0, 0);
    for (int ch = 0; ch < 4; ch++) {
        int buf = ch & 1;
        if (ch < 3) { STAGE(ch + 1, buf ^ 1); CP_WAIT1(); }
        else        { CP_WAIT0(); }
        __syncthreads();
        uint32_t base = sb + buf * CB_SZ;
#pragma unroll
        for (int ks = 0; ks < 4; ks++) {
            uint32_t kb = (uint32_t)(ks * 32);
            uint32_t a[2][4];
#pragma unroll
            for (int mt = 0; mt < 2; mt++) {
                uint32_t row = (uint32_t)(wm + mt * 16 + (lane & 15));
                uint32_t cb = (uint32_t)((lane >> 4) * 16) + kb;
                uint32_t ad = base + CB_A + swz128(row * 128 + cb);
                LDSM_X4(a[mt][0], a[mt][1], a[mt][2], a[mt][3], ad);
            }
            uint32_t bh[8][2];
#pragma unroll
            for (int ntp = 0; ntp < 4; ntp++) {
                uint32_t bo = swz128(b_row[ntp] * 128 + b_cb + kb);
                LDSM_X4(bh[2 * ntp][0], bh[2 * ntp][1], bh[2 * ntp + 1][0],
                        bh[2 * ntp + 1][1], base + CB_B + bo);
            }
#pragma unroll
            for (int mt = 0; mt < 2; mt++)
#pragma unroll
                for (int nt = 0; nt < 8; nt++)
                    MMAF16(acc[mt][nt], a[mt], bh[nt]);
        }
        __syncthreads();
    }
#undef STAGE

    // ---- epilogue: fp16 store (guarded by ncols) + optional fused attention logits ----
#pragma unroll
    for (int mt = 0; mt < 2; mt++) {
        int r0 = bm + wm + mt * 16 + (lane >> 2);
        int r1 = r0 + 8;
        float ds0 = 0.f, dd0 = 0.f, ds1 = 0.f, dd1 = 0.f;
#pragma unroll
        for (int nt = 0; nt < 8; nt++) {
            int col = bn + wn + nt * 8 + (lane & 3) * 2;
            if (col < ncols) {
                if (r0 < M) *(__half2*)(C16 + (size_t)r0 * ostride + col) =
                    __floats2half2_rn(acc[mt][nt][0], acc[mt][nt][1]);
                if (r1 < M) *(__half2*)(C16 + (size_t)r1 * ostride + col) =
                    __floats2half2_rn(acc[mt][nt][2], acc[mt][nt][3]);
            }
            if (doAl) {
                float as0 = a_src[col], as1 = a_src[col + 1];
                float ad0 = a_dst[col], ad1 = a_dst[col + 1];
                ds0 += acc[mt][nt][0] * as0 + acc[mt][nt][1] * as1;
                dd0 += acc[mt][nt][0] * ad0 + acc[mt][nt][1] * ad1;
                ds1 += acc[mt][nt][2] * as0 + acc[mt][nt][3] * as1;
                dd1 += acc[mt][nt][2] * ad0 + acc[mt][nt][3] * ad1;
            }
        }
        if (doAl) {
#pragma unroll
            for (int o = 1; o < 4; o <<= 1) {
                ds0 += __shfl_xor_sync(0xffffffffu, ds0, o);
                dd0 += __shfl_xor_sync(0xffffffffu, dd0, o);
                ds1 += __shfl_xor_sync(0xffffffffu, ds1, o);
                dd1 += __shfl_xor_sync(0xffffffffu, dd1, o);
            }
            if ((lane & 3) == 0) {
                if (r0 < M) { atomicAdd(&alsP[r0], ds0); atomicAdd(&aldP[r0], dd0); }
                if (r1 < M) { atomicAdd(&alsP[r1], ds1); atomicAdd(&aldP[r1], dd1); }
            }
        }
    }
}

// ---- fp16 row gather/store helpers ----
__device__ __forceinline__ void h16_accum(const uint2* __restrict__ hp, int idx, float w,
                                          float4& a0, float4& a1) {
    uint2 u0 = hp[idx];
    uint2 u1 = hp[idx + 32];
    float2 f0 = __half22float2(*(__half2*)&u0.x);
    float2 f1 = __half22float2(*(__half2*)&u0.y);
    float2 f2 = __half22float2(*(__half2*)&u1.x);
    float2 f3 = __half22float2(*(__half2*)&u1.y);
    a0.x += w * f0.x; a0.y += w * f0.y; a0.z += w * f1.x; a0.w += w * f1.y;
    a1.x += w * f2.x; a1.y += w * f2.y; a1.z += w * f3.x; a1.w += w * f3.y;
}

__device__ __forceinline__ void h16_store(uint2* __restrict__ o, int node, int lane,
                                          const float4& a0, const float4& a1) {
    __half2 h01 = __floats2half2_rn(a0.x, a0.y);
    __half2 h23 = __floats2half2_rn(a0.z, a0.w);
    uint2 u0 = make_uint2(*(uint32_t*)&h01, *(uint32_t*)&h23);
    __half2 h45 = __floats2half2_rn(a1.x, a1.y);
    __half2 h67 = __floats2half2_rn(a1.z, a1.w);
    uint2 u1 = make_uint2(*(uint32_t*)&h45, *(uint32_t*)&h67);
    o[(size_t)node * 64 + lane] = u0;
    o[(size_t)node * 64 + lane + 32] = u1;
}

// ---------------- GCN aggregate (warp per dst node, fp16 in/out, unroll-4) ---------------
__global__ void gcn_agg_kernel(const uint2* __restrict__ h, const float* __restrict__ bias,
                               uint2* __restrict__ out) {
    int t = blockIdx.x * blockDim.x + threadIdx.x;
    int node = t >> 5;
    int lane = t & 31;
    if (node >= NN) return;
    int beg = g_rowptr[node], end = g_rowptr[node + 1];
    float di = g_dinv[node];
    float4 a0 = make_float4(0.f, 0.f, 0.f, 0.f);
    float4 a1 = make_float4(0.f, 0.f, 0.f, 0.f);
    h16_accum(h, node * 64 + lane, di * di, a0, a1);
    int e = beg;
    for (; e + 4 <= end; e += 4) {
        int s0 = g_col[e], s1 = g_col[e + 1], s2 = g_col[e + 2], s3 = g_col[e + 3];
        float w0 = g_dinv[s0] * di, w1 = g_dinv[s1] * di;
        float w2 = g_dinv[s2] * di, w3 = g_dinv[s3] * di;
        h16_accum(h, s0 * 64 + lane, w0, a0, a1);
        h16_accum(h, s1 * 64 + lane, w1, a0, a1);
        h16_accum(h, s2 * 64 + lane, w2, a0, a1);
        h16_accum(h, s3 * 64 + lane, w3, a0, a1);
    }
    for (; e < end; e++) {
        int s = g_col[e];
        h16_accum(h, s * 64 + lane, g_dinv[s] * di, a0, a1);
    }
    float4 b0 = ((const float4*)bias)[lane];
    float4 b1 = ((const float4*)bias)[lane + 32];
    a0.x = fmaxf(a0.x + b0.x, 0.f); a0.y = fmaxf(a0.y + b0.y, 0.f);
    a0.z = fmaxf(a0.z + b0.z, 0.f); a0.w = fmaxf(a0.w + b0.w, 0.f);
    a1.x = fmaxf(a1.x + b1.x, 0.f); a1.y = fmaxf(a1.y + b1.y, 0.f);
    a1.z = fmaxf(a1.z + b1.z, 0.f); a1.w = fmaxf(a1.w + b1.w, 0.f);
    h16_store(out, node, lane, a0, a1);
}

// ---------------- GAT aggregate with segment softmax (fp16 in/out, unroll-4) -------------
__global__ void gat_agg_kernel(const uint2* __restrict__ h, const float* __restrict__ bias,
                               uint2* __restrict__ out,
                               const float* __restrict__ alsP, const float* __restrict__ aldP) {
    int t = blockIdx.x * blockDim.x + threadIdx.x;
    int node = t >> 5;
    int lane = t & 31;
    if (node >= NN) return;
    int beg = g_rowptr[node], end = g_rowptr[node + 1];
    float aldi = aldP[node];
    float e_self = lrelu(alsP[node] + aldi);
    float m = e_self;
    for (int e = beg + lane; e < end; e += 32)
        m = fmaxf(m, lrelu(alsP[g_col[e]] + aldi));
    for (int o = 16; o; o >>= 1) m = fmaxf(m, __shfl_xor_sync(0xffffffffu, m, o));
    float z = __expf(e_self - m);
    float4 a0 = make_float4(0.f, 0.f, 0.f, 0.f);
    float4 a1 = make_float4(0.f, 0.f, 0.f, 0.f);
    h16_accum(h, node * 64 + lane, z, a0, a1);
    int e = beg;
    for (; e + 4 <= end; e += 4) {
        int s0 = g_col[e], s1 = g_col[e + 1], s2 = g_col[e + 2], s3 = g_col[e + 3];
        float w0 = __expf(lrelu(alsP[s0] + aldi) - m);
        float w1 = __expf(lrelu(alsP[s1] + aldi) - m);
        float w2 = __expf(lrelu(alsP[s2] + aldi) - m);
        float w3 = __expf(lrelu(alsP[s3] + aldi) - m);
        z += w0 + w1 + w2 + w3;
        h16_accum(h, s0 * 64 + lane, w0, a0, a1);
        h16_accum(h, s1 * 64 + lane, w1, a0, a1);
        h16_accum(h, s2 * 64 + lane, w2, a0, a1);
        h16_accum(h, s3 * 64 + lane, w3, a0, a1);
    }
    for (; e < end; e++) {
        int s = g_col[e];
        float w = __expf(lrelu(alsP[s] + aldi) - m);
        z += w;
        h16_accum(h, s * 64 + lane, w, a0, a1);
    }
    float inv = 1.0f / z;
    float4 b0 = ((const float4*)bias)[lane];
    float4 b1 = ((const float4*)bias)[lane + 32];
    a0.x = fmaxf(a0.x * inv + b0.x, 0.f); a0.y = fmaxf(a0.y * inv + b0.y, 0.f);
    a0.z = fmaxf(a0.z * inv + b0.z, 0.f); a0.w = fmaxf(a0.w * inv + b0.w, 0.f);
    a1.x = fmaxf(a1.x * inv + b1.x, 0.f); a1.y = fmaxf(a1.y * inv + b1.y, 0.f);
    a1.w = fmaxf(a1.w * inv + b1.w, 0.f); a1.z = fmaxf(a1.z * inv + b1.z, 0.f);
    h16_store(out, node, lane, a0, a1);
}

// ---------------- final GCN (L=40, fp16 h2) + log_softmax (unroll-2) ----------------
__global__ void gcn2_kernel(const __half* __restrict__ h2, const float* __restrict__ b2,
                            float* __restrict__ out) {
    int t = blockIdx.x * blockDim.x + threadIdx.x;
    int node = t >> 5;
    int lane = t & 31;
    if (node >= NN) return;
    int beg = g_rowptr[node], end = g_rowptr[node + 1];
    float di = g_dinv[node];
    float w = di * di;
    float a0 = w * __half2float(h2[(size_t)node * LL + lane]);
    float a1 = (lane < 8) ? w * __half2float(h2[(size_t)node * LL + lane + 32]) : 0.f;
    int e = beg;
    for (; e + 2 <= end; e += 2) {
        int s0 = g_col[e], s1 = g_col[e + 1];
        float w0 = g_dinv[s0] * di, w1 = g_dinv[s1] * di;
        float x0 = __half2float(h2[(size_t)s0 * LL + lane]);
        float x1 = __half2float(h2[(size_t)s1 * LL + lane]);
        a0 += w0 * x0 + w1 * x1;
        if (lane < 8) {
            a1 += w0 * __half2float(h2[(size_t)s0 * LL + lane + 32]) +
                  w1 * __half2float(h2[(size_t)s1 * LL + lane + 32]);
        }
    }
    if (e < end) {
        int s = g_col[e];
        float we = g_dinv[s] * di;
        a0 += we * __half2float(h2[(size_t)s * LL + lane]);
        if (lane < 8) a1 += we * __half2float(h2[(size_t)s * LL + lane + 32]);
    }
    float v0 = a0 + b2[lane];
    float v1 = (lane < 8) ? a1 + b2[lane + 32] : -INFINITY;
    float m = fmaxf(v0, v1);
    for (int o = 16; o; o >>= 1) m = fmaxf(m, __shfl_xor_sync(0xffffffffu, m, o));
    float z = expf(v0 - m) + ((lane < 8) ? expf(v1 - m) : 0.f);
    for (int o = 16; o; o >>= 1) z += __shfl_xor_sync(0xffffffffu, z, o);
    float ls = logf(z);
    out[(size_t)node * LL + lane] = v0 - m - ls;
    if (lane < 8) out[(size_t)node * LL + lane + 32] = v1 - m - ls;
}

// ---------------- launch ----------------
extern "C" void kernel_launch(void* const* d_in, const int* in_sizes, int n_in,
                              void* d_out, int out_size) {
    const float* x   = (const float*)d_in[0];
    const void*  ei  = d_in[1];
    const float* W1  = (const float*)d_in[2];
    const float* b1  = (const float*)d_in[3];
    const float* Wg  = (const float*)d_in[4];
    const float* a_s = (const float*)d_in[5];
    const float* a_d = (const float*)d_in[6];
    const float* bg  = (const float*)d_in[7];
    const float* W2  = (const float*)d_in[8];
    const float* b2  = (const float*)d_in[9];
    float* out = (float*)d_out;

    uint2 *pH16, *pX16;
    __half* pH2;
    __half* pWhi;
    float *pAls, *pAld, *pAls2, *pAld2;
    cudaGetSymbolAddress((void**)&pH16, g_h16);
    cudaGetSymbolAddress((void**)&pX16, g_x16);
    cudaGetSymbolAddress((void**)&pH2, g_h2);
    cudaGetSymbolAddress((void**)&pWhi, g_Whi4);
    cudaGetSymbolAddress((void**)&pAls, g_als);
    cudaGetSymbolAddress((void**)&pAld, g_ald);
    cudaGetSymbolAddress((void**)&pAls2, g_als2);
    cudaGetSymbolAddress((void**)&pAld2, g_ald2);

    cudaFuncSetAttribute(mma_gemm_kernel, cudaFuncAttributeMaxDynamicSharedMemorySize, MMA_SMEM);

    const int tpb = 256;
    dim3 gMMA(2, (NN + 127) / 128);
    dim3 gMMA2(1, (NN + 127) / 128);
    int warpGrid = (NN * 32 + tpb - 1) / tpb;
    int zg = (NN + tpb - 1) / tpb;

    // side stream + fork/join events (capture-compatible fork/join pattern)
    cudaStream_t s2;
    cudaStreamCreateWithFlags(&s2, cudaStreamNonBlocking);
    cudaEvent_t evFork, evCsr, evG1, evW, evG3;
    cudaEventCreateWithFlags(&evFork, cudaEventDisableTiming);
    cudaEventCreateWithFlags(&evCsr, cudaEventDisableTiming);
    cudaEventCreateWithFlags(&evG1, cudaEventDisableTiming);
    cudaEventCreateWithFlags(&evW, cudaEventDisableTiming);
    cudaEventCreateWithFlags(&evG3, cudaEventDisableTiming);

    // ---- fork: CSR build on s2, concurrent with stats/std16/GEMM-1 on main ----
    cudaEventRecord(evFork, 0);
    cudaStreamWaitEvent(s2, evFork, 0);
    zero_kernel<<<zg, tpb, 0, s2>>>();
    detect_kernel<<<1, 32, 0, s2>>>((const unsigned int*)ei);
    convert_kernel<<<(EE + tpb - 1) / tpb, tpb, 0, s2>>>(ei);
    dinv_kernel<<<zg, tpb, 0, s2>>>();
    scan_kernel<<<1, 1024, 0, s2>>>();
    fill_kernel<<<(EE + tpb - 1) / tpb, tpb, 0, s2>>>();
    cudaEventRecord(evCsr, s2);

    // ---- main: GEMM-1 path ----
    splitW_kernel<<<(256 * 256) / tpb, tpb>>>(W1);   // also zeroes colsum/colsumsq
    stats_kernel<<<296, 256>>>(x);
    finalize_kernel<<<1, 256>>>();
    std16_kernel<<<(NN * 64 + tpb - 1) / tpb, tpb>>>(x);
    mma_gemm_kernel<<<gMMA, 256, MMA_SMEM>>>((const __half*)pX16, pWhi,
                                             (__half*)pH16, NN, 256, 256, 0,
                                             pAls, pAld, a_s, a_d);
    cudaEventRecord(evG1, 0);

    // fork: splitW(Wg) + zero both al-buffer pairs on s2, overlapping gcn_agg on main
    cudaStreamWaitEvent(s2, evG1, 0);
    splitW_kernel<<<(256 * 256) / tpb, tpb, 0, s2>>>(Wg);
    zero_al_kernel<<<zg, tpb, 0, s2>>>();
    cudaEventRecord(evW, s2);

    // main: join CSR, then GCN aggregate (+ReLU) -> x16
    cudaStreamWaitEvent(0, evCsr, 0);
    gcn_agg_kernel<<<warpGrid, tpb>>>(pH16, b1, pX16);

    // GAT layer 1 (+ReLU): logits -> als/ald
    cudaStreamWaitEvent(0, evW, 0);
    mma_gemm_kernel<<<gMMA, 256, MMA_SMEM>>>((const __half*)pX16, pWhi,
                                             (__half*)pH16, NN, 256, 256, 1,
                                             pAls, pAld, a_s, a_d);
    gat_agg_kernel<<<warpGrid, tpb>>>(pH16, bg, pX16, pAls, pAld);

    // GAT layer 2 (+ReLU): logits -> als2/ald2 (pre-zeroed on s2)
    mma_gemm_kernel<<<gMMA, 256, MMA_SMEM>>>((const __half*)pX16, pWhi,
                                             (__half*)pH16, NN, 256, 256, 1,
                                             pAls2, pAld2, a_s, a_d);
    cudaEventRecord(evG3, 0);

    // fork: splitW2(W2) on s2 overlapping gat_agg2 on main
    cudaStreamWaitEvent(s2, evG3, 0);
    splitW2_kernel<<<(128 * 256) / tpb, tpb, 0, s2>>>(W2);
    cudaEventRecord(evW, s2);

    gat_agg_kernel<<<warpGrid, tpb>>>(pH16, bg, pX16, pAls2, pAld2);

    // GCN layer 2 (tensor-core, N padded to 128, fp16 out, stride LL halves) + log_softmax
    cudaStreamWaitEvent(0, evW, 0);
    mma_gemm_kernel<<<gMMA2, 256, MMA_SMEM>>>((const __half*)pX16, pWhi,
                                              pH2, NN, LL, LL, 0,
                                              pAls, pAld, a_s, a_d);
    gcn2_kernel<<<warpGrid, tpb>>>(pH2, b2, out);

    cudaEventDestroy(evFork);
    cudaEventDestroy(evCsr);
    cudaEventDestroy(evG1);
    cudaEventDestroy(evW);
    cudaEventDestroy(evG3);
    cudaStreamDestroy(s2);
}